// round 1
// baseline (speedup 1.0000x reference)
#include <cuda_runtime.h>

// ---------------------------------------------------------------------------
// Model_86011015070455: energy model
//   traj:  te[b,i]   = MLP3_400_1024_1024_1( x4[b,i] )           (4096 rows)
//   inter: ie[b,i,j] = MLP3_800_1024_1024_1( [x4[b,i], x4[b,j]] ) (131072 rows)
//   out[b] = sum_i te + sum_ij edges[b,i,j]*ie[b,i,j]
//
// Key restructurings:
//   * inter layer1 split: h1[b,i,j] = relu(A1[b,i] + B1[b,j])  (bias folded in A1)
//     where A1 = x@int1_w[:400] + int1_b,  B1 = x@int1_w[400:]
//   * layer3 (GEMV) fused into layer2 GEMM epilogue: e = sum_n w3[n]*relu(acc+b2[n])
// ---------------------------------------------------------------------------

#define BM 128
#define BN 128
#define BK 16
#define TM 8
#define TN 8
#define NTHREADS 256

// scratch (device globals: allocation-free rule)
__device__ float g_T1[4096 * 1024];   // relu(x @ traj1_w + traj1_b)
__device__ float g_A1[4096 * 1024];   // x @ int1_w[:400] + int1_b
__device__ float g_B1[4096 * 1024];   // x @ int1_w[400:]
__device__ float g_erow[4096];        // per-agent traj energy (pre +b3)
__device__ float g_eint[131072];      // per-pair interaction energy (pre edges, pre +b3)

__global__ void init_kernel() {
    int idx = blockIdx.x * blockDim.x + threadIdx.x;
    if (idx < 131072) g_eint[idx] = 0.f;
    if (idx < 4096)   g_erow[idx] = 0.f;
}

// ---------------------------------------------------------------------------
// Stage 1: [4096 x 400] @ [400 x 3072]   (3 weight segments)
//   seg 0: traj1_w -> g_T1 = relu(acc + traj1_b)
//   seg 1: int1_w[0:400]   -> g_A1 = acc + int1_b
//   seg 2: int1_w[400:800] -> g_B1 = acc
// ---------------------------------------------------------------------------
__global__ __launch_bounds__(NTHREADS)
void stage1_kernel(const float* __restrict__ x,
                   const float* __restrict__ t1w, const float* __restrict__ t1b,
                   const float* __restrict__ i1w, const float* __restrict__ i1b)
{
    __shared__ float As[BK][BM];
    __shared__ float Bs[BK][BN];

    const int K = 400;
    const int mTile = blockIdx.x;          // 0..31
    const int seg   = blockIdx.y >> 3;     // 0..2
    const int nTile = blockIdx.y & 7;      // 0..7
    const int n0    = nTile * BN;

    const float* Bmat = (seg == 0) ? t1w : i1w;
    const int kOff = (seg == 2) ? 400 : 0;

    const int tid = threadIdx.x;
    const int tx = tid & 15;
    const int ty = tid >> 4;

    float acc[TM][TN];
    #pragma unroll
    for (int i = 0; i < TM; ++i)
        #pragma unroll
        for (int j = 0; j < TN; ++j) acc[i][j] = 0.f;

    const float* Abase = x + (long)mTile * BM * K;

    for (int k0 = 0; k0 < K; k0 += BK) {
        // A tile: 128 rows x 16 k (512 float4, 2 per thread), stored transposed
        #pragma unroll
        for (int it = 0; it < 2; ++it) {
            int idx  = tid + it * NTHREADS;
            int row  = idx >> 2;
            int col4 = (idx & 3) * 4;
            float4 v = *(const float4*)(Abase + row * K + k0 + col4);
            As[col4 + 0][row] = v.x;
            As[col4 + 1][row] = v.y;
            As[col4 + 2][row] = v.z;
            As[col4 + 3][row] = v.w;
        }
        // B tile: 16 k x 128 n
        #pragma unroll
        for (int it = 0; it < 2; ++it) {
            int idx  = tid + it * NTHREADS;
            int row  = idx >> 5;
            int col4 = (idx & 31) * 4;
            float4 v = *(const float4*)(Bmat + (long)(kOff + k0 + row) * 1024 + n0 + col4);
            *(float4*)&Bs[row][col4] = v;
        }
        __syncthreads();

        #pragma unroll
        for (int k = 0; k < BK; ++k) {
            float a[TM], b[TN];
            #pragma unroll
            for (int i = 0; i < TM; ++i) a[i] = As[k][ty * TM + i];
            #pragma unroll
            for (int j = 0; j < TN; ++j) b[j] = Bs[k][tx * TN + j];
            #pragma unroll
            for (int i = 0; i < TM; ++i)
                #pragma unroll
                for (int j = 0; j < TN; ++j)
                    acc[i][j] += a[i] * b[j];
        }
        __syncthreads();
    }

    const int mBase = mTile * BM + ty * TM;
    if (seg == 0) {
        #pragma unroll
        for (int i = 0; i < TM; ++i)
            #pragma unroll
            for (int j = 0; j < TN; ++j) {
                int n = n0 + tx * TN + j;
                g_T1[(mBase + i) * 1024 + n] = fmaxf(acc[i][j] + t1b[n], 0.f);
            }
    } else if (seg == 1) {
        #pragma unroll
        for (int i = 0; i < TM; ++i)
            #pragma unroll
            for (int j = 0; j < TN; ++j) {
                int n = n0 + tx * TN + j;
                g_A1[(mBase + i) * 1024 + n] = acc[i][j] + i1b[n];
            }
    } else {
        #pragma unroll
        for (int i = 0; i < TM; ++i)
            #pragma unroll
            for (int j = 0; j < TN; ++j) {
                int n = n0 + tx * TN + j;
                g_B1[(mBase + i) * 1024 + n] = acc[i][j];
            }
    }
}

// ---------------------------------------------------------------------------
// Stage 2 (traj): [4096 x 1024] (g_T1) @ [1024 x 1024] (traj2_w)
//   epilogue: partial_m = sum_n w3[n] * relu(acc + b2[n]) -> atomicAdd g_erow[m]
// ---------------------------------------------------------------------------
__global__ __launch_bounds__(NTHREADS)
void stage2_kernel(const float* __restrict__ W2, const float* __restrict__ b2,
                   const float* __restrict__ w3)
{
    __shared__ float As[BK][BM];
    __shared__ float Bs[BK][BN];

    const int mTile = blockIdx.x;
    const int n0    = blockIdx.y * BN;
    const int tid = threadIdx.x;
    const int tx = tid & 15;
    const int ty = tid >> 4;

    float acc[TM][TN];
    #pragma unroll
    for (int i = 0; i < TM; ++i)
        #pragma unroll
        for (int j = 0; j < TN; ++j) acc[i][j] = 0.f;

    const float* Abase = g_T1 + (long)mTile * BM * 1024;

    for (int k0 = 0; k0 < 1024; k0 += BK) {
        #pragma unroll
        for (int it = 0; it < 2; ++it) {
            int idx  = tid + it * NTHREADS;
            int row  = idx >> 2;
            int col4 = (idx & 3) * 4;
            float4 v = *(const float4*)(Abase + row * 1024 + k0 + col4);
            As[col4 + 0][row] = v.x;
            As[col4 + 1][row] = v.y;
            As[col4 + 2][row] = v.z;
            As[col4 + 3][row] = v.w;
        }
        #pragma unroll
        for (int it = 0; it < 2; ++it) {
            int idx  = tid + it * NTHREADS;
            int row  = idx >> 5;
            int col4 = (idx & 31) * 4;
            float4 v = *(const float4*)(W2 + (long)(k0 + row) * 1024 + n0 + col4);
            *(float4*)&Bs[row][col4] = v;
        }
        __syncthreads();

        #pragma unroll
        for (int k = 0; k < BK; ++k) {
            float a[TM], b[TN];
            #pragma unroll
            for (int i = 0; i < TM; ++i) a[i] = As[k][ty * TM + i];
            #pragma unroll
            for (int j = 0; j < TN; ++j) b[j] = Bs[k][tx * TN + j];
            #pragma unroll
            for (int i = 0; i < TM; ++i)
                #pragma unroll
                for (int j = 0; j < TN; ++j)
                    acc[i][j] += a[i] * b[j];
        }
        __syncthreads();
    }

    const int mBase = mTile * BM + ty * TM;
    #pragma unroll
    for (int i = 0; i < TM; ++i) {
        float partial = 0.f;
        #pragma unroll
        for (int j = 0; j < TN; ++j) {
            int n = n0 + tx * TN + j;
            partial += fmaxf(acc[i][j] + b2[n], 0.f) * w3[n];
        }
        #pragma unroll
        for (int off = 8; off >= 1; off >>= 1)
            partial += __shfl_xor_sync(0xffffffffu, partial, off, 16);
        if (tx == 0) atomicAdd(&g_erow[mBase + i], partial);
    }
}

// ---------------------------------------------------------------------------
// Stage 3 (interaction): [131072 x 1024] @ [1024 x 1024] (int2_w)
//   A rows generated on the fly: relu(g_A1[b,i,:] + g_B1[b,j,:])
//   epilogue: partial_m = sum_n w3[n]*relu(acc+b2[n]) -> atomicAdd g_eint[m]
// ---------------------------------------------------------------------------
__global__ __launch_bounds__(NTHREADS)
void stage3_kernel(const float* __restrict__ W2, const float* __restrict__ b2,
                   const float* __restrict__ w3)
{
    __shared__ float As[BK][BM];
    __shared__ float Bs[BK][BN];

    const int mTile = blockIdx.x;          // 0..1023
    const int n0    = blockIdx.y * BN;
    const int tid = threadIdx.x;
    const int tx = tid & 15;
    const int ty = tid >> 4;

    float acc[TM][TN];
    #pragma unroll
    for (int i = 0; i < TM; ++i)
        #pragma unroll
        for (int j = 0; j < TN; ++j) acc[i][j] = 0.f;

    for (int k0 = 0; k0 < 1024; k0 += BK) {
        #pragma unroll
        for (int it = 0; it < 2; ++it) {
            int idx  = tid + it * NTHREADS;
            int row  = idx >> 2;
            int col4 = (idx & 3) * 4;
            int m = mTile * BM + row;
            int b = m >> 10;
            int i = (m >> 5) & 31;
            int j = m & 31;
            float4 va = *(const float4*)&g_A1[((b << 5) + i) * 1024 + k0 + col4];
            float4 vb = *(const float4*)&g_B1[((b << 5) + j) * 1024 + k0 + col4];
            As[col4 + 0][row] = fmaxf(va.x + vb.x, 0.f);
            As[col4 + 1][row] = fmaxf(va.y + vb.y, 0.f);
            As[col4 + 2][row] = fmaxf(va.z + vb.z, 0.f);
            As[col4 + 3][row] = fmaxf(va.w + vb.w, 0.f);
        }
        #pragma unroll
        for (int it = 0; it < 2; ++it) {
            int idx  = tid + it * NTHREADS;
            int row  = idx >> 5;
            int col4 = (idx & 31) * 4;
            float4 v = *(const float4*)(W2 + (long)(k0 + row) * 1024 + n0 + col4);
            *(float4*)&Bs[row][col4] = v;
        }
        __syncthreads();

        #pragma unroll
        for (int k = 0; k < BK; ++k) {
            float a[TM], b[TN];
            #pragma unroll
            for (int i = 0; i < TM; ++i) a[i] = As[k][ty * TM + i];
            #pragma unroll
            for (int j = 0; j < TN; ++j) b[j] = Bs[k][tx * TN + j];
            #pragma unroll
            for (int i = 0; i < TM; ++i)
                #pragma unroll
                for (int j = 0; j < TN; ++j)
                    acc[i][j] += a[i] * b[j];
        }
        __syncthreads();
    }

    const int mBase = mTile * BM + ty * TM;
    #pragma unroll
    for (int i = 0; i < TM; ++i) {
        float partial = 0.f;
        #pragma unroll
        for (int j = 0; j < TN; ++j) {
            int n = n0 + tx * TN + j;
            partial += fmaxf(acc[i][j] + b2[n], 0.f) * w3[n];
        }
        #pragma unroll
        for (int off = 8; off >= 1; off >>= 1)
            partial += __shfl_xor_sync(0xffffffffu, partial, off, 16);
        if (tx == 0) atomicAdd(&g_eint[mBase + i], partial);
    }
}

// ---------------------------------------------------------------------------
// Finalize: out[b] = sum_i (g_erow[b,i] + t3b)
//                  + sum_ij edges[b,i,j] * (g_eint[b,i,j] + i3b)
// ---------------------------------------------------------------------------
__global__ void finalize_kernel(const float* __restrict__ edges,
                                const float* __restrict__ t3b,
                                const float* __restrict__ i3b,
                                float* __restrict__ out)
{
    const int b = blockIdx.x;
    const int tid = threadIdx.x;
    const float bias_i = i3b[0];

    float s = 0.f;
    #pragma unroll
    for (int it = 0; it < 4; ++it) {
        int idx = tid + it * 256;
        float e = edges[b * 1024 + idx];
        s += e * (g_eint[b * 1024 + idx] + bias_i);
    }
    if (tid < 32) s += g_erow[b * 32 + tid] + t3b[0];

    __shared__ float red[256];
    red[tid] = s;
    __syncthreads();
    for (int o = 128; o > 0; o >>= 1) {
        if (tid < o) red[tid] += red[tid + o];
        __syncthreads();
    }
    if (tid == 0) out[b] = red[0];
}

// ---------------------------------------------------------------------------
extern "C" void kernel_launch(void* const* d_in, const int* in_sizes, int n_in,
                              void* d_out, int out_size)
{
    const float* x   = (const float*)d_in[0];
    const float* edg = (const float*)d_in[1];
    const float* t1w = (const float*)d_in[2];
    const float* t1b = (const float*)d_in[3];
    const float* t2w = (const float*)d_in[4];
    const float* t2b = (const float*)d_in[5];
    const float* t3w = (const float*)d_in[6];
    const float* t3b = (const float*)d_in[7];
    const float* i1w = (const float*)d_in[8];
    const float* i1b = (const float*)d_in[9];
    const float* i2w = (const float*)d_in[10];
    const float* i2b = (const float*)d_in[11];
    const float* i3w = (const float*)d_in[12];
    const float* i3b = (const float*)d_in[13];
    float* out = (float*)d_out;

    init_kernel<<<512, 256>>>();

    dim3 g1(32, 24);                       // 32 M-tiles x (3 segs * 8 N-tiles)
    stage1_kernel<<<g1, NTHREADS>>>(x, t1w, t1b, i1w, i1b);

    dim3 g2(32, 8);
    stage2_kernel<<<g2, NTHREADS>>>(t2w, t2b, t3w);

    dim3 g3(1024, 8);
    stage3_kernel<<<g3, NTHREADS>>>(i2w, i2b, i3w);

    finalize_kernel<<<128, 256>>>(edg, t3b, i3b, out);
}

// round 4
// speedup vs baseline: 1.2080x; 1.2080x over previous
#include <cuda_runtime.h>
#include <cuda_fp16.h>
#include <cstdint>

// ===========================================================================
// Model_86011015070455 — R4: mma.sync (HMMA fp16, fp32 accum) for stages 2+3
//   R3 bug fixed: fillB now covers both planes fully (8 iters, full 128B rows)
//
//   stage1 (SIMT fp32):  T1 = relu(x@t1w+b), A1 = x@i1w[:400]+b, B1 = x@i1w[400:]
//   prep:                W2T planes = split-fp16 transpose of t2w / i2w
//   stage2/3 (HMMA):     D = A @ W2 with 3-term split fp16
//                        (Ahi*Whi + Alo*Whi + Ahi*Wlo), fp32 accum,
//                        epilogue fuses layer-3: e_m = sum_n w3[n]*relu(D+b2[n])
// ===========================================================================

__device__ __forceinline__ uint32_t smem_u32(const void* p) {
    uint32_t a;
    asm("{ .reg .u64 t; cvta.to.shared.u64 t, %1; cvt.u32.u64 %0, t; }" : "=r"(a) : "l"(p));
    return a;
}
__device__ __forceinline__ void ldsm4(uint32_t& r0, uint32_t& r1, uint32_t& r2, uint32_t& r3,
                                      uint32_t addr) {
    asm volatile("ldmatrix.sync.aligned.m8n8.x4.shared.b16 {%0,%1,%2,%3}, [%4];"
                 : "=r"(r0), "=r"(r1), "=r"(r2), "=r"(r3) : "r"(addr));
}
__device__ __forceinline__ void mma16816(float* d, const uint32_t* a, const uint32_t* b) {
    asm volatile("mma.sync.aligned.m16n8k16.row.col.f32.f16.f16.f32 "
                 "{%0,%1,%2,%3}, {%4,%5,%6,%7}, {%8,%9}, {%0,%1,%2,%3};"
                 : "+f"(d[0]), "+f"(d[1]), "+f"(d[2]), "+f"(d[3])
                 : "r"(a[0]), "r"(a[1]), "r"(a[2]), "r"(a[3]), "r"(b[0]), "r"(b[1]));
}
#define SWZ(o) ((o) ^ (((o) >> 3) & 0x70))

// ------------------------------------------------------------- device scratch
__device__ float g_T1[4096 * 1024];
__device__ float g_A1[4096 * 1024];
__device__ float g_B1[4096 * 1024];
__device__ float g_erow[4096];
__device__ float g_eint[131072];
__device__ __half g_T2T_hi[1024 * 1024];   // traj2_w transposed [n][k], fp16 hi
__device__ __half g_T2T_lo[1024 * 1024];   // residual
__device__ __half g_I2T_hi[1024 * 1024];   // int2_w transposed [n][k]
__device__ __half g_I2T_lo[1024 * 1024];

__global__ void init_kernel() {
    int idx = blockIdx.x * blockDim.x + threadIdx.x;
    if (idx < 131072) g_eint[idx] = 0.f;
    if (idx < 4096)   g_erow[idx] = 0.f;
}

// ------------------------------------------- prep: transpose + split to fp16
__global__ void prep_transpose(const float* __restrict__ t2w, const float* __restrict__ i2w) {
    __shared__ float tile[32][33];
    const float* src = blockIdx.z ? i2w : t2w;
    __half* dhi = blockIdx.z ? g_I2T_hi : g_T2T_hi;
    __half* dlo = blockIdx.z ? g_I2T_lo : g_T2T_lo;
    int k = blockIdx.y * 32 + threadIdx.y;
    int n = blockIdx.x * 32 + threadIdx.x;
    tile[threadIdx.y][threadIdx.x] = src[k * 1024 + n];
    __syncthreads();
    float v = tile[threadIdx.x][threadIdx.y];
    __half hi = __float2half_rn(v);
    __half lo = __float2half_rn(v - __half2float(hi));
    int nn = blockIdx.x * 32 + threadIdx.y;
    int kk = blockIdx.y * 32 + threadIdx.x;
    dhi[nn * 1024 + kk] = hi;
    dlo[nn * 1024 + kk] = lo;
}

// --------------------------------------------------- stage1 (SIMT fp32 GEMM)
#define BM 128
#define BN 128
#define BK 16
#define TM 8
#define TN 8
#define NTHREADS 256

__global__ __launch_bounds__(NTHREADS)
void stage1_kernel(const float* __restrict__ x,
                   const float* __restrict__ t1w, const float* __restrict__ t1b,
                   const float* __restrict__ i1w, const float* __restrict__ i1b)
{
    __shared__ float As[BK][BM];
    __shared__ float Bs[BK][BN];

    const int K = 400;
    const int mTile = blockIdx.x;
    const int seg   = blockIdx.y >> 3;
    const int n0    = (blockIdx.y & 7) * BN;
    const float* Bmat = (seg == 0) ? t1w : i1w;
    const int kOff = (seg == 2) ? 400 : 0;

    const int tid = threadIdx.x;
    const int tx = tid & 15;
    const int ty = tid >> 4;

    float acc[TM][TN];
    #pragma unroll
    for (int i = 0; i < TM; ++i)
        #pragma unroll
        for (int j = 0; j < TN; ++j) acc[i][j] = 0.f;

    const float* Abase = x + (long)mTile * BM * K;

    for (int k0 = 0; k0 < K; k0 += BK) {
        #pragma unroll
        for (int it = 0; it < 2; ++it) {
            int idx = tid + it * NTHREADS;
            int row = idx >> 2, col4 = (idx & 3) * 4;
            float4 v = *(const float4*)(Abase + row * K + k0 + col4);
            As[col4 + 0][row] = v.x; As[col4 + 1][row] = v.y;
            As[col4 + 2][row] = v.z; As[col4 + 3][row] = v.w;
        }
        #pragma unroll
        for (int it = 0; it < 2; ++it) {
            int idx = tid + it * NTHREADS;
            int row = idx >> 5, col4 = (idx & 31) * 4;
            *(float4*)&Bs[row][col4] =
                *(const float4*)(Bmat + (long)(kOff + k0 + row) * 1024 + n0 + col4);
        }
        __syncthreads();
        #pragma unroll
        for (int k = 0; k < BK; ++k) {
            float a[TM], b[TN];
            #pragma unroll
            for (int i = 0; i < TM; ++i) a[i] = As[k][ty * TM + i];
            #pragma unroll
            for (int j = 0; j < TN; ++j) b[j] = Bs[k][tx * TN + j];
            #pragma unroll
            for (int i = 0; i < TM; ++i)
                #pragma unroll
                for (int j = 0; j < TN; ++j) acc[i][j] += a[i] * b[j];
        }
        __syncthreads();
    }

    const int mBase = mTile * BM + ty * TM;
    if (seg == 0) {
        #pragma unroll
        for (int i = 0; i < TM; ++i)
            #pragma unroll
            for (int j = 0; j < TN; ++j) {
                int n = n0 + tx * TN + j;
                g_T1[(mBase + i) * 1024 + n] = fmaxf(acc[i][j] + t1b[n], 0.f);
            }
    } else if (seg == 1) {
        #pragma unroll
        for (int i = 0; i < TM; ++i)
            #pragma unroll
            for (int j = 0; j < TN; ++j) {
                int n = n0 + tx * TN + j;
                g_A1[(mBase + i) * 1024 + n] = acc[i][j] + i1b[n];
            }
    } else {
        #pragma unroll
        for (int i = 0; i < TM; ++i)
            #pragma unroll
            for (int j = 0; j < TN; ++j) {
                int n = n0 + tx * TN + j;
                g_B1[(mBase + i) * 1024 + n] = acc[i][j];
            }
    }
}

// --------------------------------------------- tensor stages (mma.sync HMMA)
// MODE 2: A rows from g_T1 (traj layer2),      out -> g_erow
// MODE 3: A rows = relu(A1[b,i] + B1[b,j]),    out -> g_eint
// CTA tile M=128, N=128; warp tile 32x64 (warps 4m x 2n); K chunks of 64.
// smem: SW128 swizzled, 128B rows of 64 fp16; double buffered.

static constexpr uint32_t TB_AHI = 0;
static constexpr uint32_t TB_ALO = 16 * 1024;
static constexpr uint32_t TB_BHI = 32 * 1024;
static constexpr uint32_t TB_BLO = 48 * 1024;
static constexpr uint32_t TB_BUF = 64 * 1024;
static constexpr uint32_t TS_SMEM = 2 * TB_BUF + 1024 + 1024;   // bufs + b2/w3 + align

template <int MODE>
__global__ __launch_bounds__(256)
void tensor_stage_kernel(const float* __restrict__ b2g, const float* __restrict__ w3g)
{
    extern __shared__ char smem_raw[];
    const uint32_t smem_u = smem_u32(smem_raw);
    const uint32_t base_u = (smem_u + 1023) & ~1023u;
    char* p = smem_raw + (base_u - smem_u);

    float* sb2 = (float*)(p + 2 * TB_BUF);
    float* sw3 = sb2 + 128;

    const int tid  = threadIdx.x;
    const int lane = tid & 31;
    const int wid  = tid >> 5;
    const int wm   = wid & 3;        // warp row (32 m each)
    const int wn   = wid >> 2;       // warp col (64 n each)
    const int mTile = blockIdx.x;
    const int n0    = blockIdx.y * 128;

    const __half* WT_hi = (MODE == 2) ? g_T2T_hi : g_I2T_hi;
    const __half* WT_lo = (MODE == 2) ? g_T2T_lo : g_I2T_lo;
    float* eout = (MODE == 2) ? g_erow : g_eint;

    if (tid < 128) { sb2[tid] = b2g[n0 + tid]; sw3[tid] = w3g[n0 + tid]; }

    // ---- A source row for this thread's fill slot ----
    const int ar = tid >> 1;          // A-tile row 0..127
    const int ahalf = tid & 1;        // k half
    const int m_fill = mTile * 128 + ar;
    const float* pa;
    const float* pb = nullptr;
    if (MODE == 2) {
        pa = g_T1 + (size_t)m_fill * 1024;
    } else {
        int b = m_fill >> 10;
        pa = g_A1 + (size_t)((b << 5) + ((m_fill >> 5) & 31)) * 1024;
        pb = g_B1 + (size_t)((b << 5) + (m_fill & 31)) * 1024;
    }

    auto fillA = [&](uint32_t bufoff, int k0) {
        char* dh = p + bufoff + TB_AHI;
        char* dl = p + bufoff + TB_ALO;
        #pragma unroll
        for (int kk = 0; kk < 32; kk += 2) {
            const int kl = ahalf * 32 + kk;
            float2 va = *(const float2*)(pa + k0 + kl);
            float h0, h1;
            if (MODE == 2) { h0 = va.x; h1 = va.y; }
            else {
                float2 vb = *(const float2*)(pb + k0 + kl);
                h0 = fmaxf(va.x + vb.x, 0.f);
                h1 = fmaxf(va.y + vb.y, 0.f);
            }
            __half H0 = __float2half_rn(h0), H1 = __float2half_rn(h1);
            __half L0 = __float2half_rn(h0 - __half2float(H0));
            __half L1 = __float2half_rn(h1 - __half2float(H1));
            uint32_t sw = SWZ((uint32_t)(ar * 128 + kl * 2));
            *(__half2*)(dh + sw) = __halves2half2(H0, H1);
            *(__half2*)(dl + sw) = __halves2half2(L0, L1);
        }
    };
    // Full coverage: 2 planes x 128 rows x 128B = 32KB -> 2048 x 16B loads
    // (256 threads x 8 iters). plane = idx>>10, row = (idx&1023)>>3, cc = idx&7.
    auto fillB = [&](uint32_t bufoff, int k0) {
        #pragma unroll
        for (int t = 0; t < 8; ++t) {
            int idx = tid + t * 256;            // 0..2047
            int plane = idx >> 10;
            int rl = (idx & 1023) >> 3;
            int cc = idx & 7;
            const __half* src = (plane ? WT_lo : WT_hi)
                                + (size_t)(n0 + rl) * 1024 + k0 + cc * 8;
            float4 v = *(const float4*)src;
            uint32_t sw = SWZ((uint32_t)(rl * 128 + cc * 16));
            *(float4*)(p + bufoff + (plane ? TB_BLO : TB_BHI) + sw) = v;
        }
    };

    // ---- ldmatrix address bases (byte offsets within a tile) ----
    uint32_t aoff[2], boff[4];
    #pragma unroll
    for (int mf = 0; mf < 2; ++mf)
        aoff[mf] = (uint32_t)((wm * 32 + mf * 16 + (lane & 15)) * 128 + (lane >> 4) * 16);
    #pragma unroll
    for (int nf2 = 0; nf2 < 4; ++nf2)
        boff[nf2] = (uint32_t)((wn * 64 + nf2 * 16 + (lane & 7) + ((lane & 16) ? 8 : 0)) * 128
                               + ((lane >> 3) & 1) * 16);

    float acc[2][8][4];
    #pragma unroll
    for (int mf = 0; mf < 2; ++mf)
        #pragma unroll
        for (int nf = 0; nf < 8; ++nf)
            #pragma unroll
            for (int q = 0; q < 4; ++q) acc[mf][nf][q] = 0.f;

    auto compute = [&](uint32_t bufoff) {
        const uint32_t ah_b = base_u + bufoff + TB_AHI;
        const uint32_t al_b = base_u + bufoff + TB_ALO;
        const uint32_t bh_b = base_u + bufoff + TB_BHI;
        const uint32_t bl_b = base_u + bufoff + TB_BLO;
        #pragma unroll
        for (int kf = 0; kf < 4; ++kf) {
            const uint32_t kadd = kf * 32;
            uint32_t ah[2][4], al[2][4];
            #pragma unroll
            for (int mf = 0; mf < 2; ++mf) {
                uint32_t sw = SWZ(aoff[mf] + kadd);
                ldsm4(ah[mf][0], ah[mf][1], ah[mf][2], ah[mf][3], ah_b + sw);
                ldsm4(al[mf][0], al[mf][1], al[mf][2], al[mf][3], al_b + sw);
            }
            uint32_t bh[8][2], bl[8][2];
            #pragma unroll
            for (int nf2 = 0; nf2 < 4; ++nf2) {
                uint32_t sw = SWZ(boff[nf2] + kadd);
                uint32_t r0, r1, r2, r3;
                ldsm4(r0, r1, r2, r3, bh_b + sw);
                bh[nf2 * 2][0] = r0; bh[nf2 * 2][1] = r1;
                bh[nf2 * 2 + 1][0] = r2; bh[nf2 * 2 + 1][1] = r3;
                ldsm4(r0, r1, r2, r3, bl_b + sw);
                bl[nf2 * 2][0] = r0; bl[nf2 * 2][1] = r1;
                bl[nf2 * 2 + 1][0] = r2; bl[nf2 * 2 + 1][1] = r3;
            }
            #pragma unroll
            for (int mf = 0; mf < 2; ++mf)
                #pragma unroll
                for (int nf = 0; nf < 8; ++nf) {
                    mma16816(acc[mf][nf], ah[mf], bh[nf]);
                    mma16816(acc[mf][nf], al[mf], bh[nf]);
                    mma16816(acc[mf][nf], ah[mf], bl[nf]);
                }
        }
    };

    // ---- pipelined main loop over K=1024 in 16 chunks of 64 ----
    fillA(0, 0); fillB(0, 0);
    __syncthreads();
    for (int c = 0; c < 16; ++c) {
        const uint32_t buf = (uint32_t)(c & 1) * TB_BUF;
        if (c < 15) {
            const uint32_t nb = (uint32_t)((c + 1) & 1) * TB_BUF;
            fillA(nb, (c + 1) * 64);
            fillB(nb, (c + 1) * 64);
        }
        compute(buf);
        __syncthreads();
    }

    // ---- epilogue: fused layer-3  e_m += sum_n w3[n]*relu(D+b2[n]) ----
    #pragma unroll
    for (int mf = 0; mf < 2; ++mf) {
        #pragma unroll
        for (int h = 0; h < 2; ++h) {
            float s = 0.f;
            #pragma unroll
            for (int nf = 0; nf < 8; ++nf) {
                int nl = wn * 64 + nf * 8 + 2 * (lane & 3);
                float d0 = acc[mf][nf][h * 2 + 0];
                float d1 = acc[mf][nf][h * 2 + 1];
                s += fmaxf(d0 + sb2[nl], 0.f) * sw3[nl]
                   + fmaxf(d1 + sb2[nl + 1], 0.f) * sw3[nl + 1];
            }
            s += __shfl_xor_sync(0xffffffffu, s, 1);
            s += __shfl_xor_sync(0xffffffffu, s, 2);
            if ((lane & 3) == 0) {
                int m = mTile * 128 + wm * 32 + mf * 16 + (lane >> 2) + h * 8;
                atomicAdd(&eout[m], s);
            }
        }
    }
}

// ------------------------------------------------------------------ finalize
__global__ void finalize_kernel(const float* __restrict__ edges,
                                const float* __restrict__ t3b,
                                const float* __restrict__ i3b,
                                float* __restrict__ out)
{
    const int b = blockIdx.x;
    const int tid = threadIdx.x;
    const float bias_i = i3b[0];

    float s = 0.f;
    #pragma unroll
    for (int it = 0; it < 4; ++it) {
        int idx = tid + it * 256;
        s += edges[b * 1024 + idx] * (g_eint[b * 1024 + idx] + bias_i);
    }
    if (tid < 32) s += g_erow[b * 32 + tid] + t3b[0];

    __shared__ float red[256];
    red[tid] = s;
    __syncthreads();
    for (int o = 128; o > 0; o >>= 1) {
        if (tid < o) red[tid] += red[tid + o];
        __syncthreads();
    }
    if (tid == 0) out[b] = red[0];
}

// ---------------------------------------------------------------------------
extern "C" void kernel_launch(void* const* d_in, const int* in_sizes, int n_in,
                              void* d_out, int out_size)
{
    const float* x   = (const float*)d_in[0];
    const float* edg = (const float*)d_in[1];
    const float* t1w = (const float*)d_in[2];
    const float* t1b = (const float*)d_in[3];
    const float* t2w = (const float*)d_in[4];
    const float* t2b = (const float*)d_in[5];
    const float* t3w = (const float*)d_in[6];
    const float* t3b = (const float*)d_in[7];
    const float* i1w = (const float*)d_in[8];
    const float* i1b = (const float*)d_in[9];
    const float* i2w = (const float*)d_in[10];
    const float* i2b = (const float*)d_in[11];
    const float* i3w = (const float*)d_in[12];
    const float* i3b = (const float*)d_in[13];
    float* out = (float*)d_out;

    cudaFuncSetAttribute(tensor_stage_kernel<2>,
                         cudaFuncAttributeMaxDynamicSharedMemorySize, TS_SMEM);
    cudaFuncSetAttribute(tensor_stage_kernel<3>,
                         cudaFuncAttributeMaxDynamicSharedMemorySize, TS_SMEM);

    init_kernel<<<512, 256>>>();

    dim3 gp(32, 32, 2);
    prep_transpose<<<gp, dim3(32, 32)>>>(t2w, i2w);

    dim3 g1(32, 24);
    stage1_kernel<<<g1, NTHREADS>>>(x, t1w, t1b, i1w, i1b);

    dim3 g2(32, 8);
    tensor_stage_kernel<2><<<g2, 256, TS_SMEM>>>(t2b, t3w);

    dim3 g3(1024, 8);
    tensor_stage_kernel<3><<<g3, 256, TS_SMEM>>>(i2b, i3w);

    finalize_kernel<<<128, 256>>>(edg, t3b, i3b, out);
}

// round 5
// speedup vs baseline: 2.3731x; 1.9645x over previous
#include <cuda_runtime.h>
#include <cuda_fp16.h>
#include <cstdint>

// ===========================================================================
// Model_86011015070455 — R5: HMMA stages 2+3 with cp.async B-fill,
//   register-prefetched A-fill, CTA tile 128x256 (lower LDS/MAC), chunk K=32.
//
//   stage1 (SIMT fp32):  T1 = relu(x@t1w+b), A1 = x@i1w[:400]+b, B1 = x@i1w[400:]
//   prep:                W2T planes = split-fp16 transpose of t2w / i2w
//   stage2/3 (HMMA):     D = A @ W2 with 3-term split fp16
//                        (Ahi*Whi + Alo*Whi + Ahi*Wlo), fp32 accum,
//                        epilogue fuses layer-3: e_m = sum_n w3[n]*relu(D+b2[n])
// ===========================================================================

__device__ __forceinline__ uint32_t smem_u32(const void* p) {
    uint32_t a;
    asm("{ .reg .u64 t; cvta.to.shared.u64 t, %1; cvt.u32.u64 %0, t; }" : "=r"(a) : "l"(p));
    return a;
}
__device__ __forceinline__ void ldsm4(uint32_t& r0, uint32_t& r1, uint32_t& r2, uint32_t& r3,
                                      uint32_t addr) {
    asm volatile("ldmatrix.sync.aligned.m8n8.x4.shared.b16 {%0,%1,%2,%3}, [%4];"
                 : "=r"(r0), "=r"(r1), "=r"(r2), "=r"(r3) : "r"(addr));
}
__device__ __forceinline__ void mma16816(float* d, const uint32_t* a, const uint32_t* b) {
    asm volatile("mma.sync.aligned.m16n8k16.row.col.f32.f16.f16.f32 "
                 "{%0,%1,%2,%3}, {%4,%5,%6,%7}, {%8,%9}, {%0,%1,%2,%3};"
                 : "+f"(d[0]), "+f"(d[1]), "+f"(d[2]), "+f"(d[3])
                 : "r"(a[0]), "r"(a[1]), "r"(a[2]), "r"(a[3]), "r"(b[0]), "r"(b[1]));
}
__device__ __forceinline__ void cp16(uint32_t dst, const void* src) {
    asm volatile("cp.async.cg.shared.global [%0], [%1], 16;"
                 :: "r"(dst), "l"(__cvta_generic_to_global(src)));
}
#define CP_COMMIT() asm volatile("cp.async.commit_group;")
#define CP_WAIT0()  asm volatile("cp.async.wait_group 0;")
#define SWZ(o)   ((o) ^ (((o) >> 3) & 0x70))
#define SWZ64(o) ((o) ^ (((o) >> 3) & 0x30))

__device__ __forceinline__ uint32_t packh2(__half a, __half b) {
    __half2 t = __halves2half2(a, b);
    return *(uint32_t*)&t;
}

// ------------------------------------------------------------- device scratch
__device__ float g_T1[4096 * 1024];
__device__ float g_A1[4096 * 1024];
__device__ float g_B1[4096 * 1024];
__device__ float g_erow[4096];
__device__ float g_eint[131072];
__device__ __half g_T2T_hi[1024 * 1024];   // traj2_w transposed [n][k], fp16 hi
__device__ __half g_T2T_lo[1024 * 1024];   // residual
__device__ __half g_I2T_hi[1024 * 1024];   // int2_w transposed [n][k]
__device__ __half g_I2T_lo[1024 * 1024];

__global__ void init_kernel() {
    int idx = blockIdx.x * blockDim.x + threadIdx.x;
    if (idx < 131072) g_eint[idx] = 0.f;
    if (idx < 4096)   g_erow[idx] = 0.f;
}

// ------------------------------------------- prep: transpose + split to fp16
__global__ void prep_transpose(const float* __restrict__ t2w, const float* __restrict__ i2w) {
    __shared__ float tile[32][33];
    const float* src = blockIdx.z ? i2w : t2w;
    __half* dhi = blockIdx.z ? g_I2T_hi : g_T2T_hi;
    __half* dlo = blockIdx.z ? g_I2T_lo : g_T2T_lo;
    int k = blockIdx.y * 32 + threadIdx.y;
    int n = blockIdx.x * 32 + threadIdx.x;
    tile[threadIdx.y][threadIdx.x] = src[k * 1024 + n];
    __syncthreads();
    float v = tile[threadIdx.x][threadIdx.y];
    __half hi = __float2half_rn(v);
    __half lo = __float2half_rn(v - __half2float(hi));
    int nn = blockIdx.x * 32 + threadIdx.y;
    int kk = blockIdx.y * 32 + threadIdx.x;
    dhi[nn * 1024 + kk] = hi;
    dlo[nn * 1024 + kk] = lo;
}

// --------------------------------------------------- stage1 (SIMT fp32 GEMM)
#define BM 128
#define BN 128
#define BK 16
#define TM 8
#define TN 8
#define NTHREADS 256

__global__ __launch_bounds__(NTHREADS)
void stage1_kernel(const float* __restrict__ x,
                   const float* __restrict__ t1w, const float* __restrict__ t1b,
                   const float* __restrict__ i1w, const float* __restrict__ i1b)
{
    __shared__ float As[BK][BM];
    __shared__ float Bs[BK][BN];

    const int K = 400;
    const int mTile = blockIdx.x;
    const int seg   = blockIdx.y >> 3;
    const int n0    = (blockIdx.y & 7) * BN;
    const float* Bmat = (seg == 0) ? t1w : i1w;
    const int kOff = (seg == 2) ? 400 : 0;

    const int tid = threadIdx.x;
    const int tx = tid & 15;
    const int ty = tid >> 4;

    float acc[TM][TN];
    #pragma unroll
    for (int i = 0; i < TM; ++i)
        #pragma unroll
        for (int j = 0; j < TN; ++j) acc[i][j] = 0.f;

    const float* Abase = x + (long)mTile * BM * K;

    for (int k0 = 0; k0 < K; k0 += BK) {
        #pragma unroll
        for (int it = 0; it < 2; ++it) {
            int idx = tid + it * NTHREADS;
            int row = idx >> 2, col4 = (idx & 3) * 4;
            float4 v = *(const float4*)(Abase + row * K + k0 + col4);
            As[col4 + 0][row] = v.x; As[col4 + 1][row] = v.y;
            As[col4 + 2][row] = v.z; As[col4 + 3][row] = v.w;
        }
        #pragma unroll
        for (int it = 0; it < 2; ++it) {
            int idx = tid + it * NTHREADS;
            int row = idx >> 5, col4 = (idx & 31) * 4;
            *(float4*)&Bs[row][col4] =
                *(const float4*)(Bmat + (long)(kOff + k0 + row) * 1024 + n0 + col4);
        }
        __syncthreads();
        #pragma unroll
        for (int k = 0; k < BK; ++k) {
            float a[TM], b[TN];
            #pragma unroll
            for (int i = 0; i < TM; ++i) a[i] = As[k][ty * TM + i];
            #pragma unroll
            for (int j = 0; j < TN; ++j) b[j] = Bs[k][tx * TN + j];
            #pragma unroll
            for (int i = 0; i < TM; ++i)
                #pragma unroll
                for (int j = 0; j < TN; ++j) acc[i][j] += a[i] * b[j];
        }
        __syncthreads();
    }

    const int mBase = mTile * BM + ty * TM;
    if (seg == 0) {
        #pragma unroll
        for (int i = 0; i < TM; ++i)
            #pragma unroll
            for (int j = 0; j < TN; ++j) {
                int n = n0 + tx * TN + j;
                g_T1[(mBase + i) * 1024 + n] = fmaxf(acc[i][j] + t1b[n], 0.f);
            }
    } else if (seg == 1) {
        #pragma unroll
        for (int i = 0; i < TM; ++i)
            #pragma unroll
            for (int j = 0; j < TN; ++j) {
                int n = n0 + tx * TN + j;
                g_A1[(mBase + i) * 1024 + n] = acc[i][j] + i1b[n];
            }
    } else {
        #pragma unroll
        for (int i = 0; i < TM; ++i)
            #pragma unroll
            for (int j = 0; j < TN; ++j) {
                int n = n0 + tx * TN + j;
                g_B1[(mBase + i) * 1024 + n] = acc[i][j];
            }
    }
}

// --------------------------------------------- tensor stages (mma.sync HMMA)
// MODE 2: A rows from g_T1 (traj layer2),      out -> g_erow
// MODE 3: A rows = relu(A1[b,i] + B1[b,j]),    out -> g_eint
// CTA tile M=128, N=256; 8 warps as 2m x 4n (warp tile 64x64); K chunks of 32.
// smem rows: 32 fp16 = 64B, SW64 swizzle. Double buffered (2 x 48KB).
// B filled by cp.async; A prefetched to regs before compute, STS'd after.

static constexpr uint32_t TB_AHI = 0;
static constexpr uint32_t TB_ALO = 8 * 1024;
static constexpr uint32_t TB_BHI = 16 * 1024;
static constexpr uint32_t TB_BLO = 32 * 1024;
static constexpr uint32_t TB_BUF = 48 * 1024;
static constexpr uint32_t TS_SMEM = 2 * TB_BUF + 2048 + 1024;   // bufs + b2/w3 + align
static constexpr int NCH = 32;   // 1024 / 32

template <int MODE>
__global__ __launch_bounds__(256)
void tensor_stage_kernel(const float* __restrict__ b2g, const float* __restrict__ w3g)
{
    extern __shared__ char smem_raw[];
    const uint32_t smem_u = smem_u32(smem_raw);
    const uint32_t base_u = (smem_u + 1023) & ~1023u;
    char* p = smem_raw + (base_u - smem_u);

    float* sb2 = (float*)(p + 2 * TB_BUF);
    float* sw3 = sb2 + 256;

    const int tid  = threadIdx.x;
    const int lane = tid & 31;
    const int wid  = tid >> 5;
    const int wm   = wid & 1;        // warp row (64 m each)
    const int wn   = wid >> 1;       // warp col (64 n each)
    const int mTile = blockIdx.x;
    const int n0    = blockIdx.y * 256;

    const __half* WT_hi = (MODE == 2) ? g_T2T_hi : g_I2T_hi;
    const __half* WT_lo = (MODE == 2) ? g_T2T_lo : g_I2T_lo;
    float* eout = (MODE == 2) ? g_erow : g_eint;

    sb2[tid] = b2g[n0 + tid];
    sw3[tid] = w3g[n0 + tid];

    // ---- A source rows for this thread's fill slot ----
    const int ar = tid >> 1;          // A-tile row 0..127
    const int khalf = tid & 1;        // 16-float half of the 32-k chunk
    const int m_fill = mTile * 128 + ar;
    const float* pa;
    const float* pb = nullptr;
    if (MODE == 2) {
        pa = g_T1 + (size_t)m_fill * 1024;
    } else {
        int b = m_fill >> 10;
        pa = g_A1 + (size_t)((b << 5) + ((m_fill >> 5) & 31)) * 1024;
        pb = g_B1 + (size_t)((b << 5) + (m_fill & 31)) * 1024;
    }

    float2 va[8], vb[8];
    auto ldA = [&](int k0) {
        const int kb = k0 + khalf * 16;
        #pragma unroll
        for (int i = 0; i < 8; ++i) va[i] = *(const float2*)(pa + kb + 2 * i);
        if (MODE == 3) {
            #pragma unroll
            for (int i = 0; i < 8; ++i) vb[i] = *(const float2*)(pb + kb + 2 * i);
        }
    };
    auto stA = [&](uint32_t bufoff) {
        uint32_t hi[8], lo[8];
        #pragma unroll
        for (int i = 0; i < 8; ++i) {
            float h0, h1;
            if (MODE == 2) { h0 = va[i].x; h1 = va[i].y; }
            else {
                h0 = fmaxf(va[i].x + vb[i].x, 0.f);
                h1 = fmaxf(va[i].y + vb[i].y, 0.f);
            }
            __half H0 = __float2half_rn(h0), H1 = __float2half_rn(h1);
            __half L0 = __float2half_rn(h0 - __half2float(H0));
            __half L1 = __float2half_rn(h1 - __half2float(H1));
            hi[i] = packh2(H0, H1);
            lo[i] = packh2(L0, L1);
        }
        const uint32_t a0 = (uint32_t)(ar * 64 + khalf * 32);
        char* dh = p + bufoff + TB_AHI;
        char* dl = p + bufoff + TB_ALO;
        *(uint4*)(dh + SWZ64(a0))      = make_uint4(hi[0], hi[1], hi[2], hi[3]);
        *(uint4*)(dh + SWZ64(a0 + 16)) = make_uint4(hi[4], hi[5], hi[6], hi[7]);
        *(uint4*)(dl + SWZ64(a0))      = make_uint4(lo[0], lo[1], lo[2], lo[3]);
        *(uint4*)(dl + SWZ64(a0 + 16)) = make_uint4(lo[4], lo[5], lo[6], lo[7]);
    };
    // B fill: 2 planes x 256 rows x 4 granules(16B) = 2048 cp.async / 256 thr
    auto fillB = [&](uint32_t bufoff, int k0) {
        #pragma unroll
        for (int t = 0; t < 8; ++t) {
            int idx = tid + t * 256;        // 0..2047
            int plane = idx >> 10;
            int rl = (idx & 1023) >> 2;     // 0..255
            int cc = idx & 3;               // 0..3
            const __half* src = (plane ? WT_lo : WT_hi)
                                + (size_t)(n0 + rl) * 1024 + k0 + cc * 8;
            uint32_t dst = base_u + bufoff + (plane ? TB_BLO : TB_BHI)
                           + SWZ64((uint32_t)(rl * 64 + cc * 16));
            cp16(dst, src);
        }
    };

    // ---- ldmatrix address bases (byte offsets within a tile, 64B rows) ----
    uint32_t aoff[4], boff[4];
    #pragma unroll
    for (int mf = 0; mf < 4; ++mf)
        aoff[mf] = (uint32_t)((wm * 64 + mf * 16 + (lane & 15)) * 64 + (lane >> 4) * 16);
    #pragma unroll
    for (int nf2 = 0; nf2 < 4; ++nf2)
        boff[nf2] = (uint32_t)((wn * 64 + nf2 * 16 + (lane & 7) + ((lane & 16) ? 8 : 0)) * 64
                               + ((lane >> 3) & 1) * 16);

    float acc[4][8][4];
    #pragma unroll
    for (int mf = 0; mf < 4; ++mf)
        #pragma unroll
        for (int nf = 0; nf < 8; ++nf)
            #pragma unroll
            for (int q = 0; q < 4; ++q) acc[mf][nf][q] = 0.f;

    auto compute = [&](uint32_t bufoff) {
        const uint32_t ah_b = base_u + bufoff + TB_AHI;
        const uint32_t al_b = base_u + bufoff + TB_ALO;
        const uint32_t bh_b = base_u + bufoff + TB_BHI;
        const uint32_t bl_b = base_u + bufoff + TB_BLO;
        #pragma unroll
        for (int kf = 0; kf < 2; ++kf) {
            const uint32_t kadd = kf * 32;
            uint32_t ah[4][4], al[4][4];
            #pragma unroll
            for (int mf = 0; mf < 4; ++mf) {
                uint32_t sw = SWZ64(aoff[mf] + kadd);
                ldsm4(ah[mf][0], ah[mf][1], ah[mf][2], ah[mf][3], ah_b + sw);
                ldsm4(al[mf][0], al[mf][1], al[mf][2], al[mf][3], al_b + sw);
            }
            #pragma unroll
            for (int nf2 = 0; nf2 < 4; ++nf2) {
                uint32_t sw = SWZ64(boff[nf2] + kadd);
                uint32_t h0, h1, h2, h3, l0, l1, l2, l3;
                ldsm4(h0, h1, h2, h3, bh_b + sw);
                ldsm4(l0, l1, l2, l3, bl_b + sw);
                uint32_t bh0[2] = {h0, h1}, bh1[2] = {h2, h3};
                uint32_t bl0[2] = {l0, l1}, bl1[2] = {l2, l3};
                #pragma unroll
                for (int mf = 0; mf < 4; ++mf) {
                    mma16816(acc[mf][nf2 * 2],     ah[mf], bh0);
                    mma16816(acc[mf][nf2 * 2],     al[mf], bh0);
                    mma16816(acc[mf][nf2 * 2],     ah[mf], bl0);
                    mma16816(acc[mf][nf2 * 2 + 1], ah[mf], bh1);
                    mma16816(acc[mf][nf2 * 2 + 1], al[mf], bh1);
                    mma16816(acc[mf][nf2 * 2 + 1], ah[mf], bl1);
                }
            }
        }
    };

    // ---- pipelined main loop over K=1024 in 32 chunks of 32 ----
    fillB(0, 0); CP_COMMIT();
    ldA(0);
    stA(0);
    CP_WAIT0();
    __syncthreads();

    #pragma unroll 1
    for (int c = 0; c < NCH; ++c) {
        const uint32_t buf = (uint32_t)(c & 1) * TB_BUF;
        const uint32_t nb  = (uint32_t)((c + 1) & 1) * TB_BUF;
        if (c + 1 < NCH) {
            fillB(nb, (c + 1) * 32); CP_COMMIT();
            ldA((c + 1) * 32);
        }
        compute(buf);
        if (c + 1 < NCH) stA(nb);
        CP_WAIT0();
        __syncthreads();
    }

    // ---- epilogue: fused layer-3  e_m += sum_n w3[n]*relu(D+b2[n]) ----
    #pragma unroll
    for (int mf = 0; mf < 4; ++mf) {
        #pragma unroll
        for (int h = 0; h < 2; ++h) {
            float s = 0.f;
            #pragma unroll
            for (int nf = 0; nf < 8; ++nf) {
                int nl = wn * 64 + nf * 8 + 2 * (lane & 3);
                float d0 = acc[mf][nf][h * 2 + 0];
                float d1 = acc[mf][nf][h * 2 + 1];
                s += fmaxf(d0 + sb2[nl], 0.f) * sw3[nl]
                   + fmaxf(d1 + sb2[nl + 1], 0.f) * sw3[nl + 1];
            }
            s += __shfl_xor_sync(0xffffffffu, s, 1);
            s += __shfl_xor_sync(0xffffffffu, s, 2);
            if ((lane & 3) == 0) {
                int m = mTile * 128 + wm * 64 + mf * 16 + (lane >> 2) + h * 8;
                atomicAdd(&eout[m], s);
            }
        }
    }
}

// ------------------------------------------------------------------ finalize
__global__ void finalize_kernel(const float* __restrict__ edges,
                                const float* __restrict__ t3b,
                                const float* __restrict__ i3b,
                                float* __restrict__ out)
{
    const int b = blockIdx.x;
    const int tid = threadIdx.x;
    const float bias_i = i3b[0];

    float s = 0.f;
    #pragma unroll
    for (int it = 0; it < 4; ++it) {
        int idx = tid + it * 256;
        s += edges[b * 1024 + idx] * (g_eint[b * 1024 + idx] + bias_i);
    }
    if (tid < 32) s += g_erow[b * 32 + tid] + t3b[0];

    __shared__ float red[256];
    red[tid] = s;
    __syncthreads();
    for (int o = 128; o > 0; o >>= 1) {
        if (tid < o) red[tid] += red[tid + o];
        __syncthreads();
    }
    if (tid == 0) out[b] = red[0];
}

// ---------------------------------------------------------------------------
extern "C" void kernel_launch(void* const* d_in, const int* in_sizes, int n_in,
                              void* d_out, int out_size)
{
    const float* x   = (const float*)d_in[0];
    const float* edg = (const float*)d_in[1];
    const float* t1w = (const float*)d_in[2];
    const float* t1b = (const float*)d_in[3];
    const float* t2w = (const float*)d_in[4];
    const float* t2b = (const float*)d_in[5];
    const float* t3w = (const float*)d_in[6];
    const float* t3b = (const float*)d_in[7];
    const float* i1w = (const float*)d_in[8];
    const float* i1b = (const float*)d_in[9];
    const float* i2w = (const float*)d_in[10];
    const float* i2b = (const float*)d_in[11];
    const float* i3w = (const float*)d_in[12];
    const float* i3b = (const float*)d_in[13];
    float* out = (float*)d_out;

    cudaFuncSetAttribute(tensor_stage_kernel<2>,
                         cudaFuncAttributeMaxDynamicSharedMemorySize, TS_SMEM);
    cudaFuncSetAttribute(tensor_stage_kernel<3>,
                         cudaFuncAttributeMaxDynamicSharedMemorySize, TS_SMEM);

    init_kernel<<<512, 256>>>();

    dim3 gp(32, 32, 2);
    prep_transpose<<<gp, dim3(32, 32)>>>(t2w, i2w);

    dim3 g1(32, 24);
    stage1_kernel<<<g1, NTHREADS>>>(x, t1w, t1b, i1w, i1b);

    dim3 g2(32, 4);
    tensor_stage_kernel<2><<<g2, 256, TS_SMEM>>>(t2b, t3w);

    dim3 g3(1024, 4);
    tensor_stage_kernel<3><<<g3, 256, TS_SMEM>>>(i2b, i3w);

    finalize_kernel<<<128, 256>>>(edg, t3b, i3b, out);
}

// round 6
// speedup vs baseline: 2.5487x; 1.0740x over previous
#include <cuda_runtime.h>
#include <cuda_fp16.h>
#include <cstdint>

// ===========================================================================
// Model_86011015070455 — R6: stages 2+3 as pure 3-stage cp.async HMMA pipeline.
//   A-operands pre-materialized as split-fp16 planes in gmem:
//     stage1 seg0 writes T1 hi/lo directly; pair_expand writes relu(A1+B1) hi/lo.
//   Tensor mainloop: cp.async(A,B) -> ldmatrix -> 3-term split-fp16 mma.sync.
// ===========================================================================

__device__ __forceinline__ uint32_t smem_u32(const void* p) {
    uint32_t a;
    asm("{ .reg .u64 t; cvta.to.shared.u64 t, %1; cvt.u32.u64 %0, t; }" : "=r"(a) : "l"(p));
    return a;
}
__device__ __forceinline__ void ldsm4(uint32_t& r0, uint32_t& r1, uint32_t& r2, uint32_t& r3,
                                      uint32_t addr) {
    asm volatile("ldmatrix.sync.aligned.m8n8.x4.shared.b16 {%0,%1,%2,%3}, [%4];"
                 : "=r"(r0), "=r"(r1), "=r"(r2), "=r"(r3) : "r"(addr));
}
__device__ __forceinline__ void mma16816(float* d, const uint32_t* a, const uint32_t* b) {
    asm volatile("mma.sync.aligned.m16n8k16.row.col.f32.f16.f16.f32 "
                 "{%0,%1,%2,%3}, {%4,%5,%6,%7}, {%8,%9}, {%0,%1,%2,%3};"
                 : "+f"(d[0]), "+f"(d[1]), "+f"(d[2]), "+f"(d[3])
                 : "r"(a[0]), "r"(a[1]), "r"(a[2]), "r"(a[3]), "r"(b[0]), "r"(b[1]));
}
__device__ __forceinline__ void cp16(uint32_t dst, const void* src) {
    asm volatile("cp.async.cg.shared.global [%0], [%1], 16;"
                 :: "r"(dst), "l"(__cvta_generic_to_global(src)));
}
#define CP_COMMIT() asm volatile("cp.async.commit_group;")
#define CP_WAIT1()  asm volatile("cp.async.wait_group 1;")
#define CP_WAIT0()  asm volatile("cp.async.wait_group 0;")
#define SWZ64(o) ((o) ^ (((o) >> 3) & 0x30))

__device__ __forceinline__ uint32_t packh2(__half a, __half b) {
    __half2 t = __halves2half2(a, b);
    return *(uint32_t*)&t;
}

// ------------------------------------------------------------- device scratch
__device__ float g_A1[4096 * 1024];             // x @ i1w[:400] + i1b
__device__ float g_B1[4096 * 1024];             // x @ i1w[400:]
__device__ __half g_T1h[4096 * 1024];           // relu(x@t1w+b) split planes
__device__ __half g_T1l[4096 * 1024];
__device__ __half g_PAh[131072u * 1024];        // relu(A1[b,i]+B1[b,j]) planes
__device__ __half g_PAl[131072u * 1024];
__device__ float g_erow[4096];
__device__ float g_eint[131072];
__device__ __half g_T2T_hi[1024 * 1024];        // traj2_w transposed [n][k]
__device__ __half g_T2T_lo[1024 * 1024];
__device__ __half g_I2T_hi[1024 * 1024];        // int2_w transposed [n][k]
__device__ __half g_I2T_lo[1024 * 1024];

__global__ void init_kernel() {
    int idx = blockIdx.x * blockDim.x + threadIdx.x;
    if (idx < 131072) g_eint[idx] = 0.f;
    if (idx < 4096)   g_erow[idx] = 0.f;
}

// ------------------------------------------- prep: transpose + split to fp16
__global__ void prep_transpose(const float* __restrict__ t2w, const float* __restrict__ i2w) {
    __shared__ float tile[32][33];
    const float* src = blockIdx.z ? i2w : t2w;
    __half* dhi = blockIdx.z ? g_I2T_hi : g_T2T_hi;
    __half* dlo = blockIdx.z ? g_I2T_lo : g_T2T_lo;
    int k = blockIdx.y * 32 + threadIdx.y;
    int n = blockIdx.x * 32 + threadIdx.x;
    tile[threadIdx.y][threadIdx.x] = src[k * 1024 + n];
    __syncthreads();
    float v = tile[threadIdx.x][threadIdx.y];
    __half hi = __float2half_rn(v);
    __half lo = __float2half_rn(v - __half2float(hi));
    int nn = blockIdx.x * 32 + threadIdx.y;
    int kk = blockIdx.y * 32 + threadIdx.x;
    dhi[nn * 1024 + kk] = hi;
    dlo[nn * 1024 + kk] = lo;
}

// --------------------------------------------------- stage1 (SIMT fp32 GEMM)
#define BM 128
#define BN 128
#define BK 16
#define TM 8
#define TN 8
#define NTHREADS 256

__global__ __launch_bounds__(NTHREADS)
void stage1_kernel(const float* __restrict__ x,
                   const float* __restrict__ t1w, const float* __restrict__ t1b,
                   const float* __restrict__ i1w, const float* __restrict__ i1b)
{
    __shared__ float As[BK][BM];
    __shared__ float Bs[BK][BN];

    const int K = 400;
    const int mTile = blockIdx.x;
    const int seg   = blockIdx.y >> 3;
    const int n0    = (blockIdx.y & 7) * BN;
    const float* Bmat = (seg == 0) ? t1w : i1w;
    const int kOff = (seg == 2) ? 400 : 0;

    const int tid = threadIdx.x;
    const int tx = tid & 15;
    const int ty = tid >> 4;

    float acc[TM][TN];
    #pragma unroll
    for (int i = 0; i < TM; ++i)
        #pragma unroll
        for (int j = 0; j < TN; ++j) acc[i][j] = 0.f;

    const float* Abase = x + (long)mTile * BM * K;

    for (int k0 = 0; k0 < K; k0 += BK) {
        #pragma unroll
        for (int it = 0; it < 2; ++it) {
            int idx = tid + it * NTHREADS;
            int row = idx >> 2, col4 = (idx & 3) * 4;
            float4 v = *(const float4*)(Abase + row * K + k0 + col4);
            As[col4 + 0][row] = v.x; As[col4 + 1][row] = v.y;
            As[col4 + 2][row] = v.z; As[col4 + 3][row] = v.w;
        }
        #pragma unroll
        for (int it = 0; it < 2; ++it) {
            int idx = tid + it * NTHREADS;
            int row = idx >> 5, col4 = (idx & 31) * 4;
            *(float4*)&Bs[row][col4] =
                *(const float4*)(Bmat + (long)(kOff + k0 + row) * 1024 + n0 + col4);
        }
        __syncthreads();
        #pragma unroll
        for (int k = 0; k < BK; ++k) {
            float a[TM], b[TN];
            #pragma unroll
            for (int i = 0; i < TM; ++i) a[i] = As[k][ty * TM + i];
            #pragma unroll
            for (int j = 0; j < TN; ++j) b[j] = Bs[k][tx * TN + j];
            #pragma unroll
            for (int i = 0; i < TM; ++i)
                #pragma unroll
                for (int j = 0; j < TN; ++j) acc[i][j] += a[i] * b[j];
        }
        __syncthreads();
    }

    const int mBase = mTile * BM + ty * TM;
    if (seg == 0) {
        // write T1 split planes directly
        #pragma unroll
        for (int i = 0; i < TM; ++i)
            #pragma unroll
            for (int j = 0; j < TN; j += 2) {
                int n = n0 + tx * TN + j;
                float v0 = fmaxf(acc[i][j]     + t1b[n],     0.f);
                float v1 = fmaxf(acc[i][j + 1] + t1b[n + 1], 0.f);
                __half H0 = __float2half_rn(v0), H1 = __float2half_rn(v1);
                __half L0 = __float2half_rn(v0 - __half2float(H0));
                __half L1 = __float2half_rn(v1 - __half2float(H1));
                size_t o = (size_t)(mBase + i) * 1024 + n;
                *(uint32_t*)&g_T1h[o] = packh2(H0, H1);
                *(uint32_t*)&g_T1l[o] = packh2(L0, L1);
            }
    } else if (seg == 1) {
        #pragma unroll
        for (int i = 0; i < TM; ++i)
            #pragma unroll
            for (int j = 0; j < TN; ++j) {
                int n = n0 + tx * TN + j;
                g_A1[(mBase + i) * 1024 + n] = acc[i][j] + i1b[n];
            }
    } else {
        #pragma unroll
        for (int i = 0; i < TM; ++i)
            #pragma unroll
            for (int j = 0; j < TN; ++j) {
                int n = n0 + tx * TN + j;
                g_B1[(mBase + i) * 1024 + n] = acc[i][j];
            }
    }
}

// ------------------------- pair expand: materialize relu(A1[b,i]+B1[b,j]) ---
__global__ __launch_bounds__(256)
void pair_expand_kernel()
{
    const int bi = blockIdx.x;          // b*32 + i
    const int b  = bi >> 5;
    const int i  = bi & 31;
    const int t  = threadIdx.x;         // k granule: 4 floats

    float4 av = *(const float4*)&g_A1[(size_t)bi * 1024 + t * 4];
    const float* Bb = g_B1 + (size_t)(b << 5) * 1024;
    const size_t mbase = ((size_t)b << 10) + ((size_t)i << 5);

    #pragma unroll 4
    for (int j = 0; j < 32; ++j) {
        float4 bv = *(const float4*)&Bb[(size_t)j * 1024 + t * 4];
        float h0 = fmaxf(av.x + bv.x, 0.f);
        float h1 = fmaxf(av.y + bv.y, 0.f);
        float h2 = fmaxf(av.z + bv.z, 0.f);
        float h3 = fmaxf(av.w + bv.w, 0.f);
        __half H0 = __float2half_rn(h0), H1 = __float2half_rn(h1);
        __half H2 = __float2half_rn(h2), H3 = __float2half_rn(h3);
        uint2 vh = make_uint2(packh2(H0, H1), packh2(H2, H3));
        uint2 vl = make_uint2(
            packh2(__float2half_rn(h0 - __half2float(H0)),
                   __float2half_rn(h1 - __half2float(H1))),
            packh2(__float2half_rn(h2 - __half2float(H2)),
                   __float2half_rn(h3 - __half2float(H3))));
        size_t m = mbase + j;
        *(uint2*)&g_PAh[m * 1024 + t * 4] = vh;
        *(uint2*)&g_PAl[m * 1024 + t * 4] = vl;
    }
}

// --------------------------------------------- tensor stages (mma.sync HMMA)
// MODE 2: A planes g_T1h/l (4096 rows) -> g_erow
// MODE 3: A planes g_PAh/l (131072 rows) -> g_eint
// CTA tile M=128, N=256; warps 2m x 4n (warp tile 64x64); K chunks of 32.
// 3-stage cp.async pipeline; smem rows 64B, SW64 swizzle.

static constexpr uint32_t TB_AHI = 0;
static constexpr uint32_t TB_ALO = 8 * 1024;
static constexpr uint32_t TB_BHI = 16 * 1024;
static constexpr uint32_t TB_BLO = 32 * 1024;
static constexpr uint32_t TB_STAGE = 48 * 1024;
static constexpr int NSTAGE = 3;
static constexpr uint32_t TS_SMEM = NSTAGE * TB_STAGE + 2048 + 1024;
static constexpr int NCH = 32;   // 1024 / 32

template <int MODE>
__global__ __launch_bounds__(256)
void tensor_stage_kernel(const float* __restrict__ b2g, const float* __restrict__ w3g)
{
    extern __shared__ char smem_raw[];
    const uint32_t smem_u = smem_u32(smem_raw);
    const uint32_t base_u = (smem_u + 1023) & ~1023u;
    char* p = smem_raw + (base_u - smem_u);

    float* sb2 = (float*)(p + NSTAGE * TB_STAGE);
    float* sw3 = sb2 + 256;

    const int tid  = threadIdx.x;
    const int lane = tid & 31;
    const int wid  = tid >> 5;
    const int wm   = wid & 1;        // warp row (64 m each)
    const int wn   = wid >> 1;       // warp col (64 n each)
    const int mTile = blockIdx.x;
    const int n0    = blockIdx.y * 256;
    const int m0    = mTile * 128;

    const __half* Ah = (MODE == 2) ? g_T1h : g_PAh;
    const __half* Al = (MODE == 2) ? g_T1l : g_PAl;
    const __half* WT_hi = (MODE == 2) ? g_T2T_hi : g_I2T_hi;
    const __half* WT_lo = (MODE == 2) ? g_T2T_lo : g_I2T_lo;
    float* eout = (MODE == 2) ? g_erow : g_eint;

    sb2[tid] = b2g[n0 + tid];
    sw3[tid] = w3g[n0 + tid];

    // ---- async fill of one stage: A (1024 granules) + B (2048 granules) ----
    auto fillAB = [&](int stage, int k0) {
        const uint32_t sb = base_u + (uint32_t)stage * TB_STAGE;
        #pragma unroll
        for (int t = 0; t < 4; ++t) {           // A: 2 planes x 128 rows x 4
            int idx = tid + t * 256;            // 0..1023
            int plane = idx >> 9;
            int rl = (idx >> 2) & 127;
            int cc = idx & 3;
            const __half* src = (plane ? Al : Ah)
                                + (size_t)(m0 + rl) * 1024 + k0 + cc * 8;
            cp16(sb + (plane ? TB_ALO : TB_AHI) + SWZ64((uint32_t)(rl * 64 + cc * 16)), src);
        }
        #pragma unroll
        for (int t = 0; t < 8; ++t) {           // B: 2 planes x 256 rows x 4
            int idx = tid + t * 256;            // 0..2047
            int plane = idx >> 10;
            int rl = (idx & 1023) >> 2;
            int cc = idx & 3;
            const __half* src = (plane ? WT_lo : WT_hi)
                                + (size_t)(n0 + rl) * 1024 + k0 + cc * 8;
            cp16(sb + (plane ? TB_BLO : TB_BHI) + SWZ64((uint32_t)(rl * 64 + cc * 16)), src);
        }
    };

    // ---- ldmatrix address bases (byte offsets within a tile, 64B rows) ----
    uint32_t aoff[4], boff[4];
    #pragma unroll
    for (int mf = 0; mf < 4; ++mf)
        aoff[mf] = (uint32_t)((wm * 64 + mf * 16 + (lane & 15)) * 64 + (lane >> 4) * 16);
    #pragma unroll
    for (int nf2 = 0; nf2 < 4; ++nf2)
        boff[nf2] = (uint32_t)((wn * 64 + nf2 * 16 + (lane & 7) + ((lane & 16) ? 8 : 0)) * 64
                               + ((lane >> 3) & 1) * 16);

    float acc[4][8][4];
    #pragma unroll
    for (int mf = 0; mf < 4; ++mf)
        #pragma unroll
        for (int nf = 0; nf < 8; ++nf)
            #pragma unroll
            for (int q = 0; q < 4; ++q) acc[mf][nf][q] = 0.f;

    auto compute = [&](int stage) {
        const uint32_t sb = base_u + (uint32_t)stage * TB_STAGE;
        const uint32_t ah_b = sb + TB_AHI;
        const uint32_t al_b = sb + TB_ALO;
        const uint32_t bh_b = sb + TB_BHI;
        const uint32_t bl_b = sb + TB_BLO;
        #pragma unroll
        for (int kf = 0; kf < 2; ++kf) {
            const uint32_t kadd = kf * 32;
            uint32_t ah[4][4], al[4][4];
            #pragma unroll
            for (int mf = 0; mf < 4; ++mf) {
                uint32_t sw = SWZ64(aoff[mf] + kadd);
                ldsm4(ah[mf][0], ah[mf][1], ah[mf][2], ah[mf][3], ah_b + sw);
                ldsm4(al[mf][0], al[mf][1], al[mf][2], al[mf][3], al_b + sw);
            }
            #pragma unroll
            for (int nf2 = 0; nf2 < 4; ++nf2) {
                uint32_t sw = SWZ64(boff[nf2] + kadd);
                uint32_t h0, h1, h2, h3, l0, l1, l2, l3;
                ldsm4(h0, h1, h2, h3, bh_b + sw);
                ldsm4(l0, l1, l2, l3, bl_b + sw);
                uint32_t bh0[2] = {h0, h1}, bh1[2] = {h2, h3};
                uint32_t bl0[2] = {l0, l1}, bl1[2] = {l2, l3};
                #pragma unroll
                for (int mf = 0; mf < 4; ++mf) {
                    mma16816(acc[mf][nf2 * 2],     ah[mf], bh0);
                    mma16816(acc[mf][nf2 * 2],     al[mf], bh0);
                    mma16816(acc[mf][nf2 * 2],     ah[mf], bl0);
                    mma16816(acc[mf][nf2 * 2 + 1], ah[mf], bh1);
                    mma16816(acc[mf][nf2 * 2 + 1], al[mf], bh1);
                    mma16816(acc[mf][nf2 * 2 + 1], ah[mf], bl1);
                }
            }
        }
    };

    // ---- 3-stage pipelined main loop over K=1024 in 32 chunks of 32 ----
    fillAB(0, 0);  CP_COMMIT();
    fillAB(1, 32); CP_COMMIT();

    #pragma unroll 1
    for (int c = 0; c < NCH; ++c) {
        if (c + 2 < NCH) { fillAB((c + 2) % NSTAGE, (c + 2) * 32); CP_COMMIT(); }
        if (c + 1 < NCH) CP_WAIT1(); else CP_WAIT0();
        __syncthreads();
        compute(c % NSTAGE);
        __syncthreads();
    }

    // ---- epilogue: fused layer-3  e_m += sum_n w3[n]*relu(D+b2[n]) ----
    #pragma unroll
    for (int mf = 0; mf < 4; ++mf) {
        #pragma unroll
        for (int h = 0; h < 2; ++h) {
            float s = 0.f;
            #pragma unroll
            for (int nf = 0; nf < 8; ++nf) {
                int nl = wn * 64 + nf * 8 + 2 * (lane & 3);
                float d0 = acc[mf][nf][h * 2 + 0];
                float d1 = acc[mf][nf][h * 2 + 1];
                s += fmaxf(d0 + sb2[nl], 0.f) * sw3[nl]
                   + fmaxf(d1 + sb2[nl + 1], 0.f) * sw3[nl + 1];
            }
            s += __shfl_xor_sync(0xffffffffu, s, 1);
            s += __shfl_xor_sync(0xffffffffu, s, 2);
            if ((lane & 3) == 0) {
                int m = m0 + wm * 64 + mf * 16 + (lane >> 2) + h * 8;
                atomicAdd(&eout[m], s);
            }
        }
    }
}

// ------------------------------------------------------------------ finalize
__global__ void finalize_kernel(const float* __restrict__ edges,
                                const float* __restrict__ t3b,
                                const float* __restrict__ i3b,
                                float* __restrict__ out)
{
    const int b = blockIdx.x;
    const int tid = threadIdx.x;
    const float bias_i = i3b[0];

    float s = 0.f;
    #pragma unroll
    for (int it = 0; it < 4; ++it) {
        int idx = tid + it * 256;
        s += edges[b * 1024 + idx] * (g_eint[b * 1024 + idx] + bias_i);
    }
    if (tid < 32) s += g_erow[b * 32 + tid] + t3b[0];

    __shared__ float red[256];
    red[tid] = s;
    __syncthreads();
    for (int o = 128; o > 0; o >>= 1) {
        if (tid < o) red[tid] += red[tid + o];
        __syncthreads();
    }
    if (tid == 0) out[b] = red[0];
}

// ---------------------------------------------------------------------------
extern "C" void kernel_launch(void* const* d_in, const int* in_sizes, int n_in,
                              void* d_out, int out_size)
{
    const float* x   = (const float*)d_in[0];
    const float* edg = (const float*)d_in[1];
    const float* t1w = (const float*)d_in[2];
    const float* t1b = (const float*)d_in[3];
    const float* t2w = (const float*)d_in[4];
    const float* t2b = (const float*)d_in[5];
    const float* t3w = (const float*)d_in[6];
    const float* t3b = (const float*)d_in[7];
    const float* i1w = (const float*)d_in[8];
    const float* i1b = (const float*)d_in[9];
    const float* i2w = (const float*)d_in[10];
    const float* i2b = (const float*)d_in[11];
    const float* i3w = (const float*)d_in[12];
    const float* i3b = (const float*)d_in[13];
    float* out = (float*)d_out;

    cudaFuncSetAttribute(tensor_stage_kernel<2>,
                         cudaFuncAttributeMaxDynamicSharedMemorySize, TS_SMEM);
    cudaFuncSetAttribute(tensor_stage_kernel<3>,
                         cudaFuncAttributeMaxDynamicSharedMemorySize, TS_SMEM);

    init_kernel<<<512, 256>>>();

    dim3 gp(32, 32, 2);
    prep_transpose<<<gp, dim3(32, 32)>>>(t2w, i2w);

    dim3 g1(32, 24);
    stage1_kernel<<<g1, NTHREADS>>>(x, t1w, t1b, i1w, i1b);

    pair_expand_kernel<<<4096, 256>>>();

    dim3 g2(32, 4);
    tensor_stage_kernel<2><<<g2, 256, TS_SMEM>>>(t2b, t3w);

    dim3 g3(1024, 4);
    tensor_stage_kernel<3><<<g3, 256, TS_SMEM>>>(i2b, i3w);

    finalize_kernel<<<128, 256>>>(edg, t3b, i3b, out);
}

// round 7
// speedup vs baseline: 2.5651x; 1.0064x over previous
#include <cuda_runtime.h>
#include <cuda_fp16.h>
#include <cstdint>

// ===========================================================================
// Model_86011015070455 — R7: mma issue reorder (term-major, acc-interleaved)
//   + stage2 merged into stage3 grid. 3-stage cp.async pipeline unchanged.
// ===========================================================================

__device__ __forceinline__ uint32_t smem_u32(const void* p) {
    uint32_t a;
    asm("{ .reg .u64 t; cvta.to.shared.u64 t, %1; cvt.u32.u64 %0, t; }" : "=r"(a) : "l"(p));
    return a;
}
__device__ __forceinline__ void ldsm4(uint32_t& r0, uint32_t& r1, uint32_t& r2, uint32_t& r3,
                                      uint32_t addr) {
    asm volatile("ldmatrix.sync.aligned.m8n8.x4.shared.b16 {%0,%1,%2,%3}, [%4];"
                 : "=r"(r0), "=r"(r1), "=r"(r2), "=r"(r3) : "r"(addr));
}
__device__ __forceinline__ void mma16816(float* d, const uint32_t* a, const uint32_t* b) {
    asm volatile("mma.sync.aligned.m16n8k16.row.col.f32.f16.f16.f32 "
                 "{%0,%1,%2,%3}, {%4,%5,%6,%7}, {%8,%9}, {%0,%1,%2,%3};"
                 : "+f"(d[0]), "+f"(d[1]), "+f"(d[2]), "+f"(d[3])
                 : "r"(a[0]), "r"(a[1]), "r"(a[2]), "r"(a[3]), "r"(b[0]), "r"(b[1]));
}
__device__ __forceinline__ void cp16(uint32_t dst, const void* src) {
    asm volatile("cp.async.cg.shared.global [%0], [%1], 16;"
                 :: "r"(dst), "l"(__cvta_generic_to_global(src)));
}
#define CP_COMMIT() asm volatile("cp.async.commit_group;")
#define CP_WAIT1()  asm volatile("cp.async.wait_group 1;")
#define CP_WAIT0()  asm volatile("cp.async.wait_group 0;")
#define SWZ64(o) ((o) ^ (((o) >> 3) & 0x30))

__device__ __forceinline__ uint32_t packh2(__half a, __half b) {
    __half2 t = __halves2half2(a, b);
    return *(uint32_t*)&t;
}

// ------------------------------------------------------------- device scratch
__device__ float g_A1[4096 * 1024];
__device__ float g_B1[4096 * 1024];
__device__ __half g_T1h[4096 * 1024];
__device__ __half g_T1l[4096 * 1024];
__device__ __half g_PAh[131072u * 1024];
__device__ __half g_PAl[131072u * 1024];
__device__ float g_erow[4096];
__device__ float g_eint[131072];
__device__ __half g_T2T_hi[1024 * 1024];
__device__ __half g_T2T_lo[1024 * 1024];
__device__ __half g_I2T_hi[1024 * 1024];
__device__ __half g_I2T_lo[1024 * 1024];

__global__ void init_kernel() {
    int idx = blockIdx.x * blockDim.x + threadIdx.x;
    if (idx < 131072) g_eint[idx] = 0.f;
    if (idx < 4096)   g_erow[idx] = 0.f;
}

// ------------------------------------------- prep: transpose + split to fp16
__global__ void prep_transpose(const float* __restrict__ t2w, const float* __restrict__ i2w) {
    __shared__ float tile[32][33];
    const float* src = blockIdx.z ? i2w : t2w;
    __half* dhi = blockIdx.z ? g_I2T_hi : g_T2T_hi;
    __half* dlo = blockIdx.z ? g_I2T_lo : g_T2T_lo;
    int k = blockIdx.y * 32 + threadIdx.y;
    int n = blockIdx.x * 32 + threadIdx.x;
    tile[threadIdx.y][threadIdx.x] = src[k * 1024 + n];
    __syncthreads();
    float v = tile[threadIdx.x][threadIdx.y];
    __half hi = __float2half_rn(v);
    __half lo = __float2half_rn(v - __half2float(hi));
    int nn = blockIdx.x * 32 + threadIdx.y;
    int kk = blockIdx.y * 32 + threadIdx.x;
    dhi[nn * 1024 + kk] = hi;
    dlo[nn * 1024 + kk] = lo;
}

// --------------------------------------------------- stage1 (SIMT fp32 GEMM)
#define BM 128
#define BN 128
#define BK 16
#define TM 8
#define TN 8
#define NTHREADS 256

__global__ __launch_bounds__(NTHREADS)
void stage1_kernel(const float* __restrict__ x,
                   const float* __restrict__ t1w, const float* __restrict__ t1b,
                   const float* __restrict__ i1w, const float* __restrict__ i1b)
{
    __shared__ float As[BK][BM];
    __shared__ float Bs[BK][BN];

    const int K = 400;
    const int mTile = blockIdx.x;
    const int seg   = blockIdx.y >> 3;
    const int n0    = (blockIdx.y & 7) * BN;
    const float* Bmat = (seg == 0) ? t1w : i1w;
    const int kOff = (seg == 2) ? 400 : 0;

    const int tid = threadIdx.x;
    const int tx = tid & 15;
    const int ty = tid >> 4;

    float acc[TM][TN];
    #pragma unroll
    for (int i = 0; i < TM; ++i)
        #pragma unroll
        for (int j = 0; j < TN; ++j) acc[i][j] = 0.f;

    const float* Abase = x + (long)mTile * BM * K;

    for (int k0 = 0; k0 < K; k0 += BK) {
        #pragma unroll
        for (int it = 0; it < 2; ++it) {
            int idx = tid + it * NTHREADS;
            int row = idx >> 2, col4 = (idx & 3) * 4;
            float4 v = *(const float4*)(Abase + row * K + k0 + col4);
            As[col4 + 0][row] = v.x; As[col4 + 1][row] = v.y;
            As[col4 + 2][row] = v.z; As[col4 + 3][row] = v.w;
        }
        #pragma unroll
        for (int it = 0; it < 2; ++it) {
            int idx = tid + it * NTHREADS;
            int row = idx >> 5, col4 = (idx & 31) * 4;
            *(float4*)&Bs[row][col4] =
                *(const float4*)(Bmat + (long)(kOff + k0 + row) * 1024 + n0 + col4);
        }
        __syncthreads();
        #pragma unroll
        for (int k = 0; k < BK; ++k) {
            float a[TM], b[TN];
            #pragma unroll
            for (int i = 0; i < TM; ++i) a[i] = As[k][ty * TM + i];
            #pragma unroll
            for (int j = 0; j < TN; ++j) b[j] = Bs[k][tx * TN + j];
            #pragma unroll
            for (int i = 0; i < TM; ++i)
                #pragma unroll
                for (int j = 0; j < TN; ++j) acc[i][j] += a[i] * b[j];
        }
        __syncthreads();
    }

    const int mBase = mTile * BM + ty * TM;
    if (seg == 0) {
        #pragma unroll
        for (int i = 0; i < TM; ++i)
            #pragma unroll
            for (int j = 0; j < TN; j += 2) {
                int n = n0 + tx * TN + j;
                float v0 = fmaxf(acc[i][j]     + t1b[n],     0.f);
                float v1 = fmaxf(acc[i][j + 1] + t1b[n + 1], 0.f);
                __half H0 = __float2half_rn(v0), H1 = __float2half_rn(v1);
                __half L0 = __float2half_rn(v0 - __half2float(H0));
                __half L1 = __float2half_rn(v1 - __half2float(H1));
                size_t o = (size_t)(mBase + i) * 1024 + n;
                *(uint32_t*)&g_T1h[o] = packh2(H0, H1);
                *(uint32_t*)&g_T1l[o] = packh2(L0, L1);
            }
    } else if (seg == 1) {
        #pragma unroll
        for (int i = 0; i < TM; ++i)
            #pragma unroll
            for (int j = 0; j < TN; ++j) {
                int n = n0 + tx * TN + j;
                g_A1[(mBase + i) * 1024 + n] = acc[i][j] + i1b[n];
            }
    } else {
        #pragma unroll
        for (int i = 0; i < TM; ++i)
            #pragma unroll
            for (int j = 0; j < TN; ++j) {
                int n = n0 + tx * TN + j;
                g_B1[(mBase + i) * 1024 + n] = acc[i][j];
            }
    }
}

// ------------------------- pair expand: materialize relu(A1[b,i]+B1[b,j]) ---
__global__ __launch_bounds__(256)
void pair_expand_kernel()
{
    const int bi = blockIdx.x;          // b*32 + i
    const int b  = bi >> 5;
    const int i  = bi & 31;
    const int t  = threadIdx.x;         // k granule: 4 floats

    float4 av = *(const float4*)&g_A1[(size_t)bi * 1024 + t * 4];
    const float* Bb = g_B1 + (size_t)(b << 5) * 1024;
    const size_t mbase = ((size_t)b << 10) + ((size_t)i << 5);

    #pragma unroll 4
    for (int j = 0; j < 32; ++j) {
        float4 bv = *(const float4*)&Bb[(size_t)j * 1024 + t * 4];
        float h0 = fmaxf(av.x + bv.x, 0.f);
        float h1 = fmaxf(av.y + bv.y, 0.f);
        float h2 = fmaxf(av.z + bv.z, 0.f);
        float h3 = fmaxf(av.w + bv.w, 0.f);
        __half H0 = __float2half_rn(h0), H1 = __float2half_rn(h1);
        __half H2 = __float2half_rn(h2), H3 = __float2half_rn(h3);
        uint2 vh = make_uint2(packh2(H0, H1), packh2(H2, H3));
        uint2 vl = make_uint2(
            packh2(__float2half_rn(h0 - __half2float(H0)),
                   __float2half_rn(h1 - __half2float(H1))),
            packh2(__float2half_rn(h2 - __half2float(H2)),
                   __float2half_rn(h3 - __half2float(H3))));
        size_t m = mbase + j;
        *(uint2*)&g_PAh[m * 1024 + t * 4] = vh;
        *(uint2*)&g_PAl[m * 1024 + t * 4] = vl;
    }
}

// --------------------------------------------- unified tensor stage (HMMA)
// blockIdx.x <  1024 : interaction rows (g_PAh/l -> g_eint), mtile = x
// blockIdx.x >= 1024 : traj rows        (g_T1h/l -> g_erow), mtile = x-1024
// CTA tile M=128, N=256; warps 2m x 4n; K chunks of 32; 3-stage cp.async.
// mma issued term-major: 32 distinct accumulators between same-acc reuses.

static constexpr uint32_t TB_AHI = 0;
static constexpr uint32_t TB_ALO = 8 * 1024;
static constexpr uint32_t TB_BHI = 16 * 1024;
static constexpr uint32_t TB_BLO = 32 * 1024;
static constexpr uint32_t TB_STAGE = 48 * 1024;
static constexpr int NSTAGE = 3;
static constexpr uint32_t TS_SMEM = NSTAGE * TB_STAGE + 2048 + 1024;
static constexpr int NCH = 32;   // 1024 / 32

__global__ __launch_bounds__(256)
void tensor_stage_kernel(const float* __restrict__ t2b, const float* __restrict__ t3w,
                         const float* __restrict__ i2b, const float* __restrict__ i3w)
{
    extern __shared__ char smem_raw[];
    const uint32_t smem_u = smem_u32(smem_raw);
    const uint32_t base_u = (smem_u + 1023) & ~1023u;
    char* p = smem_raw + (base_u - smem_u);

    float* sb2 = (float*)(p + NSTAGE * TB_STAGE);
    float* sw3 = sb2 + 256;

    const int tid  = threadIdx.x;
    const int lane = tid & 31;
    const int wid  = tid >> 5;
    const int wm   = wid & 1;
    const int wn   = wid >> 1;

    const bool traj = (blockIdx.x >= 1024);
    const int mTile = traj ? (blockIdx.x - 1024) : blockIdx.x;
    const int n0    = blockIdx.y * 256;
    const int m0    = mTile * 128;

    const __half* Ah    = traj ? g_T1h    : g_PAh;
    const __half* Al    = traj ? g_T1l    : g_PAl;
    const __half* WT_hi = traj ? g_T2T_hi : g_I2T_hi;
    const __half* WT_lo = traj ? g_T2T_lo : g_I2T_lo;
    const float*  b2g   = traj ? t2b : i2b;
    const float*  w3g   = traj ? t3w : i3w;
    float* eout         = traj ? g_erow : g_eint;

    sb2[tid] = b2g[n0 + tid];
    sw3[tid] = w3g[n0 + tid];

    // ---- async fill of one stage: A (1024 granules) + B (2048 granules) ----
    auto fillAB = [&](int stage, int k0) {
        const uint32_t sb = base_u + (uint32_t)stage * TB_STAGE;
        #pragma unroll
        for (int t = 0; t < 4; ++t) {
            int idx = tid + t * 256;
            int plane = idx >> 9;
            int rl = (idx >> 2) & 127;
            int cc = idx & 3;
            const __half* src = (plane ? Al : Ah)
                                + (size_t)(m0 + rl) * 1024 + k0 + cc * 8;
            cp16(sb + (plane ? TB_ALO : TB_AHI) + SWZ64((uint32_t)(rl * 64 + cc * 16)), src);
        }
        #pragma unroll
        for (int t = 0; t < 8; ++t) {
            int idx = tid + t * 256;
            int plane = idx >> 10;
            int rl = (idx & 1023) >> 2;
            int cc = idx & 3;
            const __half* src = (plane ? WT_lo : WT_hi)
                                + (size_t)(n0 + rl) * 1024 + k0 + cc * 8;
            cp16(sb + (plane ? TB_BLO : TB_BHI) + SWZ64((uint32_t)(rl * 64 + cc * 16)), src);
        }
    };

    // ---- ldmatrix address bases ----
    uint32_t aoff[4], boff[4];
    #pragma unroll
    for (int mf = 0; mf < 4; ++mf)
        aoff[mf] = (uint32_t)((wm * 64 + mf * 16 + (lane & 15)) * 64 + (lane >> 4) * 16);
    #pragma unroll
    for (int nf2 = 0; nf2 < 4; ++nf2)
        boff[nf2] = (uint32_t)((wn * 64 + nf2 * 16 + (lane & 7) + ((lane & 16) ? 8 : 0)) * 64
                               + ((lane >> 3) & 1) * 16);

    float acc[4][8][4];
    #pragma unroll
    for (int mf = 0; mf < 4; ++mf)
        #pragma unroll
        for (int nf = 0; nf < 8; ++nf)
            #pragma unroll
            for (int q = 0; q < 4; ++q) acc[mf][nf][q] = 0.f;

    // term-major issue: same-acc reuse distance = 32 mma (no RAW stalls)
    auto compute = [&](int stage) {
        const uint32_t sb = base_u + (uint32_t)stage * TB_STAGE;
        #pragma unroll
        for (int kf = 0; kf < 2; ++kf) {
            const uint32_t kadd = kf * 32;
            uint32_t ah[4][4], al[4][4], bf[8][2];
            #pragma unroll
            for (int mf = 0; mf < 4; ++mf) {
                uint32_t sw = SWZ64(aoff[mf] + kadd);
                ldsm4(ah[mf][0], ah[mf][1], ah[mf][2], ah[mf][3], sb + TB_AHI + sw);
                ldsm4(al[mf][0], al[mf][1], al[mf][2], al[mf][3], sb + TB_ALO + sw);
            }
            #pragma unroll
            for (int nf2 = 0; nf2 < 4; ++nf2) {
                uint32_t sw = SWZ64(boff[nf2] + kadd);
                ldsm4(bf[nf2 * 2][0], bf[nf2 * 2][1],
                      bf[nf2 * 2 + 1][0], bf[nf2 * 2 + 1][1], sb + TB_BHI + sw);
            }
            // pass 1: Ahi * Bhi
            #pragma unroll
            for (int mf = 0; mf < 4; ++mf)
                #pragma unroll
                for (int nf = 0; nf < 8; ++nf)
                    mma16816(acc[mf][nf], ah[mf], bf[nf]);
            // pass 2: Alo * Bhi
            #pragma unroll
            for (int mf = 0; mf < 4; ++mf)
                #pragma unroll
                for (int nf = 0; nf < 8; ++nf)
                    mma16816(acc[mf][nf], al[mf], bf[nf]);
            // reload B-lo into bf (bh dead)
            #pragma unroll
            for (int nf2 = 0; nf2 < 4; ++nf2) {
                uint32_t sw = SWZ64(boff[nf2] + kadd);
                ldsm4(bf[nf2 * 2][0], bf[nf2 * 2][1],
                      bf[nf2 * 2 + 1][0], bf[nf2 * 2 + 1][1], sb + TB_BLO + sw);
            }
            // pass 3: Ahi * Blo
            #pragma unroll
            for (int mf = 0; mf < 4; ++mf)
                #pragma unroll
                for (int nf = 0; nf < 8; ++nf)
                    mma16816(acc[mf][nf], ah[mf], bf[nf]);
        }
    };

    // ---- 3-stage pipelined main loop ----
    fillAB(0, 0);  CP_COMMIT();
    fillAB(1, 32); CP_COMMIT();

    #pragma unroll 1
    for (int c = 0; c < NCH; ++c) {
        if (c + 2 < NCH) { fillAB((c + 2) % NSTAGE, (c + 2) * 32); CP_COMMIT(); }
        if (c + 1 < NCH) CP_WAIT1(); else CP_WAIT0();
        __syncthreads();
        compute(c % NSTAGE);
        __syncthreads();
    }

    // ---- epilogue: fused layer-3  e_m += sum_n w3[n]*relu(D+b2[n]) ----
    #pragma unroll
    for (int mf = 0; mf < 4; ++mf) {
        #pragma unroll
        for (int h = 0; h < 2; ++h) {
            float s = 0.f;
            #pragma unroll
            for (int nf = 0; nf < 8; ++nf) {
                int nl = wn * 64 + nf * 8 + 2 * (lane & 3);
                float d0 = acc[mf][nf][h * 2 + 0];
                float d1 = acc[mf][nf][h * 2 + 1];
                s += fmaxf(d0 + sb2[nl], 0.f) * sw3[nl]
                   + fmaxf(d1 + sb2[nl + 1], 0.f) * sw3[nl + 1];
            }
            s += __shfl_xor_sync(0xffffffffu, s, 1);
            s += __shfl_xor_sync(0xffffffffu, s, 2);
            if ((lane & 3) == 0) {
                int m = m0 + wm * 64 + mf * 16 + (lane >> 2) + h * 8;
                atomicAdd(&eout[m], s);
            }
        }
    }
}

// ------------------------------------------------------------------ finalize
__global__ void finalize_kernel(const float* __restrict__ edges,
                                const float* __restrict__ t3b,
                                const float* __restrict__ i3b,
                                float* __restrict__ out)
{
    const int b = blockIdx.x;
    const int tid = threadIdx.x;
    const float bias_i = i3b[0];

    float s = 0.f;
    #pragma unroll
    for (int it = 0; it < 4; ++it) {
        int idx = tid + it * 256;
        s += edges[b * 1024 + idx] * (g_eint[b * 1024 + idx] + bias_i);
    }
    if (tid < 32) s += g_erow[b * 32 + tid] + t3b[0];

    __shared__ float red[256];
    red[tid] = s;
    __syncthreads();
    for (int o = 128; o > 0; o >>= 1) {
        if (tid < o) red[tid] += red[tid + o];
        __syncthreads();
    }
    if (tid == 0) out[b] = red[0];
}

// ---------------------------------------------------------------------------
extern "C" void kernel_launch(void* const* d_in, const int* in_sizes, int n_in,
                              void* d_out, int out_size)
{
    const float* x   = (const float*)d_in[0];
    const float* edg = (const float*)d_in[1];
    const float* t1w = (const float*)d_in[2];
    const float* t1b = (const float*)d_in[3];
    const float* t2w = (const float*)d_in[4];
    const float* t2b = (const float*)d_in[5];
    const float* t3w = (const float*)d_in[6];
    const float* t3b = (const float*)d_in[7];
    const float* i1w = (const float*)d_in[8];
    const float* i1b = (const float*)d_in[9];
    const float* i2w = (const float*)d_in[10];
    const float* i2b = (const float*)d_in[11];
    const float* i3w = (const float*)d_in[12];
    const float* i3b = (const float*)d_in[13];
    float* out = (float*)d_out;

    cudaFuncSetAttribute(tensor_stage_kernel,
                         cudaFuncAttributeMaxDynamicSharedMemorySize, TS_SMEM);

    init_kernel<<<512, 256>>>();

    dim3 gp(32, 32, 2);
    prep_transpose<<<gp, dim3(32, 32)>>>(t2w, i2w);

    dim3 g1(32, 24);
    stage1_kernel<<<g1, NTHREADS>>>(x, t1w, t1b, i1w, i1b);

    pair_expand_kernel<<<4096, 256>>>();

    dim3 gt(1056, 4);   // x<1024: interaction; x>=1024: traj (32 mtiles)
    tensor_stage_kernel<<<gt, 256, TS_SMEM>>>(t2b, t3w, i2b, i3w);

    finalize_kernel<<<128, 256>>>(edg, t3b, i3b, out);
}

// round 8
// speedup vs baseline: 2.8275x; 1.1023x over previous
#include <cuda_runtime.h>
#include <cuda_fp16.h>
#include <cstdint>

// ===========================================================================
// Model_86011015070455 — R8: 128-thread CTAs, 2 CTAs/SM co-residency for the
//   tensor stage (latency hiding across independent CTAs). Tile 128x128,
//   warp tile 64x64, 3-stage cp.async, 3-term split-fp16 HMMA.
// ===========================================================================

__device__ __forceinline__ uint32_t smem_u32(const void* p) {
    uint32_t a;
    asm("{ .reg .u64 t; cvta.to.shared.u64 t, %1; cvt.u32.u64 %0, t; }" : "=r"(a) : "l"(p));
    return a;
}
__device__ __forceinline__ void ldsm4(uint32_t& r0, uint32_t& r1, uint32_t& r2, uint32_t& r3,
                                      uint32_t addr) {
    asm volatile("ldmatrix.sync.aligned.m8n8.x4.shared.b16 {%0,%1,%2,%3}, [%4];"
                 : "=r"(r0), "=r"(r1), "=r"(r2), "=r"(r3) : "r"(addr));
}
__device__ __forceinline__ void mma16816(float* d, const uint32_t* a, const uint32_t* b) {
    asm volatile("mma.sync.aligned.m16n8k16.row.col.f32.f16.f16.f32 "
                 "{%0,%1,%2,%3}, {%4,%5,%6,%7}, {%8,%9}, {%0,%1,%2,%3};"
                 : "+f"(d[0]), "+f"(d[1]), "+f"(d[2]), "+f"(d[3])
                 : "r"(a[0]), "r"(a[1]), "r"(a[2]), "r"(a[3]), "r"(b[0]), "r"(b[1]));
}
__device__ __forceinline__ void cp16(uint32_t dst, const void* src) {
    asm volatile("cp.async.cg.shared.global [%0], [%1], 16;"
                 :: "r"(dst), "l"(__cvta_generic_to_global(src)));
}
#define CP_COMMIT() asm volatile("cp.async.commit_group;")
#define CP_WAIT1()  asm volatile("cp.async.wait_group 1;")
#define CP_WAIT0()  asm volatile("cp.async.wait_group 0;")
#define SWZ64(o) ((o) ^ (((o) >> 3) & 0x30))

__device__ __forceinline__ uint32_t packh2(__half a, __half b) {
    __half2 t = __halves2half2(a, b);
    return *(uint32_t*)&t;
}

// ------------------------------------------------------------- device scratch
__device__ float g_A1[4096 * 1024];
__device__ float g_B1[4096 * 1024];
__device__ __half g_T1h[4096 * 1024];
__device__ __half g_T1l[4096 * 1024];
__device__ __half g_PAh[131072u * 1024];
__device__ __half g_PAl[131072u * 1024];
__device__ float g_erow[4096];
__device__ float g_eint[131072];
__device__ __half g_T2T_hi[1024 * 1024];
__device__ __half g_T2T_lo[1024 * 1024];
__device__ __half g_I2T_hi[1024 * 1024];
__device__ __half g_I2T_lo[1024 * 1024];

__global__ void init_kernel() {
    int idx = blockIdx.x * blockDim.x + threadIdx.x;
    if (idx < 131072) g_eint[idx] = 0.f;
    if (idx < 4096)   g_erow[idx] = 0.f;
}

// ------------------------------------------- prep: transpose + split to fp16
__global__ void prep_transpose(const float* __restrict__ t2w, const float* __restrict__ i2w) {
    __shared__ float tile[32][33];
    const float* src = blockIdx.z ? i2w : t2w;
    __half* dhi = blockIdx.z ? g_I2T_hi : g_T2T_hi;
    __half* dlo = blockIdx.z ? g_I2T_lo : g_T2T_lo;
    int k = blockIdx.y * 32 + threadIdx.y;
    int n = blockIdx.x * 32 + threadIdx.x;
    tile[threadIdx.y][threadIdx.x] = src[k * 1024 + n];
    __syncthreads();
    float v = tile[threadIdx.x][threadIdx.y];
    __half hi = __float2half_rn(v);
    __half lo = __float2half_rn(v - __half2float(hi));
    int nn = blockIdx.x * 32 + threadIdx.y;
    int kk = blockIdx.y * 32 + threadIdx.x;
    dhi[nn * 1024 + kk] = hi;
    dlo[nn * 1024 + kk] = lo;
}

// --------------------------------------------------- stage1 (SIMT fp32 GEMM)
#define BM 128
#define BN 128
#define BK 16
#define TM 8
#define TN 8
#define NTHREADS 256

__global__ __launch_bounds__(NTHREADS)
void stage1_kernel(const float* __restrict__ x,
                   const float* __restrict__ t1w, const float* __restrict__ t1b,
                   const float* __restrict__ i1w, const float* __restrict__ i1b)
{
    __shared__ float As[BK][BM];
    __shared__ float Bs[BK][BN];

    const int K = 400;
    const int mTile = blockIdx.x;
    const int seg   = blockIdx.y >> 3;
    const int n0    = (blockIdx.y & 7) * BN;
    const float* Bmat = (seg == 0) ? t1w : i1w;
    const int kOff = (seg == 2) ? 400 : 0;

    const int tid = threadIdx.x;
    const int tx = tid & 15;
    const int ty = tid >> 4;

    float acc[TM][TN];
    #pragma unroll
    for (int i = 0; i < TM; ++i)
        #pragma unroll
        for (int j = 0; j < TN; ++j) acc[i][j] = 0.f;

    const float* Abase = x + (long)mTile * BM * K;

    for (int k0 = 0; k0 < K; k0 += BK) {
        #pragma unroll
        for (int it = 0; it < 2; ++it) {
            int idx = tid + it * NTHREADS;
            int row = idx >> 2, col4 = (idx & 3) * 4;
            float4 v = *(const float4*)(Abase + row * K + k0 + col4);
            As[col4 + 0][row] = v.x; As[col4 + 1][row] = v.y;
            As[col4 + 2][row] = v.z; As[col4 + 3][row] = v.w;
        }
        #pragma unroll
        for (int it = 0; it < 2; ++it) {
            int idx = tid + it * NTHREADS;
            int row = idx >> 5, col4 = (idx & 31) * 4;
            *(float4*)&Bs[row][col4] =
                *(const float4*)(Bmat + (long)(kOff + k0 + row) * 1024 + n0 + col4);
        }
        __syncthreads();
        #pragma unroll
        for (int k = 0; k < BK; ++k) {
            float a[TM], b[TN];
            #pragma unroll
            for (int i = 0; i < TM; ++i) a[i] = As[k][ty * TM + i];
            #pragma unroll
            for (int j = 0; j < TN; ++j) b[j] = Bs[k][tx * TN + j];
            #pragma unroll
            for (int i = 0; i < TM; ++i)
                #pragma unroll
                for (int j = 0; j < TN; ++j) acc[i][j] += a[i] * b[j];
        }
        __syncthreads();
    }

    const int mBase = mTile * BM + ty * TM;
    if (seg == 0) {
        #pragma unroll
        for (int i = 0; i < TM; ++i)
            #pragma unroll
            for (int j = 0; j < TN; j += 2) {
                int n = n0 + tx * TN + j;
                float v0 = fmaxf(acc[i][j]     + t1b[n],     0.f);
                float v1 = fmaxf(acc[i][j + 1] + t1b[n + 1], 0.f);
                __half H0 = __float2half_rn(v0), H1 = __float2half_rn(v1);
                __half L0 = __float2half_rn(v0 - __half2float(H0));
                __half L1 = __float2half_rn(v1 - __half2float(H1));
                size_t o = (size_t)(mBase + i) * 1024 + n;
                *(uint32_t*)&g_T1h[o] = packh2(H0, H1);
                *(uint32_t*)&g_T1l[o] = packh2(L0, L1);
            }
    } else if (seg == 1) {
        #pragma unroll
        for (int i = 0; i < TM; ++i)
            #pragma unroll
            for (int j = 0; j < TN; ++j) {
                int n = n0 + tx * TN + j;
                g_A1[(mBase + i) * 1024 + n] = acc[i][j] + i1b[n];
            }
    } else {
        #pragma unroll
        for (int i = 0; i < TM; ++i)
            #pragma unroll
            for (int j = 0; j < TN; ++j) {
                int n = n0 + tx * TN + j;
                g_B1[(mBase + i) * 1024 + n] = acc[i][j];
            }
    }
}

// ------------------------- pair expand: materialize relu(A1[b,i]+B1[b,j]) ---
__global__ __launch_bounds__(256)
void pair_expand_kernel()
{
    const int bi = blockIdx.x;          // b*32 + i
    const int b  = bi >> 5;
    const int i  = bi & 31;
    const int t  = threadIdx.x;         // k granule: 4 floats

    float4 av = *(const float4*)&g_A1[(size_t)bi * 1024 + t * 4];
    const float* Bb = g_B1 + (size_t)(b << 5) * 1024;
    const size_t mbase = ((size_t)b << 10) + ((size_t)i << 5);

    #pragma unroll 4
    for (int j = 0; j < 32; ++j) {
        float4 bv = *(const float4*)&Bb[(size_t)j * 1024 + t * 4];
        float h0 = fmaxf(av.x + bv.x, 0.f);
        float h1 = fmaxf(av.y + bv.y, 0.f);
        float h2 = fmaxf(av.z + bv.z, 0.f);
        float h3 = fmaxf(av.w + bv.w, 0.f);
        __half H0 = __float2half_rn(h0), H1 = __float2half_rn(h1);
        __half H2 = __float2half_rn(h2), H3 = __float2half_rn(h3);
        uint2 vh = make_uint2(packh2(H0, H1), packh2(H2, H3));
        uint2 vl = make_uint2(
            packh2(__float2half_rn(h0 - __half2float(H0)),
                   __float2half_rn(h1 - __half2float(H1))),
            packh2(__float2half_rn(h2 - __half2float(H2)),
                   __float2half_rn(h3 - __half2float(H3))));
        size_t m = mbase + j;
        *(uint2*)&g_PAh[m * 1024 + t * 4] = vh;
        *(uint2*)&g_PAl[m * 1024 + t * 4] = vl;
    }
}

// --------------------------------------------- unified tensor stage (HMMA)
// 128 threads (4 warps), CTA tile 128m x 128n, warp tile 64x64 (2m x 2n).
// 2 CTAs/SM co-resident. 3-stage cp.async, K chunks of 32.
// blockIdx.x < 1024: interaction (g_PAh/l -> g_eint); else traj -> g_erow.

static constexpr uint32_t TB_AHI = 0;
static constexpr uint32_t TB_ALO = 8 * 1024;
static constexpr uint32_t TB_BHI = 16 * 1024;
static constexpr uint32_t TB_BLO = 24 * 1024;
static constexpr uint32_t TB_STAGE = 32 * 1024;
static constexpr int NSTAGE = 3;
static constexpr uint32_t TS_SMEM = NSTAGE * TB_STAGE + 1024 + 1024;
static constexpr int NCH = 32;   // 1024 / 32

__global__ __launch_bounds__(128, 2)
void tensor_stage_kernel(const float* __restrict__ t2b, const float* __restrict__ t3w,
                         const float* __restrict__ i2b, const float* __restrict__ i3w)
{
    extern __shared__ char smem_raw[];
    const uint32_t smem_u = smem_u32(smem_raw);
    const uint32_t base_u = (smem_u + 1023) & ~1023u;
    char* p = smem_raw + (base_u - smem_u);

    float* sb2 = (float*)(p + NSTAGE * TB_STAGE);
    float* sw3 = sb2 + 128;

    const int tid  = threadIdx.x;
    const int lane = tid & 31;
    const int wid  = tid >> 5;       // 0..3
    const int wm   = wid & 1;        // warp row (64 m each)
    const int wn   = wid >> 1;       // warp col (64 n each)

    const bool traj = (blockIdx.x >= 1024);
    const int mTile = traj ? (blockIdx.x - 1024) : blockIdx.x;
    const int n0    = blockIdx.y * 128;
    const int m0    = mTile * 128;

    const __half* Ah    = traj ? g_T1h    : g_PAh;
    const __half* Al    = traj ? g_T1l    : g_PAl;
    const __half* WT_hi = traj ? g_T2T_hi : g_I2T_hi;
    const __half* WT_lo = traj ? g_T2T_lo : g_I2T_lo;
    const float*  b2g   = traj ? t2b : i2b;
    const float*  w3g   = traj ? t3w : i3w;
    float* eout         = traj ? g_erow : g_eint;

    sb2[tid] = b2g[n0 + tid];
    sw3[tid] = w3g[n0 + tid];

    // ---- async fill: A 1024 granules + B 1024 granules, 128 threads ----
    auto fillAB = [&](int stage, int k0) {
        const uint32_t sb = base_u + (uint32_t)stage * TB_STAGE;
        #pragma unroll
        for (int t = 0; t < 8; ++t) {           // A: 2 planes x 128 rows x 4
            int idx = tid + t * 128;            // 0..1023
            int plane = idx >> 9;
            int rl = (idx >> 2) & 127;
            int cc = idx & 3;
            const __half* src = (plane ? Al : Ah)
                                + (size_t)(m0 + rl) * 1024 + k0 + cc * 8;
            cp16(sb + (plane ? TB_ALO : TB_AHI) + SWZ64((uint32_t)(rl * 64 + cc * 16)), src);
        }
        #pragma unroll
        for (int t = 0; t < 8; ++t) {           // B: 2 planes x 128 rows x 4
            int idx = tid + t * 128;
            int plane = idx >> 9;
            int rl = (idx >> 2) & 127;
            int cc = idx & 3;
            const __half* src = (plane ? WT_lo : WT_hi)
                                + (size_t)(n0 + rl) * 1024 + k0 + cc * 8;
            cp16(sb + (plane ? TB_BLO : TB_BHI) + SWZ64((uint32_t)(rl * 64 + cc * 16)), src);
        }
    };

    // ---- ldmatrix address bases ----
    uint32_t aoff[4], boff[4];
    #pragma unroll
    for (int mf = 0; mf < 4; ++mf)
        aoff[mf] = (uint32_t)((wm * 64 + mf * 16 + (lane & 15)) * 64 + (lane >> 4) * 16);
    #pragma unroll
    for (int nf2 = 0; nf2 < 4; ++nf2)
        boff[nf2] = (uint32_t)((wn * 64 + nf2 * 16 + (lane & 7) + ((lane & 16) ? 8 : 0)) * 64
                               + ((lane >> 3) & 1) * 16);

    float acc[4][8][4];
    #pragma unroll
    for (int mf = 0; mf < 4; ++mf)
        #pragma unroll
        for (int nf = 0; nf < 8; ++nf)
            #pragma unroll
            for (int q = 0; q < 4; ++q) acc[mf][nf][q] = 0.f;

    auto compute = [&](int stage) {
        const uint32_t sb = base_u + (uint32_t)stage * TB_STAGE;
        #pragma unroll
        for (int kf = 0; kf < 2; ++kf) {
            const uint32_t kadd = kf * 32;
            uint32_t ah[4][4], al[4][4], bf[8][2];
            #pragma unroll
            for (int mf = 0; mf < 4; ++mf) {
                uint32_t sw = SWZ64(aoff[mf] + kadd);
                ldsm4(ah[mf][0], ah[mf][1], ah[mf][2], ah[mf][3], sb + TB_AHI + sw);
                ldsm4(al[mf][0], al[mf][1], al[mf][2], al[mf][3], sb + TB_ALO + sw);
            }
            #pragma unroll
            for (int nf2 = 0; nf2 < 4; ++nf2) {
                uint32_t sw = SWZ64(boff[nf2] + kadd);
                ldsm4(bf[nf2 * 2][0], bf[nf2 * 2][1],
                      bf[nf2 * 2 + 1][0], bf[nf2 * 2 + 1][1], sb + TB_BHI + sw);
            }
            #pragma unroll
            for (int mf = 0; mf < 4; ++mf)
                #pragma unroll
                for (int nf = 0; nf < 8; ++nf)
                    mma16816(acc[mf][nf], ah[mf], bf[nf]);
            #pragma unroll
            for (int mf = 0; mf < 4; ++mf)
                #pragma unroll
                for (int nf = 0; nf < 8; ++nf)
                    mma16816(acc[mf][nf], al[mf], bf[nf]);
            #pragma unroll
            for (int nf2 = 0; nf2 < 4; ++nf2) {
                uint32_t sw = SWZ64(boff[nf2] + kadd);
                ldsm4(bf[nf2 * 2][0], bf[nf2 * 2][1],
                      bf[nf2 * 2 + 1][0], bf[nf2 * 2 + 1][1], sb + TB_BLO + sw);
            }
            #pragma unroll
            for (int mf = 0; mf < 4; ++mf)
                #pragma unroll
                for (int nf = 0; nf < 8; ++nf)
                    mma16816(acc[mf][nf], ah[mf], bf[nf]);
        }
    };

    // ---- 3-stage pipelined main loop ----
    fillAB(0, 0);  CP_COMMIT();
    fillAB(1, 32); CP_COMMIT();

    #pragma unroll 1
    for (int c = 0; c < NCH; ++c) {
        if (c + 2 < NCH) { fillAB((c + 2) % NSTAGE, (c + 2) * 32); CP_COMMIT(); }
        if (c + 1 < NCH) CP_WAIT1(); else CP_WAIT0();
        __syncthreads();
        compute(c % NSTAGE);
        __syncthreads();
    }

    // ---- epilogue: fused layer-3  e_m += sum_n w3[n]*relu(D+b2[n]) ----
    #pragma unroll
    for (int mf = 0; mf < 4; ++mf) {
        #pragma unroll
        for (int h = 0; h < 2; ++h) {
            float s = 0.f;
            #pragma unroll
            for (int nf = 0; nf < 8; ++nf) {
                int nl = wn * 64 + nf * 8 + 2 * (lane & 3);
                float d0 = acc[mf][nf][h * 2 + 0];
                float d1 = acc[mf][nf][h * 2 + 1];
                s += fmaxf(d0 + sb2[nl], 0.f) * sw3[nl]
                   + fmaxf(d1 + sb2[nl + 1], 0.f) * sw3[nl + 1];
            }
            s += __shfl_xor_sync(0xffffffffu, s, 1);
            s += __shfl_xor_sync(0xffffffffu, s, 2);
            if ((lane & 3) == 0) {
                int m = m0 + wm * 64 + mf * 16 + (lane >> 2) + h * 8;
                atomicAdd(&eout[m], s);
            }
        }
    }
}

// ------------------------------------------------------------------ finalize
__global__ void finalize_kernel(const float* __restrict__ edges,
                                const float* __restrict__ t3b,
                                const float* __restrict__ i3b,
                                float* __restrict__ out)
{
    const int b = blockIdx.x;
    const int tid = threadIdx.x;
    const float bias_i = i3b[0];

    float s = 0.f;
    #pragma unroll
    for (int it = 0; it < 4; ++it) {
        int idx = tid + it * 256;
        s += edges[b * 1024 + idx] * (g_eint[b * 1024 + idx] + bias_i);
    }
    if (tid < 32) s += g_erow[b * 32 + tid] + t3b[0];

    __shared__ float red[256];
    red[tid] = s;
    __syncthreads();
    for (int o = 128; o > 0; o >>= 1) {
        if (tid < o) red[tid] += red[tid + o];
        __syncthreads();
    }
    if (tid == 0) out[b] = red[0];
}

// ---------------------------------------------------------------------------
extern "C" void kernel_launch(void* const* d_in, const int* in_sizes, int n_in,
                              void* d_out, int out_size)
{
    const float* x   = (const float*)d_in[0];
    const float* edg = (const float*)d_in[1];
    const float* t1w = (const float*)d_in[2];
    const float* t1b = (const float*)d_in[3];
    const float* t2w = (const float*)d_in[4];
    const float* t2b = (const float*)d_in[5];
    const float* t3w = (const float*)d_in[6];
    const float* t3b = (const float*)d_in[7];
    const float* i1w = (const float*)d_in[8];
    const float* i1b = (const float*)d_in[9];
    const float* i2w = (const float*)d_in[10];
    const float* i2b = (const float*)d_in[11];
    const float* i3w = (const float*)d_in[12];
    const float* i3b = (const float*)d_in[13];
    float* out = (float*)d_out;

    cudaFuncSetAttribute(tensor_stage_kernel,
                         cudaFuncAttributeMaxDynamicSharedMemorySize, TS_SMEM);

    init_kernel<<<512, 256>>>();

    dim3 gp(32, 32, 2);
    prep_transpose<<<gp, dim3(32, 32)>>>(t2w, i2w);

    dim3 g1(32, 24);
    stage1_kernel<<<g1, NTHREADS>>>(x, t1w, t1b, i1w, i1b);

    pair_expand_kernel<<<4096, 256>>>();

    dim3 gt(1056, 8);   // x<1024: interaction; x>=1024: traj; y: 8 n-tiles
    tensor_stage_kernel<<<gt, 128, TS_SMEM>>>(t2b, t3w, i2b, i3w);

    finalize_kernel<<<128, 256>>>(edg, t3b, i3b, out);
}

// round 9
// speedup vs baseline: 3.8253x; 1.3529x over previous
#include <cuda_runtime.h>
#include <cuda_fp16.h>
#include <cstdint>

// ===========================================================================
// Model_86011015070455 — R9: 2-term split ((Ahi+Alo)·Bhi, drop A·Blo),
//   4-stage cp.async pipeline, 2 CTAs/SM. B planes fp16-only.
// ===========================================================================

__device__ __forceinline__ uint32_t smem_u32(const void* p) {
    uint32_t a;
    asm("{ .reg .u64 t; cvta.to.shared.u64 t, %1; cvt.u32.u64 %0, t; }" : "=r"(a) : "l"(p));
    return a;
}
__device__ __forceinline__ void ldsm4(uint32_t& r0, uint32_t& r1, uint32_t& r2, uint32_t& r3,
                                      uint32_t addr) {
    asm volatile("ldmatrix.sync.aligned.m8n8.x4.shared.b16 {%0,%1,%2,%3}, [%4];"
                 : "=r"(r0), "=r"(r1), "=r"(r2), "=r"(r3) : "r"(addr));
}
__device__ __forceinline__ void mma16816(float* d, const uint32_t* a, const uint32_t* b) {
    asm volatile("mma.sync.aligned.m16n8k16.row.col.f32.f16.f16.f32 "
                 "{%0,%1,%2,%3}, {%4,%5,%6,%7}, {%8,%9}, {%0,%1,%2,%3};"
                 : "+f"(d[0]), "+f"(d[1]), "+f"(d[2]), "+f"(d[3])
                 : "r"(a[0]), "r"(a[1]), "r"(a[2]), "r"(a[3]), "r"(b[0]), "r"(b[1]));
}
__device__ __forceinline__ void cp16(uint32_t dst, const void* src) {
    asm volatile("cp.async.cg.shared.global [%0], [%1], 16;"
                 :: "r"(dst), "l"(__cvta_generic_to_global(src)));
}
#define CP_COMMIT() asm volatile("cp.async.commit_group;")
#define CP_WAIT2()  asm volatile("cp.async.wait_group 2;")
#define CP_WAIT0()  asm volatile("cp.async.wait_group 0;")
#define SWZ64(o) ((o) ^ (((o) >> 3) & 0x30))

__device__ __forceinline__ uint32_t packh2(__half a, __half b) {
    __half2 t = __halves2half2(a, b);
    return *(uint32_t*)&t;
}

// ------------------------------------------------------------- device scratch
__device__ float g_A1[4096 * 1024];
__device__ float g_B1[4096 * 1024];
__device__ __half g_T1h[4096 * 1024];
__device__ __half g_T1l[4096 * 1024];
__device__ __half g_PAh[131072u * 1024];
__device__ __half g_PAl[131072u * 1024];
__device__ float g_erow[4096];
__device__ float g_eint[131072];
__device__ __half g_T2T[1024 * 1024];     // traj2_w transposed [n][k], fp16
__device__ __half g_I2T[1024 * 1024];     // int2_w transposed [n][k], fp16

__global__ void init_kernel() {
    int idx = blockIdx.x * blockDim.x + threadIdx.x;
    if (idx < 131072) g_eint[idx] = 0.f;
    if (idx < 4096)   g_erow[idx] = 0.f;
}

// ------------------------------------------- prep: transpose to fp16
__global__ void prep_transpose(const float* __restrict__ t2w, const float* __restrict__ i2w) {
    __shared__ float tile[32][33];
    const float* src = blockIdx.z ? i2w : t2w;
    __half* dhi = blockIdx.z ? g_I2T : g_T2T;
    int k = blockIdx.y * 32 + threadIdx.y;
    int n = blockIdx.x * 32 + threadIdx.x;
    tile[threadIdx.y][threadIdx.x] = src[k * 1024 + n];
    __syncthreads();
    float v = tile[threadIdx.x][threadIdx.y];
    int nn = blockIdx.x * 32 + threadIdx.y;
    int kk = blockIdx.y * 32 + threadIdx.x;
    dhi[nn * 1024 + kk] = __float2half_rn(v);
}

// --------------------------------------------------- stage1 (SIMT fp32 GEMM)
#define BM 128
#define BN 128
#define BK 16
#define TM 8
#define TN 8
#define NTHREADS 256

__global__ __launch_bounds__(NTHREADS)
void stage1_kernel(const float* __restrict__ x,
                   const float* __restrict__ t1w, const float* __restrict__ t1b,
                   const float* __restrict__ i1w, const float* __restrict__ i1b)
{
    __shared__ float As[BK][BM];
    __shared__ float Bs[BK][BN];

    const int K = 400;
    const int mTile = blockIdx.x;
    const int seg   = blockIdx.y >> 3;
    const int n0    = (blockIdx.y & 7) * BN;
    const float* Bmat = (seg == 0) ? t1w : i1w;
    const int kOff = (seg == 2) ? 400 : 0;

    const int tid = threadIdx.x;
    const int tx = tid & 15;
    const int ty = tid >> 4;

    float acc[TM][TN];
    #pragma unroll
    for (int i = 0; i < TM; ++i)
        #pragma unroll
        for (int j = 0; j < TN; ++j) acc[i][j] = 0.f;

    const float* Abase = x + (long)mTile * BM * K;

    for (int k0 = 0; k0 < K; k0 += BK) {
        #pragma unroll
        for (int it = 0; it < 2; ++it) {
            int idx = tid + it * NTHREADS;
            int row = idx >> 2, col4 = (idx & 3) * 4;
            float4 v = *(const float4*)(Abase + row * K + k0 + col4);
            As[col4 + 0][row] = v.x; As[col4 + 1][row] = v.y;
            As[col4 + 2][row] = v.z; As[col4 + 3][row] = v.w;
        }
        #pragma unroll
        for (int it = 0; it < 2; ++it) {
            int idx = tid + it * NTHREADS;
            int row = idx >> 5, col4 = (idx & 31) * 4;
            *(float4*)&Bs[row][col4] =
                *(const float4*)(Bmat + (long)(kOff + k0 + row) * 1024 + n0 + col4);
        }
        __syncthreads();
        #pragma unroll
        for (int k = 0; k < BK; ++k) {
            float a[TM], b[TN];
            #pragma unroll
            for (int i = 0; i < TM; ++i) a[i] = As[k][ty * TM + i];
            #pragma unroll
            for (int j = 0; j < TN; ++j) b[j] = Bs[k][tx * TN + j];
            #pragma unroll
            for (int i = 0; i < TM; ++i)
                #pragma unroll
                for (int j = 0; j < TN; ++j) acc[i][j] += a[i] * b[j];
        }
        __syncthreads();
    }

    const int mBase = mTile * BM + ty * TM;
    if (seg == 0) {
        #pragma unroll
        for (int i = 0; i < TM; ++i)
            #pragma unroll
            for (int j = 0; j < TN; j += 2) {
                int n = n0 + tx * TN + j;
                float v0 = fmaxf(acc[i][j]     + t1b[n],     0.f);
                float v1 = fmaxf(acc[i][j + 1] + t1b[n + 1], 0.f);
                __half H0 = __float2half_rn(v0), H1 = __float2half_rn(v1);
                __half L0 = __float2half_rn(v0 - __half2float(H0));
                __half L1 = __float2half_rn(v1 - __half2float(H1));
                size_t o = (size_t)(mBase + i) * 1024 + n;
                *(uint32_t*)&g_T1h[o] = packh2(H0, H1);
                *(uint32_t*)&g_T1l[o] = packh2(L0, L1);
            }
    } else if (seg == 1) {
        #pragma unroll
        for (int i = 0; i < TM; ++i)
            #pragma unroll
            for (int j = 0; j < TN; ++j) {
                int n = n0 + tx * TN + j;
                g_A1[(mBase + i) * 1024 + n] = acc[i][j] + i1b[n];
            }
    } else {
        #pragma unroll
        for (int i = 0; i < TM; ++i)
            #pragma unroll
            for (int j = 0; j < TN; ++j) {
                int n = n0 + tx * TN + j;
                g_B1[(mBase + i) * 1024 + n] = acc[i][j];
            }
    }
}

// ------------------------- pair expand: materialize relu(A1[b,i]+B1[b,j]) ---
__global__ __launch_bounds__(256)
void pair_expand_kernel()
{
    const int bi = blockIdx.x;          // b*32 + i
    const int b  = bi >> 5;
    const int i  = bi & 31;
    const int t  = threadIdx.x;         // k granule: 4 floats

    float4 av = *(const float4*)&g_A1[(size_t)bi * 1024 + t * 4];
    const float* Bb = g_B1 + (size_t)(b << 5) * 1024;
    const size_t mbase = ((size_t)b << 10) + ((size_t)i << 5);

    #pragma unroll 4
    for (int j = 0; j < 32; ++j) {
        float4 bv = *(const float4*)&Bb[(size_t)j * 1024 + t * 4];
        float h0 = fmaxf(av.x + bv.x, 0.f);
        float h1 = fmaxf(av.y + bv.y, 0.f);
        float h2 = fmaxf(av.z + bv.z, 0.f);
        float h3 = fmaxf(av.w + bv.w, 0.f);
        __half H0 = __float2half_rn(h0), H1 = __float2half_rn(h1);
        __half H2 = __float2half_rn(h2), H3 = __float2half_rn(h3);
        uint2 vh = make_uint2(packh2(H0, H1), packh2(H2, H3));
        uint2 vl = make_uint2(
            packh2(__float2half_rn(h0 - __half2float(H0)),
                   __float2half_rn(h1 - __half2float(H1))),
            packh2(__float2half_rn(h2 - __half2float(H2)),
                   __float2half_rn(h3 - __half2float(H3))));
        size_t m = mbase + j;
        *(uint2*)&g_PAh[m * 1024 + t * 4] = vh;
        *(uint2*)&g_PAl[m * 1024 + t * 4] = vl;
    }
}

// --------------------------------------------- unified tensor stage (HMMA)
// 128 threads (4 warps), CTA tile 128m x 128n, warp tile 64x64 (2m x 2n).
// 2 CTAs/SM. 4-stage cp.async, K chunks of 32. 2-term split: (Ahi+Alo)*Bhi.
// blockIdx.x < 1024: interaction (g_PAh/l -> g_eint); else traj -> g_erow.

static constexpr uint32_t TB_AHI = 0;
static constexpr uint32_t TB_ALO = 8 * 1024;
static constexpr uint32_t TB_BHI = 16 * 1024;
static constexpr uint32_t TB_STAGE = 24 * 1024;
static constexpr int NSTAGE = 4;
static constexpr uint32_t TS_SMEM = NSTAGE * TB_STAGE + 1024 + 1024;
static constexpr int NCH = 32;   // 1024 / 32

__global__ __launch_bounds__(128, 2)
void tensor_stage_kernel(const float* __restrict__ t2b, const float* __restrict__ t3w,
                         const float* __restrict__ i2b, const float* __restrict__ i3w)
{
    extern __shared__ char smem_raw[];
    const uint32_t smem_u = smem_u32(smem_raw);
    const uint32_t base_u = (smem_u + 1023) & ~1023u;
    char* p = smem_raw + (base_u - smem_u);

    float* sb2 = (float*)(p + NSTAGE * TB_STAGE);
    float* sw3 = sb2 + 128;

    const int tid  = threadIdx.x;
    const int lane = tid & 31;
    const int wid  = tid >> 5;       // 0..3
    const int wm   = wid & 1;        // warp row (64 m each)
    const int wn   = wid >> 1;       // warp col (64 n each)

    const bool traj = (blockIdx.x >= 1024);
    const int mTile = traj ? (blockIdx.x - 1024) : blockIdx.x;
    const int n0    = blockIdx.y * 128;
    const int m0    = mTile * 128;

    const __half* Ah  = traj ? g_T1h : g_PAh;
    const __half* Al  = traj ? g_T1l : g_PAl;
    const __half* WT  = traj ? g_T2T : g_I2T;
    const float*  b2g = traj ? t2b : i2b;
    const float*  w3g = traj ? t3w : i3w;
    float* eout       = traj ? g_erow : g_eint;

    sb2[tid] = b2g[n0 + tid];
    sw3[tid] = w3g[n0 + tid];

    // ---- async fill: A 1024 granules + B 512 granules, 128 threads ----
    auto fillAB = [&](int stage, int k0) {
        const uint32_t sb = base_u + (uint32_t)stage * TB_STAGE;
        #pragma unroll
        for (int t = 0; t < 8; ++t) {           // A: 2 planes x 128 rows x 4
            int idx = tid + t * 128;            // 0..1023
            int plane = idx >> 9;
            int rl = (idx >> 2) & 127;
            int cc = idx & 3;
            const __half* src = (plane ? Al : Ah)
                                + (size_t)(m0 + rl) * 1024 + k0 + cc * 8;
            cp16(sb + (plane ? TB_ALO : TB_AHI) + SWZ64((uint32_t)(rl * 64 + cc * 16)), src);
        }
        #pragma unroll
        for (int t = 0; t < 4; ++t) {           // B: 1 plane x 128 rows x 4
            int idx = tid + t * 128;            // 0..511
            int rl = idx >> 2;
            int cc = idx & 3;
            const __half* src = WT + (size_t)(n0 + rl) * 1024 + k0 + cc * 8;
            cp16(sb + TB_BHI + SWZ64((uint32_t)(rl * 64 + cc * 16)), src);
        }
    };

    // ---- ldmatrix address bases ----
    uint32_t aoff[4], boff[4];
    #pragma unroll
    for (int mf = 0; mf < 4; ++mf)
        aoff[mf] = (uint32_t)((wm * 64 + mf * 16 + (lane & 15)) * 64 + (lane >> 4) * 16);
    #pragma unroll
    for (int nf2 = 0; nf2 < 4; ++nf2)
        boff[nf2] = (uint32_t)((wn * 64 + nf2 * 16 + (lane & 7) + ((lane & 16) ? 8 : 0)) * 64
                               + ((lane >> 3) & 1) * 16);

    float acc[4][8][4];
    #pragma unroll
    for (int mf = 0; mf < 4; ++mf)
        #pragma unroll
        for (int nf = 0; nf < 8; ++nf)
            #pragma unroll
            for (int q = 0; q < 4; ++q) acc[mf][nf][q] = 0.f;

    auto compute = [&](int stage) {
        const uint32_t sb = base_u + (uint32_t)stage * TB_STAGE;
        #pragma unroll
        for (int kf = 0; kf < 2; ++kf) {
            const uint32_t kadd = kf * 32;
            uint32_t ah[4][4], al[4][4], bf[8][2];
            #pragma unroll
            for (int mf = 0; mf < 4; ++mf) {
                uint32_t sw = SWZ64(aoff[mf] + kadd);
                ldsm4(ah[mf][0], ah[mf][1], ah[mf][2], ah[mf][3], sb + TB_AHI + sw);
                ldsm4(al[mf][0], al[mf][1], al[mf][2], al[mf][3], sb + TB_ALO + sw);
            }
            #pragma unroll
            for (int nf2 = 0; nf2 < 4; ++nf2) {
                uint32_t sw = SWZ64(boff[nf2] + kadd);
                ldsm4(bf[nf2 * 2][0], bf[nf2 * 2][1],
                      bf[nf2 * 2 + 1][0], bf[nf2 * 2 + 1][1], sb + TB_BHI + sw);
            }
            #pragma unroll
            for (int mf = 0; mf < 4; ++mf)
                #pragma unroll
                for (int nf = 0; nf < 8; ++nf)
                    mma16816(acc[mf][nf], ah[mf], bf[nf]);
            #pragma unroll
            for (int mf = 0; mf < 4; ++mf)
                #pragma unroll
                for (int nf = 0; nf < 8; ++nf)
                    mma16816(acc[mf][nf], al[mf], bf[nf]);
        }
    };

    // ---- 4-stage pipelined main loop ----
    fillAB(0, 0);  CP_COMMIT();
    fillAB(1, 32); CP_COMMIT();
    fillAB(2, 64); CP_COMMIT();

    #pragma unroll 1
    for (int c = 0; c < NCH; ++c) {
        if (c + 3 < NCH) {
            fillAB((c + 3) & 3, (c + 3) * 32); CP_COMMIT();
            CP_WAIT2();
        } else {
            CP_WAIT0();
        }
        __syncthreads();
        compute(c & 3);
        __syncthreads();
    }

    // ---- epilogue: fused layer-3  e_m += sum_n w3[n]*relu(D+b2[n]) ----
    #pragma unroll
    for (int mf = 0; mf < 4; ++mf) {
        #pragma unroll
        for (int h = 0; h < 2; ++h) {
            float s = 0.f;
            #pragma unroll
            for (int nf = 0; nf < 8; ++nf) {
                int nl = wn * 64 + nf * 8 + 2 * (lane & 3);
                float d0 = acc[mf][nf][h * 2 + 0];
                float d1 = acc[mf][nf][h * 2 + 1];
                s += fmaxf(d0 + sb2[nl], 0.f) * sw3[nl]
                   + fmaxf(d1 + sb2[nl + 1], 0.f) * sw3[nl + 1];
            }
            s += __shfl_xor_sync(0xffffffffu, s, 1);
            s += __shfl_xor_sync(0xffffffffu, s, 2);
            if ((lane & 3) == 0) {
                int m = m0 + wm * 64 + mf * 16 + (lane >> 2) + h * 8;
                atomicAdd(&eout[m], s);
            }
        }
    }
}

// ------------------------------------------------------------------ finalize
__global__ void finalize_kernel(const float* __restrict__ edges,
                                const float* __restrict__ t3b,
                                const float* __restrict__ i3b,
                                float* __restrict__ out)
{
    const int b = blockIdx.x;
    const int tid = threadIdx.x;
    const float bias_i = i3b[0];

    float s = 0.f;
    #pragma unroll
    for (int it = 0; it < 4; ++it) {
        int idx = tid + it * 256;
        s += edges[b * 1024 + idx] * (g_eint[b * 1024 + idx] + bias_i);
    }
    if (tid < 32) s += g_erow[b * 32 + tid] + t3b[0];

    __shared__ float red[256];
    red[tid] = s;
    __syncthreads();
    for (int o = 128; o > 0; o >>= 1) {
        if (tid < o) red[tid] += red[tid + o];
        __syncthreads();
    }
    if (tid == 0) out[b] = red[0];
}

// ---------------------------------------------------------------------------
extern "C" void kernel_launch(void* const* d_in, const int* in_sizes, int n_in,
                              void* d_out, int out_size)
{
    const float* x   = (const float*)d_in[0];
    const float* edg = (const float*)d_in[1];
    const float* t1w = (const float*)d_in[2];
    const float* t1b = (const float*)d_in[3];
    const float* t2w = (const float*)d_in[4];
    const float* t2b = (const float*)d_in[5];
    const float* t3w = (const float*)d_in[6];
    const float* t3b = (const float*)d_in[7];
    const float* i1w = (const float*)d_in[8];
    const float* i1b = (const float*)d_in[9];
    const float* i2w = (const float*)d_in[10];
    const float* i2b = (const float*)d_in[11];
    const float* i3w = (const float*)d_in[12];
    const float* i3b = (const float*)d_in[13];
    float* out = (float*)d_out;

    cudaFuncSetAttribute(tensor_stage_kernel,
                         cudaFuncAttributeMaxDynamicSharedMemorySize, TS_SMEM);

    init_kernel<<<512, 256>>>();

    dim3 gp(32, 32, 2);
    prep_transpose<<<gp, dim3(32, 32)>>>(t2w, i2w);

    dim3 g1(32, 24);
    stage1_kernel<<<g1, NTHREADS>>>(x, t1w, t1b, i1w, i1b);

    pair_expand_kernel<<<4096, 256>>>();

    dim3 gt(1056, 8);   // x<1024: interaction; x>=1024: traj; y: 8 n-tiles
    tensor_stage_kernel<<<gt, 128, TS_SMEM>>>(t2b, t3w, i2b, i3w);

    finalize_kernel<<<128, 256>>>(edg, t3b, i3b, out);
}

// round 10
// speedup vs baseline: 6.0251x; 1.5751x over previous
#include <cuda_runtime.h>
#include <cuda_fp16.h>
#include <cstdint>

// ===========================================================================
// Model_86011015070455 — R10: 1-term fp16 GEMM (A fp16, B fp16, fp32 accum).
//   Measured error calibration: each dropped residual term adds ~1.6e-4
//   rel_err (independent) -> expected ~2.3e-4 total, threshold 1e-3.
//   4-stage cp.async pipeline, 2 CTAs/SM, stage = 16KB.
// ===========================================================================

__device__ __forceinline__ uint32_t smem_u32(const void* p) {
    uint32_t a;
    asm("{ .reg .u64 t; cvta.to.shared.u64 t, %1; cvt.u32.u64 %0, t; }" : "=r"(a) : "l"(p));
    return a;
}
__device__ __forceinline__ void ldsm4(uint32_t& r0, uint32_t& r1, uint32_t& r2, uint32_t& r3,
                                      uint32_t addr) {
    asm volatile("ldmatrix.sync.aligned.m8n8.x4.shared.b16 {%0,%1,%2,%3}, [%4];"
                 : "=r"(r0), "=r"(r1), "=r"(r2), "=r"(r3) : "r"(addr));
}
__device__ __forceinline__ void mma16816(float* d, const uint32_t* a, const uint32_t* b) {
    asm volatile("mma.sync.aligned.m16n8k16.row.col.f32.f16.f16.f32 "
                 "{%0,%1,%2,%3}, {%4,%5,%6,%7}, {%8,%9}, {%0,%1,%2,%3};"
                 : "+f"(d[0]), "+f"(d[1]), "+f"(d[2]), "+f"(d[3])
                 : "r"(a[0]), "r"(a[1]), "r"(a[2]), "r"(a[3]), "r"(b[0]), "r"(b[1]));
}
__device__ __forceinline__ void cp16(uint32_t dst, const void* src) {
    asm volatile("cp.async.cg.shared.global [%0], [%1], 16;"
                 :: "r"(dst), "l"(__cvta_generic_to_global(src)));
}
#define CP_COMMIT() asm volatile("cp.async.commit_group;")
#define CP_WAIT2()  asm volatile("cp.async.wait_group 2;")
#define CP_WAIT0()  asm volatile("cp.async.wait_group 0;")
#define SWZ64(o) ((o) ^ (((o) >> 3) & 0x30))

__device__ __forceinline__ uint32_t packh2(__half a, __half b) {
    __half2 t = __halves2half2(a, b);
    return *(uint32_t*)&t;
}

// ------------------------------------------------------------- device scratch
__device__ float g_A1[4096 * 1024];
__device__ float g_B1[4096 * 1024];
__device__ __half g_T1h[4096 * 1024];        // relu(x@t1w+b), fp16
__device__ __half g_PAh[131072u * 1024];     // relu(A1[b,i]+B1[b,j]), fp16
__device__ float g_erow[4096];
__device__ float g_eint[131072];
__device__ __half g_T2T[1024 * 1024];        // traj2_w transposed [n][k], fp16
__device__ __half g_I2T[1024 * 1024];        // int2_w transposed [n][k], fp16

__global__ void init_kernel() {
    int idx = blockIdx.x * blockDim.x + threadIdx.x;
    if (idx < 131072) g_eint[idx] = 0.f;
    if (idx < 4096)   g_erow[idx] = 0.f;
}

// ------------------------------------------- prep: transpose to fp16
__global__ void prep_transpose(const float* __restrict__ t2w, const float* __restrict__ i2w) {
    __shared__ float tile[32][33];
    const float* src = blockIdx.z ? i2w : t2w;
    __half* dst = blockIdx.z ? g_I2T : g_T2T;
    int k = blockIdx.y * 32 + threadIdx.y;
    int n = blockIdx.x * 32 + threadIdx.x;
    tile[threadIdx.y][threadIdx.x] = src[k * 1024 + n];
    __syncthreads();
    float v = tile[threadIdx.x][threadIdx.y];
    int nn = blockIdx.x * 32 + threadIdx.y;
    int kk = blockIdx.y * 32 + threadIdx.x;
    dst[nn * 1024 + kk] = __float2half_rn(v);
}

// --------------------------------------------------- stage1 (SIMT fp32 GEMM)
#define BM 128
#define BN 128
#define BK 16
#define TM 8
#define TN 8
#define NTHREADS 256

__global__ __launch_bounds__(NTHREADS)
void stage1_kernel(const float* __restrict__ x,
                   const float* __restrict__ t1w, const float* __restrict__ t1b,
                   const float* __restrict__ i1w, const float* __restrict__ i1b)
{
    __shared__ float As[BK][BM];
    __shared__ float Bs[BK][BN];

    const int K = 400;
    const int mTile = blockIdx.x;
    const int seg   = blockIdx.y >> 3;
    const int n0    = (blockIdx.y & 7) * BN;
    const float* Bmat = (seg == 0) ? t1w : i1w;
    const int kOff = (seg == 2) ? 400 : 0;

    const int tid = threadIdx.x;
    const int tx = tid & 15;
    const int ty = tid >> 4;

    float acc[TM][TN];
    #pragma unroll
    for (int i = 0; i < TM; ++i)
        #pragma unroll
        for (int j = 0; j < TN; ++j) acc[i][j] = 0.f;

    const float* Abase = x + (long)mTile * BM * K;

    for (int k0 = 0; k0 < K; k0 += BK) {
        #pragma unroll
        for (int it = 0; it < 2; ++it) {
            int idx = tid + it * NTHREADS;
            int row = idx >> 2, col4 = (idx & 3) * 4;
            float4 v = *(const float4*)(Abase + row * K + k0 + col4);
            As[col4 + 0][row] = v.x; As[col4 + 1][row] = v.y;
            As[col4 + 2][row] = v.z; As[col4 + 3][row] = v.w;
        }
        #pragma unroll
        for (int it = 0; it < 2; ++it) {
            int idx = tid + it * NTHREADS;
            int row = idx >> 5, col4 = (idx & 31) * 4;
            *(float4*)&Bs[row][col4] =
                *(const float4*)(Bmat + (long)(kOff + k0 + row) * 1024 + n0 + col4);
        }
        __syncthreads();
        #pragma unroll
        for (int k = 0; k < BK; ++k) {
            float a[TM], b[TN];
            #pragma unroll
            for (int i = 0; i < TM; ++i) a[i] = As[k][ty * TM + i];
            #pragma unroll
            for (int j = 0; j < TN; ++j) b[j] = Bs[k][tx * TN + j];
            #pragma unroll
            for (int i = 0; i < TM; ++i)
                #pragma unroll
                for (int j = 0; j < TN; ++j) acc[i][j] += a[i] * b[j];
        }
        __syncthreads();
    }

    const int mBase = mTile * BM + ty * TM;
    if (seg == 0) {
        #pragma unroll
        for (int i = 0; i < TM; ++i)
            #pragma unroll
            for (int j = 0; j < TN; j += 2) {
                int n = n0 + tx * TN + j;
                float v0 = fmaxf(acc[i][j]     + t1b[n],     0.f);
                float v1 = fmaxf(acc[i][j + 1] + t1b[n + 1], 0.f);
                size_t o = (size_t)(mBase + i) * 1024 + n;
                *(uint32_t*)&g_T1h[o] = packh2(__float2half_rn(v0), __float2half_rn(v1));
            }
    } else if (seg == 1) {
        #pragma unroll
        for (int i = 0; i < TM; ++i)
            #pragma unroll
            for (int j = 0; j < TN; ++j) {
                int n = n0 + tx * TN + j;
                g_A1[(mBase + i) * 1024 + n] = acc[i][j] + i1b[n];
            }
    } else {
        #pragma unroll
        for (int i = 0; i < TM; ++i)
            #pragma unroll
            for (int j = 0; j < TN; ++j) {
                int n = n0 + tx * TN + j;
                g_B1[(mBase + i) * 1024 + n] = acc[i][j];
            }
    }
}

// ------------------------- pair expand: materialize relu(A1[b,i]+B1[b,j]) ---
__global__ __launch_bounds__(256)
void pair_expand_kernel()
{
    const int bi = blockIdx.x;          // b*32 + i
    const int b  = bi >> 5;
    const int i  = bi & 31;
    const int t  = threadIdx.x;         // k granule: 4 floats

    float4 av = *(const float4*)&g_A1[(size_t)bi * 1024 + t * 4];
    const float* Bb = g_B1 + (size_t)(b << 5) * 1024;
    const size_t mbase = ((size_t)b << 10) + ((size_t)i << 5);

    #pragma unroll 4
    for (int j = 0; j < 32; ++j) {
        float4 bv = *(const float4*)&Bb[(size_t)j * 1024 + t * 4];
        float h0 = fmaxf(av.x + bv.x, 0.f);
        float h1 = fmaxf(av.y + bv.y, 0.f);
        float h2 = fmaxf(av.z + bv.z, 0.f);
        float h3 = fmaxf(av.w + bv.w, 0.f);
        uint2 vh = make_uint2(packh2(__float2half_rn(h0), __float2half_rn(h1)),
                              packh2(__float2half_rn(h2), __float2half_rn(h3)));
        *(uint2*)&g_PAh[(mbase + j) * 1024 + t * 4] = vh;
    }
}

// --------------------------------------------- unified tensor stage (HMMA)
// 128 threads (4 warps), CTA tile 128m x 128n, warp tile 64x64 (2m x 2n).
// 2 CTAs/SM. 4-stage cp.async, K chunks of 32. Plain fp16 A x fp16 B.
// blockIdx.x < 1024: interaction (g_PAh -> g_eint); else traj -> g_erow.

static constexpr uint32_t TB_A = 0;
static constexpr uint32_t TB_B = 8 * 1024;
static constexpr uint32_t TB_STAGE = 16 * 1024;
static constexpr int NSTAGE = 4;
static constexpr uint32_t TS_SMEM = NSTAGE * TB_STAGE + 1024 + 1024;
static constexpr int NCH = 32;   // 1024 / 32

__global__ __launch_bounds__(128, 2)
void tensor_stage_kernel(const float* __restrict__ t2b, const float* __restrict__ t3w,
                         const float* __restrict__ i2b, const float* __restrict__ i3w)
{
    extern __shared__ char smem_raw[];
    const uint32_t smem_u = smem_u32(smem_raw);
    const uint32_t base_u = (smem_u + 1023) & ~1023u;
    char* p = smem_raw + (base_u - smem_u);

    float* sb2 = (float*)(p + NSTAGE * TB_STAGE);
    float* sw3 = sb2 + 128;

    const int tid  = threadIdx.x;
    const int lane = tid & 31;
    const int wid  = tid >> 5;       // 0..3
    const int wm   = wid & 1;        // warp row (64 m each)
    const int wn   = wid >> 1;       // warp col (64 n each)

    const bool traj = (blockIdx.x >= 1024);
    const int mTile = traj ? (blockIdx.x - 1024) : blockIdx.x;
    const int n0    = blockIdx.y * 128;
    const int m0    = mTile * 128;

    const __half* Ah  = traj ? g_T1h : g_PAh;
    const __half* WT  = traj ? g_T2T : g_I2T;
    const float*  b2g = traj ? t2b : i2b;
    const float*  w3g = traj ? t3w : i3w;
    float* eout       = traj ? g_erow : g_eint;

    sb2[tid] = b2g[n0 + tid];
    sw3[tid] = w3g[n0 + tid];

    // ---- async fill: A 512 granules + B 512 granules, 128 threads ----
    auto fillAB = [&](int stage, int k0) {
        const uint32_t sb = base_u + (uint32_t)stage * TB_STAGE;
        #pragma unroll
        for (int t = 0; t < 4; ++t) {           // A: 128 rows x 4 granules
            int idx = tid + t * 128;            // 0..511
            int rl = idx >> 2;
            int cc = idx & 3;
            const __half* src = Ah + (size_t)(m0 + rl) * 1024 + k0 + cc * 8;
            cp16(sb + TB_A + SWZ64((uint32_t)(rl * 64 + cc * 16)), src);
        }
        #pragma unroll
        for (int t = 0; t < 4; ++t) {           // B: 128 rows x 4 granules
            int idx = tid + t * 128;
            int rl = idx >> 2;
            int cc = idx & 3;
            const __half* src = WT + (size_t)(n0 + rl) * 1024 + k0 + cc * 8;
            cp16(sb + TB_B + SWZ64((uint32_t)(rl * 64 + cc * 16)), src);
        }
    };

    // ---- ldmatrix address bases ----
    uint32_t aoff[4], boff[4];
    #pragma unroll
    for (int mf = 0; mf < 4; ++mf)
        aoff[mf] = (uint32_t)((wm * 64 + mf * 16 + (lane & 15)) * 64 + (lane >> 4) * 16);
    #pragma unroll
    for (int nf2 = 0; nf2 < 4; ++nf2)
        boff[nf2] = (uint32_t)((wn * 64 + nf2 * 16 + (lane & 7) + ((lane & 16) ? 8 : 0)) * 64
                               + ((lane >> 3) & 1) * 16);

    float acc[4][8][4];
    #pragma unroll
    for (int mf = 0; mf < 4; ++mf)
        #pragma unroll
        for (int nf = 0; nf < 8; ++nf)
            #pragma unroll
            for (int q = 0; q < 4; ++q) acc[mf][nf][q] = 0.f;

    auto compute = [&](int stage) {
        const uint32_t sb = base_u + (uint32_t)stage * TB_STAGE;
        #pragma unroll
        for (int kf = 0; kf < 2; ++kf) {
            const uint32_t kadd = kf * 32;
            uint32_t ah[4][4], bf[8][2];
            #pragma unroll
            for (int mf = 0; mf < 4; ++mf) {
                uint32_t sw = SWZ64(aoff[mf] + kadd);
                ldsm4(ah[mf][0], ah[mf][1], ah[mf][2], ah[mf][3], sb + TB_A + sw);
            }
            #pragma unroll
            for (int nf2 = 0; nf2 < 4; ++nf2) {
                uint32_t sw = SWZ64(boff[nf2] + kadd);
                ldsm4(bf[nf2 * 2][0], bf[nf2 * 2][1],
                      bf[nf2 * 2 + 1][0], bf[nf2 * 2 + 1][1], sb + TB_B + sw);
            }
            #pragma unroll
            for (int mf = 0; mf < 4; ++mf)
                #pragma unroll
                for (int nf = 0; nf < 8; ++nf)
                    mma16816(acc[mf][nf], ah[mf], bf[nf]);
        }
    };

    // ---- 4-stage pipelined main loop ----
    fillAB(0, 0);  CP_COMMIT();
    fillAB(1, 32); CP_COMMIT();
    fillAB(2, 64); CP_COMMIT();

    #pragma unroll 1
    for (int c = 0; c < NCH; ++c) {
        if (c + 3 < NCH) {
            fillAB((c + 3) & 3, (c + 3) * 32); CP_COMMIT();
            CP_WAIT2();
        } else {
            CP_WAIT0();
        }
        __syncthreads();
        compute(c & 3);
        __syncthreads();
    }

    // ---- epilogue: fused layer-3  e_m += sum_n w3[n]*relu(D+b2[n]) ----
    #pragma unroll
    for (int mf = 0; mf < 4; ++mf) {
        #pragma unroll
        for (int h = 0; h < 2; ++h) {
            float s = 0.f;
            #pragma unroll
            for (int nf = 0; nf < 8; ++nf) {
                int nl = wn * 64 + nf * 8 + 2 * (lane & 3);
                float d0 = acc[mf][nf][h * 2 + 0];
                float d1 = acc[mf][nf][h * 2 + 1];
                s += fmaxf(d0 + sb2[nl], 0.f) * sw3[nl]
                   + fmaxf(d1 + sb2[nl + 1], 0.f) * sw3[nl + 1];
            }
            s += __shfl_xor_sync(0xffffffffu, s, 1);
            s += __shfl_xor_sync(0xffffffffu, s, 2);
            if ((lane & 3) == 0) {
                int m = m0 + wm * 64 + mf * 16 + (lane >> 2) + h * 8;
                atomicAdd(&eout[m], s);
            }
        }
    }
}

// ------------------------------------------------------------------ finalize
__global__ void finalize_kernel(const float* __restrict__ edges,
                                const float* __restrict__ t3b,
                                const float* __restrict__ i3b,
                                float* __restrict__ out)
{
    const int b = blockIdx.x;
    const int tid = threadIdx.x;
    const float bias_i = i3b[0];

    float s = 0.f;
    #pragma unroll
    for (int it = 0; it < 4; ++it) {
        int idx = tid + it * 256;
        s += edges[b * 1024 + idx] * (g_eint[b * 1024 + idx] + bias_i);
    }
    if (tid < 32) s += g_erow[b * 32 + tid] + t3b[0];

    __shared__ float red[256];
    red[tid] = s;
    __syncthreads();
    for (int o = 128; o > 0; o >>= 1) {
        if (tid < o) red[tid] += red[tid + o];
        __syncthreads();
    }
    if (tid == 0) out[b] = red[0];
}

// ---------------------------------------------------------------------------
extern "C" void kernel_launch(void* const* d_in, const int* in_sizes, int n_in,
                              void* d_out, int out_size)
{
    const float* x   = (const float*)d_in[0];
    const float* edg = (const float*)d_in[1];
    const float* t1w = (const float*)d_in[2];
    const float* t1b = (const float*)d_in[3];
    const float* t2w = (const float*)d_in[4];
    const float* t2b = (const float*)d_in[5];
    const float* t3w = (const float*)d_in[6];
    const float* t3b = (const float*)d_in[7];
    const float* i1w = (const float*)d_in[8];
    const float* i1b = (const float*)d_in[9];
    const float* i2w = (const float*)d_in[10];
    const float* i2b = (const float*)d_in[11];
    const float* i3w = (const float*)d_in[12];
    const float* i3b = (const float*)d_in[13];
    float* out = (float*)d_out;

    cudaFuncSetAttribute(tensor_stage_kernel,
                         cudaFuncAttributeMaxDynamicSharedMemorySize, TS_SMEM);

    init_kernel<<<512, 256>>>();

    dim3 gp(32, 32, 2);
    prep_transpose<<<gp, dim3(32, 32)>>>(t2w, i2w);

    dim3 g1(32, 24);
    stage1_kernel<<<g1, NTHREADS>>>(x, t1w, t1b, i1w, i1b);

    pair_expand_kernel<<<4096, 256>>>();

    dim3 gt(1056, 8);   // x<1024: interaction; x>=1024: traj; y: 8 n-tiles
    tensor_stage_kernel<<<gt, 128, TS_SMEM>>>(t2b, t3w, i2b, i3w);

    finalize_kernel<<<128, 256>>>(edg, t3b, i3b, out);
}

// round 11
// speedup vs baseline: 7.9812x; 1.3247x over previous
#include <cuda_runtime.h>
#include <cuda_fp16.h>
#include <cstdint>

// ===========================================================================
// Model_86011015070455 — R11: stage1 tensorized (fp16 HMMA, K=416 padded),
//   pair_expand 16B stores. Tensor stage (R10) unchanged.
//   Error model (measured): W2-fp16 ~1.6e-4 systematic; W1-fp16 adds ~same
//   independent -> ~2.3e-4 expected, threshold 1e-3.
// ===========================================================================

__device__ __forceinline__ uint32_t smem_u32(const void* p) {
    uint32_t a;
    asm("{ .reg .u64 t; cvta.to.shared.u64 t, %1; cvt.u32.u64 %0, t; }" : "=r"(a) : "l"(p));
    return a;
}
__device__ __forceinline__ void ldsm4(uint32_t& r0, uint32_t& r1, uint32_t& r2, uint32_t& r3,
                                      uint32_t addr) {
    asm volatile("ldmatrix.sync.aligned.m8n8.x4.shared.b16 {%0,%1,%2,%3}, [%4];"
                 : "=r"(r0), "=r"(r1), "=r"(r2), "=r"(r3) : "r"(addr));
}
__device__ __forceinline__ void mma16816(float* d, const uint32_t* a, const uint32_t* b) {
    asm volatile("mma.sync.aligned.m16n8k16.row.col.f32.f16.f16.f32 "
                 "{%0,%1,%2,%3}, {%4,%5,%6,%7}, {%8,%9}, {%0,%1,%2,%3};"
                 : "+f"(d[0]), "+f"(d[1]), "+f"(d[2]), "+f"(d[3])
                 : "r"(a[0]), "r"(a[1]), "r"(a[2]), "r"(a[3]), "r"(b[0]), "r"(b[1]));
}
__device__ __forceinline__ void cp16(uint32_t dst, const void* src) {
    asm volatile("cp.async.cg.shared.global [%0], [%1], 16;"
                 :: "r"(dst), "l"(__cvta_generic_to_global(src)));
}
#define CP_COMMIT() asm volatile("cp.async.commit_group;")
#define CP_WAIT2()  asm volatile("cp.async.wait_group 2;")
#define CP_WAIT0()  asm volatile("cp.async.wait_group 0;")
#define SWZ64(o) ((o) ^ (((o) >> 3) & 0x30))

__device__ __forceinline__ uint32_t packh2(__half a, __half b) {
    __half2 t = __halves2half2(a, b);
    return *(uint32_t*)&t;
}

// ------------------------------------------------------------- device scratch
__device__ float  g_A1[4096 * 1024];
__device__ float  g_B1[4096 * 1024];
__device__ __half g_T1h[4096 * 1024];        // relu(x@t1w+b), fp16
__device__ __half g_PAh[131072u * 1024];     // relu(A1[b,i]+B1[b,j]), fp16
__device__ float  g_erow[4096];
__device__ float  g_eint[131072];
__device__ __half g_T2T[1024 * 1024];        // traj2_w^T [n][k], fp16
__device__ __half g_I2T[1024 * 1024];        // int2_w^T  [n][k], fp16
__device__ __half g_Xh[4096 * 416];          // x rows fp16, K padded to 416
__device__ __half g_W1T[3072 * 416];         // [t1w | i1w_hi | i1w_lo]^T fp16

__global__ void init_kernel() {
    int idx = blockIdx.x * blockDim.x + threadIdx.x;
    if (idx < 131072) g_eint[idx] = 0.f;
    if (idx < 4096)   g_erow[idx] = 0.f;
}

// ------------------------------------------- prep: W2 transpose to fp16
__global__ void prep_transpose(const float* __restrict__ t2w, const float* __restrict__ i2w) {
    __shared__ float tile[32][33];
    const float* src = blockIdx.z ? i2w : t2w;
    __half* dst = blockIdx.z ? g_I2T : g_T2T;
    int k = blockIdx.y * 32 + threadIdx.y;
    int n = blockIdx.x * 32 + threadIdx.x;
    tile[threadIdx.y][threadIdx.x] = src[k * 1024 + n];
    __syncthreads();
    float v = tile[threadIdx.x][threadIdx.y];
    int nn = blockIdx.x * 32 + threadIdx.y;
    int kk = blockIdx.y * 32 + threadIdx.x;
    dst[nn * 1024 + kk] = __float2half_rn(v);
}

// --------------------------- prep: x rows -> fp16, K 400 padded to 416 ------
__global__ void convert_x_kernel(const float* __restrict__ x) {
    const int row = blockIdx.x;          // 0..4095 (rows contiguous, 400 floats)
    const int t = threadIdx.x;           // 0..127, active t<104
    if (t >= 104) return;
    const int k = t * 4;
    uint2 out;
    if (k < 400) {
        float4 v = *(const float4*)(x + (size_t)row * 400 + k);
        out = make_uint2(packh2(__float2half_rn(v.x), __float2half_rn(v.y)),
                         packh2(__float2half_rn(v.z), __float2half_rn(v.w)));
    } else {
        out = make_uint2(0u, 0u);
    }
    *(uint2*)&g_Xh[(size_t)row * 416 + k] = out;
}

// --------------------- prep: W1 segments -> transposed fp16 [3072][416] -----
// n in [0,1024): t1w col n;  [1024,2048): i1w[0:400] col; [2048,3072): i1w[400:800]
__global__ void convert_w1_kernel(const float* __restrict__ t1w,
                                  const float* __restrict__ i1w) {
    __shared__ float tile[32][33];
    int n = blockIdx.x * 32 + threadIdx.x;
    int k = blockIdx.y * 32 + threadIdx.y;
    float v = 0.f;
    if (k < 400) {
        int seg = n >> 10, nc = n & 1023;
        v = (seg == 0) ? t1w[k * 1024 + nc]
          : (seg == 1) ? i1w[k * 1024 + nc]
                       : i1w[(k + 400) * 1024 + nc];
    }
    tile[threadIdx.y][threadIdx.x] = v;
    __syncthreads();
    int nn = blockIdx.x * 32 + threadIdx.y;
    int kk = blockIdx.y * 32 + threadIdx.x;
    g_W1T[(size_t)nn * 416 + kk] = __float2half_rn(tile[threadIdx.x][threadIdx.y]);
}

// --------------------------------------------- shared GEMM tile constants ---
static constexpr uint32_t TB_A = 0;
static constexpr uint32_t TB_B = 8 * 1024;
static constexpr uint32_t TB_STAGE = 16 * 1024;
static constexpr int NSTAGE = 4;
static constexpr uint32_t TS_SMEM = NSTAGE * TB_STAGE + 1024 + 1024;

// ------------------------------------- stage1 GEMM (HMMA): X @ W1 -> 3 segs -
// M=4096, N=3072, K=416 (13 chunks). Epilogue by n-seg:
//   seg0 -> g_T1h = fp16(relu(acc + t1b));  seg1 -> g_A1 = acc + i1b;
//   seg2 -> g_B1 = acc.
static constexpr int NCH1 = 13;

__global__ __launch_bounds__(128, 2)
void stage1_mma_kernel(const float* __restrict__ t1b, const float* __restrict__ i1b)
{
    extern __shared__ char smem_raw[];
    const uint32_t smem_u = smem_u32(smem_raw);
    const uint32_t base_u = (smem_u + 1023) & ~1023u;
    char* p = smem_raw + (base_u - smem_u);
    float* sb1 = (float*)(p + NSTAGE * TB_STAGE);

    const int tid  = threadIdx.x;
    const int lane = tid & 31;
    const int wid  = tid >> 5;
    const int wm   = wid & 1;
    const int wn   = wid >> 1;
    const int m0   = blockIdx.x * 128;
    const int n0   = blockIdx.y * 128;
    const int seg  = n0 >> 10;

    if (seg == 0)      sb1[tid] = t1b[n0 + tid];
    else if (seg == 1) sb1[tid] = i1b[n0 - 1024 + tid];
    else               sb1[tid] = 0.f;

    auto fillAB = [&](int stage, int k0) {
        const uint32_t sb = base_u + (uint32_t)stage * TB_STAGE;
        #pragma unroll
        for (int t = 0; t < 4; ++t) {
            int idx = tid + t * 128;
            int rl = idx >> 2;
            int cc = idx & 3;
            const __half* src = g_Xh + (size_t)(m0 + rl) * 416 + k0 + cc * 8;
            cp16(sb + TB_A + SWZ64((uint32_t)(rl * 64 + cc * 16)), src);
        }
        #pragma unroll
        for (int t = 0; t < 4; ++t) {
            int idx = tid + t * 128;
            int rl = idx >> 2;
            int cc = idx & 3;
            const __half* src = g_W1T + (size_t)(n0 + rl) * 416 + k0 + cc * 8;
            cp16(sb + TB_B + SWZ64((uint32_t)(rl * 64 + cc * 16)), src);
        }
    };

    uint32_t aoff[4], boff[4];
    #pragma unroll
    for (int mf = 0; mf < 4; ++mf)
        aoff[mf] = (uint32_t)((wm * 64 + mf * 16 + (lane & 15)) * 64 + (lane >> 4) * 16);
    #pragma unroll
    for (int nf2 = 0; nf2 < 4; ++nf2)
        boff[nf2] = (uint32_t)((wn * 64 + nf2 * 16 + (lane & 7) + ((lane & 16) ? 8 : 0)) * 64
                               + ((lane >> 3) & 1) * 16);

    float acc[4][8][4];
    #pragma unroll
    for (int mf = 0; mf < 4; ++mf)
        #pragma unroll
        for (int nf = 0; nf < 8; ++nf)
            #pragma unroll
            for (int q = 0; q < 4; ++q) acc[mf][nf][q] = 0.f;

    auto compute = [&](int stage) {
        const uint32_t sb = base_u + (uint32_t)stage * TB_STAGE;
        #pragma unroll
        for (int kf = 0; kf < 2; ++kf) {
            const uint32_t kadd = kf * 32;
            uint32_t ah[4][4], bf[8][2];
            #pragma unroll
            for (int mf = 0; mf < 4; ++mf) {
                uint32_t sw = SWZ64(aoff[mf] + kadd);
                ldsm4(ah[mf][0], ah[mf][1], ah[mf][2], ah[mf][3], sb + TB_A + sw);
            }
            #pragma unroll
            for (int nf2 = 0; nf2 < 4; ++nf2) {
                uint32_t sw = SWZ64(boff[nf2] + kadd);
                ldsm4(bf[nf2 * 2][0], bf[nf2 * 2][1],
                      bf[nf2 * 2 + 1][0], bf[nf2 * 2 + 1][1], sb + TB_B + sw);
            }
            #pragma unroll
            for (int mf = 0; mf < 4; ++mf)
                #pragma unroll
                for (int nf = 0; nf < 8; ++nf)
                    mma16816(acc[mf][nf], ah[mf], bf[nf]);
        }
    };

    fillAB(0, 0);  CP_COMMIT();
    fillAB(1, 32); CP_COMMIT();
    fillAB(2, 64); CP_COMMIT();

    #pragma unroll 1
    for (int c = 0; c < NCH1; ++c) {
        if (c + 3 < NCH1) {
            fillAB((c + 3) & 3, (c + 3) * 32); CP_COMMIT();
            CP_WAIT2();
        } else {
            CP_WAIT0();
        }
        __syncthreads();
        compute(c & 3);
        __syncthreads();
    }

    // ---- epilogue by segment ----
    const int colBase = n0 & 1023;
    #pragma unroll
    for (int mf = 0; mf < 4; ++mf) {
        #pragma unroll
        for (int h = 0; h < 2; ++h) {
            const int m = m0 + wm * 64 + mf * 16 + (lane >> 2) + h * 8;
            #pragma unroll
            for (int nf = 0; nf < 8; ++nf) {
                const int nl = wn * 64 + nf * 8 + 2 * (lane & 3);
                float d0 = acc[mf][nf][h * 2 + 0] + sb1[nl];
                float d1 = acc[mf][nf][h * 2 + 1] + sb1[nl + 1];
                const size_t o = (size_t)m * 1024 + colBase + nl;
                if (seg == 0) {
                    d0 = fmaxf(d0, 0.f); d1 = fmaxf(d1, 0.f);
                    *(uint32_t*)&g_T1h[o] = packh2(__float2half_rn(d0), __float2half_rn(d1));
                } else if (seg == 1) {
                    *(float2*)&g_A1[o] = make_float2(d0, d1);
                } else {
                    *(float2*)&g_B1[o] = make_float2(d0, d1);
                }
            }
        }
    }
}

// ------------------------- pair expand: materialize relu(A1[b,i]+B1[b,j]) ---
__global__ __launch_bounds__(128)
void pair_expand_kernel()
{
    const int bi = blockIdx.x;          // b*32 + i
    const int b  = bi >> 5;
    const int i  = bi & 31;
    const int t  = threadIdx.x;         // k granule: 8 values

    const float* Arow = g_A1 + (size_t)bi * 1024 + t * 8;
    float4 a0 = *(const float4*)(Arow);
    float4 a1 = *(const float4*)(Arow + 4);
    const float* Bb = g_B1 + (size_t)(b << 5) * 1024;
    const size_t mbase = ((size_t)b << 10) + ((size_t)i << 5);

    #pragma unroll 4
    for (int j = 0; j < 32; ++j) {
        const float* Brow = Bb + (size_t)j * 1024 + t * 8;
        float4 b0 = *(const float4*)(Brow);
        float4 b1 = *(const float4*)(Brow + 4);
        uint4 out;
        out.x = packh2(__float2half_rn(fmaxf(a0.x + b0.x, 0.f)),
                       __float2half_rn(fmaxf(a0.y + b0.y, 0.f)));
        out.y = packh2(__float2half_rn(fmaxf(a0.z + b0.z, 0.f)),
                       __float2half_rn(fmaxf(a0.w + b0.w, 0.f)));
        out.z = packh2(__float2half_rn(fmaxf(a1.x + b1.x, 0.f)),
                       __float2half_rn(fmaxf(a1.y + b1.y, 0.f)));
        out.w = packh2(__float2half_rn(fmaxf(a1.z + b1.z, 0.f)),
                       __float2half_rn(fmaxf(a1.w + b1.w, 0.f)));
        *(uint4*)&g_PAh[(mbase + j) * 1024 + t * 8] = out;
    }
}

// --------------------------------------------- unified tensor stage (HMMA)
// 128 threads, CTA tile 128x128, warp tile 64x64. 2 CTAs/SM, 4-stage cp.async.
// blockIdx.x < 1024: interaction (g_PAh -> g_eint); else traj -> g_erow.
static constexpr int NCH = 32;   // 1024 / 32

__global__ __launch_bounds__(128, 2)
void tensor_stage_kernel(const float* __restrict__ t2b, const float* __restrict__ t3w,
                         const float* __restrict__ i2b, const float* __restrict__ i3w)
{
    extern __shared__ char smem_raw[];
    const uint32_t smem_u = smem_u32(smem_raw);
    const uint32_t base_u = (smem_u + 1023) & ~1023u;
    char* p = smem_raw + (base_u - smem_u);

    float* sb2 = (float*)(p + NSTAGE * TB_STAGE);
    float* sw3 = sb2 + 128;

    const int tid  = threadIdx.x;
    const int lane = tid & 31;
    const int wid  = tid >> 5;
    const int wm   = wid & 1;
    const int wn   = wid >> 1;

    const bool traj = (blockIdx.x >= 1024);
    const int mTile = traj ? (blockIdx.x - 1024) : blockIdx.x;
    const int n0    = blockIdx.y * 128;
    const int m0    = mTile * 128;

    const __half* Ah  = traj ? g_T1h : g_PAh;
    const __half* WT  = traj ? g_T2T : g_I2T;
    const float*  b2g = traj ? t2b : i2b;
    const float*  w3g = traj ? t3w : i3w;
    float* eout       = traj ? g_erow : g_eint;

    sb2[tid] = b2g[n0 + tid];
    sw3[tid] = w3g[n0 + tid];

    auto fillAB = [&](int stage, int k0) {
        const uint32_t sb = base_u + (uint32_t)stage * TB_STAGE;
        #pragma unroll
        for (int t = 0; t < 4; ++t) {
            int idx = tid + t * 128;
            int rl = idx >> 2;
            int cc = idx & 3;
            const __half* src = Ah + (size_t)(m0 + rl) * 1024 + k0 + cc * 8;
            cp16(sb + TB_A + SWZ64((uint32_t)(rl * 64 + cc * 16)), src);
        }
        #pragma unroll
        for (int t = 0; t < 4; ++t) {
            int idx = tid + t * 128;
            int rl = idx >> 2;
            int cc = idx & 3;
            const __half* src = WT + (size_t)(n0 + rl) * 1024 + k0 + cc * 8;
            cp16(sb + TB_B + SWZ64((uint32_t)(rl * 64 + cc * 16)), src);
        }
    };

    uint32_t aoff[4], boff[4];
    #pragma unroll
    for (int mf = 0; mf < 4; ++mf)
        aoff[mf] = (uint32_t)((wm * 64 + mf * 16 + (lane & 15)) * 64 + (lane >> 4) * 16);
    #pragma unroll
    for (int nf2 = 0; nf2 < 4; ++nf2)
        boff[nf2] = (uint32_t)((wn * 64 + nf2 * 16 + (lane & 7) + ((lane & 16) ? 8 : 0)) * 64
                               + ((lane >> 3) & 1) * 16);

    float acc[4][8][4];
    #pragma unroll
    for (int mf = 0; mf < 4; ++mf)
        #pragma unroll
        for (int nf = 0; nf < 8; ++nf)
            #pragma unroll
            for (int q = 0; q < 4; ++q) acc[mf][nf][q] = 0.f;

    auto compute = [&](int stage) {
        const uint32_t sb = base_u + (uint32_t)stage * TB_STAGE;
        #pragma unroll
        for (int kf = 0; kf < 2; ++kf) {
            const uint32_t kadd = kf * 32;
            uint32_t ah[4][4], bf[8][2];
            #pragma unroll
            for (int mf = 0; mf < 4; ++mf) {
                uint32_t sw = SWZ64(aoff[mf] + kadd);
                ldsm4(ah[mf][0], ah[mf][1], ah[mf][2], ah[mf][3], sb + TB_A + sw);
            }
            #pragma unroll
            for (int nf2 = 0; nf2 < 4; ++nf2) {
                uint32_t sw = SWZ64(boff[nf2] + kadd);
                ldsm4(bf[nf2 * 2][0], bf[nf2 * 2][1],
                      bf[nf2 * 2 + 1][0], bf[nf2 * 2 + 1][1], sb + TB_B + sw);
            }
            #pragma unroll
            for (int mf = 0; mf < 4; ++mf)
                #pragma unroll
                for (int nf = 0; nf < 8; ++nf)
                    mma16816(acc[mf][nf], ah[mf], bf[nf]);
        }
    };

    fillAB(0, 0);  CP_COMMIT();
    fillAB(1, 32); CP_COMMIT();
    fillAB(2, 64); CP_COMMIT();

    #pragma unroll 1
    for (int c = 0; c < NCH; ++c) {
        if (c + 3 < NCH) {
            fillAB((c + 3) & 3, (c + 3) * 32); CP_COMMIT();
            CP_WAIT2();
        } else {
            CP_WAIT0();
        }
        __syncthreads();
        compute(c & 3);
        __syncthreads();
    }

    // ---- epilogue: fused layer-3  e_m += sum_n w3[n]*relu(D+b2[n]) ----
    #pragma unroll
    for (int mf = 0; mf < 4; ++mf) {
        #pragma unroll
        for (int h = 0; h < 2; ++h) {
            float s = 0.f;
            #pragma unroll
            for (int nf = 0; nf < 8; ++nf) {
                int nl = wn * 64 + nf * 8 + 2 * (lane & 3);
                float d0 = acc[mf][nf][h * 2 + 0];
                float d1 = acc[mf][nf][h * 2 + 1];
                s += fmaxf(d0 + sb2[nl], 0.f) * sw3[nl]
                   + fmaxf(d1 + sb2[nl + 1], 0.f) * sw3[nl + 1];
            }
            s += __shfl_xor_sync(0xffffffffu, s, 1);
            s += __shfl_xor_sync(0xffffffffu, s, 2);
            if ((lane & 3) == 0) {
                int m = m0 + wm * 64 + mf * 16 + (lane >> 2) + h * 8;
                atomicAdd(&eout[m], s);
            }
        }
    }
}

// ------------------------------------------------------------------ finalize
__global__ void finalize_kernel(const float* __restrict__ edges,
                                const float* __restrict__ t3b,
                                const float* __restrict__ i3b,
                                float* __restrict__ out)
{
    const int b = blockIdx.x;
    const int tid = threadIdx.x;
    const float bias_i = i3b[0];

    float s = 0.f;
    #pragma unroll
    for (int it = 0; it < 4; ++it) {
        int idx = tid + it * 256;
        s += edges[b * 1024 + idx] * (g_eint[b * 1024 + idx] + bias_i);
    }
    if (tid < 32) s += g_erow[b * 32 + tid] + t3b[0];

    __shared__ float red[256];
    red[tid] = s;
    __syncthreads();
    for (int o = 128; o > 0; o >>= 1) {
        if (tid < o) red[tid] += red[tid + o];
        __syncthreads();
    }
    if (tid == 0) out[b] = red[0];
}

// ---------------------------------------------------------------------------
extern "C" void kernel_launch(void* const* d_in, const int* in_sizes, int n_in,
                              void* d_out, int out_size)
{
    const float* x   = (const float*)d_in[0];
    const float* edg = (const float*)d_in[1];
    const float* t1w = (const float*)d_in[2];
    const float* t1b = (const float*)d_in[3];
    const float* t2w = (const float*)d_in[4];
    const float* t2b = (const float*)d_in[5];
    const float* t3w = (const float*)d_in[6];
    const float* t3b = (const float*)d_in[7];
    const float* i1w = (const float*)d_in[8];
    const float* i1b = (const float*)d_in[9];
    const float* i2w = (const float*)d_in[10];
    const float* i2b = (const float*)d_in[11];
    const float* i3w = (const float*)d_in[12];
    const float* i3b = (const float*)d_in[13];
    float* out = (float*)d_out;

    cudaFuncSetAttribute(tensor_stage_kernel,
                         cudaFuncAttributeMaxDynamicSharedMemorySize, TS_SMEM);
    cudaFuncSetAttribute(stage1_mma_kernel,
                         cudaFuncAttributeMaxDynamicSharedMemorySize, TS_SMEM);

    init_kernel<<<512, 256>>>();

    dim3 gp(32, 32, 2);
    prep_transpose<<<gp, dim3(32, 32)>>>(t2w, i2w);

    convert_x_kernel<<<4096, 128>>>(x);
    convert_w1_kernel<<<dim3(96, 13), dim3(32, 32)>>>(t1w, i1w);

    stage1_mma_kernel<<<dim3(32, 24), 128, TS_SMEM>>>(t1b, i1b);

    pair_expand_kernel<<<4096, 128>>>();

    dim3 gt(1056, 8);   // x<1024: interaction; x>=1024: traj; y: 8 n-tiles
    tensor_stage_kernel<<<gt, 128, TS_SMEM>>>(t2b, t3w, i2b, i3w);

    finalize_kernel<<<128, 256>>>(edg, t3b, i3b, out);
}

// round 12
// speedup vs baseline: 8.2965x; 1.0395x over previous
#include <cuda_runtime.h>
#include <cuda_fp16.h>
#include <cstdint>

// ===========================================================================
// Model_86011015070455 — R12: tensor-stage grid remap for A-tile L2 reuse.
//   mtile = bx>>3, ntile = bx&7  ->  the 8 CTAs sharing one 256KB A-tile are
//   launch-adjacent (co-resident), cutting A DRAM re-reads ~8x.
//   Everything else identical to R11.
// ===========================================================================

__device__ __forceinline__ uint32_t smem_u32(const void* p) {
    uint32_t a;
    asm("{ .reg .u64 t; cvta.to.shared.u64 t, %1; cvt.u32.u64 %0, t; }" : "=r"(a) : "l"(p));
    return a;
}
__device__ __forceinline__ void ldsm4(uint32_t& r0, uint32_t& r1, uint32_t& r2, uint32_t& r3,
                                      uint32_t addr) {
    asm volatile("ldmatrix.sync.aligned.m8n8.x4.shared.b16 {%0,%1,%2,%3}, [%4];"
                 : "=r"(r0), "=r"(r1), "=r"(r2), "=r"(r3) : "r"(addr));
}
__device__ __forceinline__ void mma16816(float* d, const uint32_t* a, const uint32_t* b) {
    asm volatile("mma.sync.aligned.m16n8k16.row.col.f32.f16.f16.f32 "
                 "{%0,%1,%2,%3}, {%4,%5,%6,%7}, {%8,%9}, {%0,%1,%2,%3};"
                 : "+f"(d[0]), "+f"(d[1]), "+f"(d[2]), "+f"(d[3])
                 : "r"(a[0]), "r"(a[1]), "r"(a[2]), "r"(a[3]), "r"(b[0]), "r"(b[1]));
}
__device__ __forceinline__ void cp16(uint32_t dst, const void* src) {
    asm volatile("cp.async.cg.shared.global [%0], [%1], 16;"
                 :: "r"(dst), "l"(__cvta_generic_to_global(src)));
}
#define CP_COMMIT() asm volatile("cp.async.commit_group;")
#define CP_WAIT2()  asm volatile("cp.async.wait_group 2;")
#define CP_WAIT0()  asm volatile("cp.async.wait_group 0;")
#define SWZ64(o) ((o) ^ (((o) >> 3) & 0x30))

__device__ __forceinline__ uint32_t packh2(__half a, __half b) {
    __half2 t = __halves2half2(a, b);
    return *(uint32_t*)&t;
}

// ------------------------------------------------------------- device scratch
__device__ float  g_A1[4096 * 1024];
__device__ float  g_B1[4096 * 1024];
__device__ __half g_T1h[4096 * 1024];        // relu(x@t1w+b), fp16
__device__ __half g_PAh[131072u * 1024];     // relu(A1[b,i]+B1[b,j]), fp16
__device__ float  g_erow[4096];
__device__ float  g_eint[131072];
__device__ __half g_T2T[1024 * 1024];        // traj2_w^T [n][k], fp16
__device__ __half g_I2T[1024 * 1024];        // int2_w^T  [n][k], fp16
__device__ __half g_Xh[4096 * 416];          // x rows fp16, K padded to 416
__device__ __half g_W1T[3072 * 416];         // [t1w | i1w_hi | i1w_lo]^T fp16

__global__ void init_kernel() {
    int idx = blockIdx.x * blockDim.x + threadIdx.x;
    if (idx < 131072) g_eint[idx] = 0.f;
    if (idx < 4096)   g_erow[idx] = 0.f;
}

// ------------------------------------------- prep: W2 transpose to fp16
__global__ void prep_transpose(const float* __restrict__ t2w, const float* __restrict__ i2w) {
    __shared__ float tile[32][33];
    const float* src = blockIdx.z ? i2w : t2w;
    __half* dst = blockIdx.z ? g_I2T : g_T2T;
    int k = blockIdx.y * 32 + threadIdx.y;
    int n = blockIdx.x * 32 + threadIdx.x;
    tile[threadIdx.y][threadIdx.x] = src[k * 1024 + n];
    __syncthreads();
    float v = tile[threadIdx.x][threadIdx.y];
    int nn = blockIdx.x * 32 + threadIdx.y;
    int kk = blockIdx.y * 32 + threadIdx.x;
    dst[nn * 1024 + kk] = __float2half_rn(v);
}

// --------------------------- prep: x rows -> fp16, K 400 padded to 416 ------
__global__ void convert_x_kernel(const float* __restrict__ x) {
    const int row = blockIdx.x;
    const int t = threadIdx.x;
    if (t >= 104) return;
    const int k = t * 4;
    uint2 out;
    if (k < 400) {
        float4 v = *(const float4*)(x + (size_t)row * 400 + k);
        out = make_uint2(packh2(__float2half_rn(v.x), __float2half_rn(v.y)),
                         packh2(__float2half_rn(v.z), __float2half_rn(v.w)));
    } else {
        out = make_uint2(0u, 0u);
    }
    *(uint2*)&g_Xh[(size_t)row * 416 + k] = out;
}

// --------------------- prep: W1 segments -> transposed fp16 [3072][416] -----
__global__ void convert_w1_kernel(const float* __restrict__ t1w,
                                  const float* __restrict__ i1w) {
    __shared__ float tile[32][33];
    int n = blockIdx.x * 32 + threadIdx.x;
    int k = blockIdx.y * 32 + threadIdx.y;
    float v = 0.f;
    if (k < 400) {
        int seg = n >> 10, nc = n & 1023;
        v = (seg == 0) ? t1w[k * 1024 + nc]
          : (seg == 1) ? i1w[k * 1024 + nc]
                       : i1w[(k + 400) * 1024 + nc];
    }
    tile[threadIdx.y][threadIdx.x] = v;
    __syncthreads();
    int nn = blockIdx.x * 32 + threadIdx.y;
    int kk = blockIdx.y * 32 + threadIdx.x;
    g_W1T[(size_t)nn * 416 + kk] = __float2half_rn(tile[threadIdx.x][threadIdx.y]);
}

// --------------------------------------------- shared GEMM tile constants ---
static constexpr uint32_t TB_A = 0;
static constexpr uint32_t TB_B = 8 * 1024;
static constexpr uint32_t TB_STAGE = 16 * 1024;
static constexpr int NSTAGE = 4;
static constexpr uint32_t TS_SMEM = NSTAGE * TB_STAGE + 1024 + 1024;

// ------------------------------------- stage1 GEMM (HMMA): X @ W1 -> 3 segs -
static constexpr int NCH1 = 13;

__global__ __launch_bounds__(128, 2)
void stage1_mma_kernel(const float* __restrict__ t1b, const float* __restrict__ i1b)
{
    extern __shared__ char smem_raw[];
    const uint32_t smem_u = smem_u32(smem_raw);
    const uint32_t base_u = (smem_u + 1023) & ~1023u;
    char* p = smem_raw + (base_u - smem_u);
    float* sb1 = (float*)(p + NSTAGE * TB_STAGE);

    const int tid  = threadIdx.x;
    const int lane = tid & 31;
    const int wid  = tid >> 5;
    const int wm   = wid & 1;
    const int wn   = wid >> 1;
    const int m0   = blockIdx.x * 128;
    const int n0   = blockIdx.y * 128;
    const int seg  = n0 >> 10;

    if (seg == 0)      sb1[tid] = t1b[n0 + tid];
    else if (seg == 1) sb1[tid] = i1b[n0 - 1024 + tid];
    else               sb1[tid] = 0.f;

    auto fillAB = [&](int stage, int k0) {
        const uint32_t sb = base_u + (uint32_t)stage * TB_STAGE;
        #pragma unroll
        for (int t = 0; t < 4; ++t) {
            int idx = tid + t * 128;
            int rl = idx >> 2;
            int cc = idx & 3;
            const __half* src = g_Xh + (size_t)(m0 + rl) * 416 + k0 + cc * 8;
            cp16(sb + TB_A + SWZ64((uint32_t)(rl * 64 + cc * 16)), src);
        }
        #pragma unroll
        for (int t = 0; t < 4; ++t) {
            int idx = tid + t * 128;
            int rl = idx >> 2;
            int cc = idx & 3;
            const __half* src = g_W1T + (size_t)(n0 + rl) * 416 + k0 + cc * 8;
            cp16(sb + TB_B + SWZ64((uint32_t)(rl * 64 + cc * 16)), src);
        }
    };

    uint32_t aoff[4], boff[4];
    #pragma unroll
    for (int mf = 0; mf < 4; ++mf)
        aoff[mf] = (uint32_t)((wm * 64 + mf * 16 + (lane & 15)) * 64 + (lane >> 4) * 16);
    #pragma unroll
    for (int nf2 = 0; nf2 < 4; ++nf2)
        boff[nf2] = (uint32_t)((wn * 64 + nf2 * 16 + (lane & 7) + ((lane & 16) ? 8 : 0)) * 64
                               + ((lane >> 3) & 1) * 16);

    float acc[4][8][4];
    #pragma unroll
    for (int mf = 0; mf < 4; ++mf)
        #pragma unroll
        for (int nf = 0; nf < 8; ++nf)
            #pragma unroll
            for (int q = 0; q < 4; ++q) acc[mf][nf][q] = 0.f;

    auto compute = [&](int stage) {
        const uint32_t sb = base_u + (uint32_t)stage * TB_STAGE;
        #pragma unroll
        for (int kf = 0; kf < 2; ++kf) {
            const uint32_t kadd = kf * 32;
            uint32_t ah[4][4], bf[8][2];
            #pragma unroll
            for (int mf = 0; mf < 4; ++mf) {
                uint32_t sw = SWZ64(aoff[mf] + kadd);
                ldsm4(ah[mf][0], ah[mf][1], ah[mf][2], ah[mf][3], sb + TB_A + sw);
            }
            #pragma unroll
            for (int nf2 = 0; nf2 < 4; ++nf2) {
                uint32_t sw = SWZ64(boff[nf2] + kadd);
                ldsm4(bf[nf2 * 2][0], bf[nf2 * 2][1],
                      bf[nf2 * 2 + 1][0], bf[nf2 * 2 + 1][1], sb + TB_B + sw);
            }
            #pragma unroll
            for (int mf = 0; mf < 4; ++mf)
                #pragma unroll
                for (int nf = 0; nf < 8; ++nf)
                    mma16816(acc[mf][nf], ah[mf], bf[nf]);
        }
    };

    fillAB(0, 0);  CP_COMMIT();
    fillAB(1, 32); CP_COMMIT();
    fillAB(2, 64); CP_COMMIT();

    #pragma unroll 1
    for (int c = 0; c < NCH1; ++c) {
        if (c + 3 < NCH1) {
            fillAB((c + 3) & 3, (c + 3) * 32); CP_COMMIT();
            CP_WAIT2();
        } else {
            CP_WAIT0();
        }
        __syncthreads();
        compute(c & 3);
        __syncthreads();
    }

    const int colBase = n0 & 1023;
    #pragma unroll
    for (int mf = 0; mf < 4; ++mf) {
        #pragma unroll
        for (int h = 0; h < 2; ++h) {
            const int m = m0 + wm * 64 + mf * 16 + (lane >> 2) + h * 8;
            #pragma unroll
            for (int nf = 0; nf < 8; ++nf) {
                const int nl = wn * 64 + nf * 8 + 2 * (lane & 3);
                float d0 = acc[mf][nf][h * 2 + 0] + sb1[nl];
                float d1 = acc[mf][nf][h * 2 + 1] + sb1[nl + 1];
                const size_t o = (size_t)m * 1024 + colBase + nl;
                if (seg == 0) {
                    d0 = fmaxf(d0, 0.f); d1 = fmaxf(d1, 0.f);
                    *(uint32_t*)&g_T1h[o] = packh2(__float2half_rn(d0), __float2half_rn(d1));
                } else if (seg == 1) {
                    *(float2*)&g_A1[o] = make_float2(d0, d1);
                } else {
                    *(float2*)&g_B1[o] = make_float2(d0, d1);
                }
            }
        }
    }
}

// ------------------------- pair expand: materialize relu(A1[b,i]+B1[b,j]) ---
__global__ __launch_bounds__(128)
void pair_expand_kernel()
{
    const int bi = blockIdx.x;
    const int b  = bi >> 5;
    const int i  = bi & 31;
    const int t  = threadIdx.x;

    const float* Arow = g_A1 + (size_t)bi * 1024 + t * 8;
    float4 a0 = *(const float4*)(Arow);
    float4 a1 = *(const float4*)(Arow + 4);
    const float* Bb = g_B1 + (size_t)(b << 5) * 1024;
    const size_t mbase = ((size_t)b << 10) + ((size_t)i << 5);

    #pragma unroll 4
    for (int j = 0; j < 32; ++j) {
        const float* Brow = Bb + (size_t)j * 1024 + t * 8;
        float4 b0 = *(const float4*)(Brow);
        float4 b1 = *(const float4*)(Brow + 4);
        uint4 out;
        out.x = packh2(__float2half_rn(fmaxf(a0.x + b0.x, 0.f)),
                       __float2half_rn(fmaxf(a0.y + b0.y, 0.f)));
        out.y = packh2(__float2half_rn(fmaxf(a0.z + b0.z, 0.f)),
                       __float2half_rn(fmaxf(a0.w + b0.w, 0.f)));
        out.z = packh2(__float2half_rn(fmaxf(a1.x + b1.x, 0.f)),
                       __float2half_rn(fmaxf(a1.y + b1.y, 0.f)));
        out.w = packh2(__float2half_rn(fmaxf(a1.z + b1.z, 0.f)),
                       __float2half_rn(fmaxf(a1.w + b1.w, 0.f)));
        *(uint4*)&g_PAh[(mbase + j) * 1024 + t * 8] = out;
    }
}

// --------------------------------------------- unified tensor stage (HMMA)
// 1-D grid, n-tile fastest: bx < 8192: interaction, mtile=bx>>3, nt=bx&7;
// bx >= 8192: traj, idx=bx-8192, mtile=idx>>3, nt=idx&7.
// The 8 CTAs sharing an A-tile are launch-adjacent -> A reads hit L2.
static constexpr int NCH = 32;   // 1024 / 32

__global__ __launch_bounds__(128, 2)
void tensor_stage_kernel(const float* __restrict__ t2b, const float* __restrict__ t3w,
                         const float* __restrict__ i2b, const float* __restrict__ i3w)
{
    extern __shared__ char smem_raw[];
    const uint32_t smem_u = smem_u32(smem_raw);
    const uint32_t base_u = (smem_u + 1023) & ~1023u;
    char* p = smem_raw + (base_u - smem_u);

    float* sb2 = (float*)(p + NSTAGE * TB_STAGE);
    float* sw3 = sb2 + 128;

    const int tid  = threadIdx.x;
    const int lane = tid & 31;
    const int wid  = tid >> 5;
    const int wm   = wid & 1;
    const int wn   = wid >> 1;

    const bool traj = (blockIdx.x >= 8192);
    const int idx   = traj ? (blockIdx.x - 8192) : blockIdx.x;
    const int m0    = (idx >> 3) * 128;
    const int n0    = (idx & 7) * 128;

    const __half* Ah  = traj ? g_T1h : g_PAh;
    const __half* WT  = traj ? g_T2T : g_I2T;
    const float*  b2g = traj ? t2b : i2b;
    const float*  w3g = traj ? t3w : i3w;
    float* eout       = traj ? g_erow : g_eint;

    sb2[tid] = b2g[n0 + tid];
    sw3[tid] = w3g[n0 + tid];

    auto fillAB = [&](int stage, int k0) {
        const uint32_t sb = base_u + (uint32_t)stage * TB_STAGE;
        #pragma unroll
        for (int t = 0; t < 4; ++t) {
            int idx2 = tid + t * 128;
            int rl = idx2 >> 2;
            int cc = idx2 & 3;
            const __half* src = Ah + (size_t)(m0 + rl) * 1024 + k0 + cc * 8;
            cp16(sb + TB_A + SWZ64((uint32_t)(rl * 64 + cc * 16)), src);
        }
        #pragma unroll
        for (int t = 0; t < 4; ++t) {
            int idx2 = tid + t * 128;
            int rl = idx2 >> 2;
            int cc = idx2 & 3;
            const __half* src = WT + (size_t)(n0 + rl) * 1024 + k0 + cc * 8;
            cp16(sb + TB_B + SWZ64((uint32_t)(rl * 64 + cc * 16)), src);
        }
    };

    uint32_t aoff[4], boff[4];
    #pragma unroll
    for (int mf = 0; mf < 4; ++mf)
        aoff[mf] = (uint32_t)((wm * 64 + mf * 16 + (lane & 15)) * 64 + (lane >> 4) * 16);
    #pragma unroll
    for (int nf2 = 0; nf2 < 4; ++nf2)
        boff[nf2] = (uint32_t)((wn * 64 + nf2 * 16 + (lane & 7) + ((lane & 16) ? 8 : 0)) * 64
                               + ((lane >> 3) & 1) * 16);

    float acc[4][8][4];
    #pragma unroll
    for (int mf = 0; mf < 4; ++mf)
        #pragma unroll
        for (int nf = 0; nf < 8; ++nf)
            #pragma unroll
            for (int q = 0; q < 4; ++q) acc[mf][nf][q] = 0.f;

    auto compute = [&](int stage) {
        const uint32_t sb = base_u + (uint32_t)stage * TB_STAGE;
        #pragma unroll
        for (int kf = 0; kf < 2; ++kf) {
            const uint32_t kadd = kf * 32;
            uint32_t ah[4][4], bf[8][2];
            #pragma unroll
            for (int mf = 0; mf < 4; ++mf) {
                uint32_t sw = SWZ64(aoff[mf] + kadd);
                ldsm4(ah[mf][0], ah[mf][1], ah[mf][2], ah[mf][3], sb + TB_A + sw);
            }
            #pragma unroll
            for (int nf2 = 0; nf2 < 4; ++nf2) {
                uint32_t sw = SWZ64(boff[nf2] + kadd);
                ldsm4(bf[nf2 * 2][0], bf[nf2 * 2][1],
                      bf[nf2 * 2 + 1][0], bf[nf2 * 2 + 1][1], sb + TB_B + sw);
            }
            #pragma unroll
            for (int mf = 0; mf < 4; ++mf)
                #pragma unroll
                for (int nf = 0; nf < 8; ++nf)
                    mma16816(acc[mf][nf], ah[mf], bf[nf]);
        }
    };

    fillAB(0, 0);  CP_COMMIT();
    fillAB(1, 32); CP_COMMIT();
    fillAB(2, 64); CP_COMMIT();

    #pragma unroll 1
    for (int c = 0; c < NCH; ++c) {
        if (c + 3 < NCH) {
            fillAB((c + 3) & 3, (c + 3) * 32); CP_COMMIT();
            CP_WAIT2();
        } else {
            CP_WAIT0();
        }
        __syncthreads();
        compute(c & 3);
        __syncthreads();
    }

    // ---- epilogue: fused layer-3  e_m += sum_n w3[n]*relu(D+b2[n]) ----
    #pragma unroll
    for (int mf = 0; mf < 4; ++mf) {
        #pragma unroll
        for (int h = 0; h < 2; ++h) {
            float s = 0.f;
            #pragma unroll
            for (int nf = 0; nf < 8; ++nf) {
                int nl = wn * 64 + nf * 8 + 2 * (lane & 3);
                float d0 = acc[mf][nf][h * 2 + 0];
                float d1 = acc[mf][nf][h * 2 + 1];
                s += fmaxf(d0 + sb2[nl], 0.f) * sw3[nl]
                   + fmaxf(d1 + sb2[nl + 1], 0.f) * sw3[nl + 1];
            }
            s += __shfl_xor_sync(0xffffffffu, s, 1);
            s += __shfl_xor_sync(0xffffffffu, s, 2);
            if ((lane & 3) == 0) {
                int m = m0 + wm * 64 + mf * 16 + (lane >> 2) + h * 8;
                atomicAdd(&eout[m], s);
            }
        }
    }
}

// ------------------------------------------------------------------ finalize
__global__ void finalize_kernel(const float* __restrict__ edges,
                                const float* __restrict__ t3b,
                                const float* __restrict__ i3b,
                                float* __restrict__ out)
{
    const int b = blockIdx.x;
    const int tid = threadIdx.x;
    const float bias_i = i3b[0];

    float s = 0.f;
    #pragma unroll
    for (int it = 0; it < 4; ++it) {
        int idx = tid + it * 256;
        s += edges[b * 1024 + idx] * (g_eint[b * 1024 + idx] + bias_i);
    }
    if (tid < 32) s += g_erow[b * 32 + tid] + t3b[0];

    __shared__ float red[256];
    red[tid] = s;
    __syncthreads();
    for (int o = 128; o > 0; o >>= 1) {
        if (tid < o) red[tid] += red[tid + o];
        __syncthreads();
    }
    if (tid == 0) out[b] = red[0];
}

// ---------------------------------------------------------------------------
extern "C" void kernel_launch(void* const* d_in, const int* in_sizes, int n_in,
                              void* d_out, int out_size)
{
    const float* x   = (const float*)d_in[0];
    const float* edg = (const float*)d_in[1];
    const float* t1w = (const float*)d_in[2];
    const float* t1b = (const float*)d_in[3];
    const float* t2w = (const float*)d_in[4];
    const float* t2b = (const float*)d_in[5];
    const float* t3w = (const float*)d_in[6];
    const float* t3b = (const float*)d_in[7];
    const float* i1w = (const float*)d_in[8];
    const float* i1b = (const float*)d_in[9];
    const float* i2w = (const float*)d_in[10];
    const float* i2b = (const float*)d_in[11];
    const float* i3w = (const float*)d_in[12];
    const float* i3b = (const float*)d_in[13];
    float* out = (float*)d_out;

    cudaFuncSetAttribute(tensor_stage_kernel,
                         cudaFuncAttributeMaxDynamicSharedMemorySize, TS_SMEM);
    cudaFuncSetAttribute(stage1_mma_kernel,
                         cudaFuncAttributeMaxDynamicSharedMemorySize, TS_SMEM);

    init_kernel<<<512, 256>>>();

    dim3 gp(32, 32, 2);
    prep_transpose<<<gp, dim3(32, 32)>>>(t2w, i2w);

    convert_x_kernel<<<4096, 128>>>(x);
    convert_w1_kernel<<<dim3(96, 13), dim3(32, 32)>>>(t1w, i1w);

    stage1_mma_kernel<<<dim3(32, 24), 128, TS_SMEM>>>(t1b, i1b);

    pair_expand_kernel<<<4096, 128>>>();

    tensor_stage_kernel<<<8448, 128, TS_SMEM>>>(t2b, t3w, i2b, i3w);

    finalize_kernel<<<128, 256>>>(edg, t3b, i3b, out);
}

// round 13
// speedup vs baseline: 8.9619x; 1.0802x over previous
#include <cuda_runtime.h>
#include <cuda_fp16.h>
#include <cstdint>

// ===========================================================================
// Model_86011015070455 — R13: pair-expansion fused into the tensor-stage
//   A-fill. stage1 emits A1h/B1h as fp16 (8MB each, L2-resident); the
//   interaction A-tile rows relu(A1h[b,i]+B1h[b,j]) are generated in-kernel
//   (L2-hit LDG + HADD2/HMAX2 + STS, prefetched 1 chunk ahead).
//   g_PAh (268MB round-trip) and pair_expand kernel deleted.
// ===========================================================================

__device__ __forceinline__ uint32_t smem_u32(const void* p) {
    uint32_t a;
    asm("{ .reg .u64 t; cvta.to.shared.u64 t, %1; cvt.u32.u64 %0, t; }" : "=r"(a) : "l"(p));
    return a;
}
__device__ __forceinline__ void ldsm4(uint32_t& r0, uint32_t& r1, uint32_t& r2, uint32_t& r3,
                                      uint32_t addr) {
    asm volatile("ldmatrix.sync.aligned.m8n8.x4.shared.b16 {%0,%1,%2,%3}, [%4];"
                 : "=r"(r0), "=r"(r1), "=r"(r2), "=r"(r3) : "r"(addr));
}
__device__ __forceinline__ void mma16816(float* d, const uint32_t* a, const uint32_t* b) {
    asm volatile("mma.sync.aligned.m16n8k16.row.col.f32.f16.f16.f32 "
                 "{%0,%1,%2,%3}, {%4,%5,%6,%7}, {%8,%9}, {%0,%1,%2,%3};"
                 : "+f"(d[0]), "+f"(d[1]), "+f"(d[2]), "+f"(d[3])
                 : "r"(a[0]), "r"(a[1]), "r"(a[2]), "r"(a[3]), "r"(b[0]), "r"(b[1]));
}
__device__ __forceinline__ void cp16(uint32_t dst, const void* src) {
    asm volatile("cp.async.cg.shared.global [%0], [%1], 16;"
                 :: "r"(dst), "l"(__cvta_generic_to_global(src)));
}
#define CP_COMMIT() asm volatile("cp.async.commit_group;")
#define CP_WAIT2()  asm volatile("cp.async.wait_group 2;")
#define CP_WAIT0()  asm volatile("cp.async.wait_group 0;")
#define SWZ64(o) ((o) ^ (((o) >> 3) & 0x30))

__device__ __forceinline__ uint32_t packh2(__half a, __half b) {
    __half2 t = __halves2half2(a, b);
    return *(uint32_t*)&t;
}
__device__ __forceinline__ uint32_t haddrelu2(uint32_t a, uint32_t b) {
    __half2 s = __hadd2(*(__half2*)&a, *(__half2*)&b);
    s = __hmax2(s, __float2half2_rn(0.f));
    return *(uint32_t*)&s;
}

// ------------------------------------------------------------- device scratch
__device__ __half g_A1h[4096 * 1024];        // x@i1w[:400]+i1b, fp16 (8MB, L2)
__device__ __half g_B1h[4096 * 1024];        // x@i1w[400:], fp16 (8MB, L2)
__device__ __half g_T1h[4096 * 1024];        // relu(x@t1w+b), fp16
__device__ float  g_erow[4096];
__device__ float  g_eint[131072];
__device__ __half g_T2T[1024 * 1024];        // traj2_w^T [n][k], fp16
__device__ __half g_I2T[1024 * 1024];        // int2_w^T  [n][k], fp16
__device__ __half g_Xh[4096 * 416];          // x rows fp16, K padded to 416
__device__ __half g_W1T[3072 * 416];         // [t1w | i1w_hi | i1w_lo]^T fp16

__global__ void init_kernel() {
    int idx = blockIdx.x * blockDim.x + threadIdx.x;
    if (idx < 131072) g_eint[idx] = 0.f;
    if (idx < 4096)   g_erow[idx] = 0.f;
}

// ------------------------------------------- prep: W2 transpose to fp16
__global__ void prep_transpose(const float* __restrict__ t2w, const float* __restrict__ i2w) {
    __shared__ float tile[32][33];
    const float* src = blockIdx.z ? i2w : t2w;
    __half* dst = blockIdx.z ? g_I2T : g_T2T;
    int k = blockIdx.y * 32 + threadIdx.y;
    int n = blockIdx.x * 32 + threadIdx.x;
    tile[threadIdx.y][threadIdx.x] = src[k * 1024 + n];
    __syncthreads();
    float v = tile[threadIdx.x][threadIdx.y];
    int nn = blockIdx.x * 32 + threadIdx.y;
    int kk = blockIdx.y * 32 + threadIdx.x;
    dst[nn * 1024 + kk] = __float2half_rn(v);
}

// --------------------------- prep: x rows -> fp16, K 400 padded to 416 ------
__global__ void convert_x_kernel(const float* __restrict__ x) {
    const int row = blockIdx.x;
    const int t = threadIdx.x;
    if (t >= 104) return;
    const int k = t * 4;
    uint2 out;
    if (k < 400) {
        float4 v = *(const float4*)(x + (size_t)row * 400 + k);
        out = make_uint2(packh2(__float2half_rn(v.x), __float2half_rn(v.y)),
                         packh2(__float2half_rn(v.z), __float2half_rn(v.w)));
    } else {
        out = make_uint2(0u, 0u);
    }
    *(uint2*)&g_Xh[(size_t)row * 416 + k] = out;
}

// --------------------- prep: W1 segments -> transposed fp16 [3072][416] -----
__global__ void convert_w1_kernel(const float* __restrict__ t1w,
                                  const float* __restrict__ i1w) {
    __shared__ float tile[32][33];
    int n = blockIdx.x * 32 + threadIdx.x;
    int k = blockIdx.y * 32 + threadIdx.y;
    float v = 0.f;
    if (k < 400) {
        int seg = n >> 10, nc = n & 1023;
        v = (seg == 0) ? t1w[k * 1024 + nc]
          : (seg == 1) ? i1w[k * 1024 + nc]
                       : i1w[(k + 400) * 1024 + nc];
    }
    tile[threadIdx.y][threadIdx.x] = v;
    __syncthreads();
    int nn = blockIdx.x * 32 + threadIdx.y;
    int kk = blockIdx.y * 32 + threadIdx.x;
    g_W1T[(size_t)nn * 416 + kk] = __float2half_rn(tile[threadIdx.x][threadIdx.y]);
}

// --------------------------------------------- shared GEMM tile constants ---
static constexpr uint32_t TB_A = 0;
static constexpr uint32_t TB_B = 8 * 1024;
static constexpr uint32_t TB_STAGE = 16 * 1024;
static constexpr int NSTAGE = 4;
static constexpr uint32_t TS_SMEM = NSTAGE * TB_STAGE + 1024 + 1024;

// ------------------------------------- stage1 GEMM (HMMA): X @ W1 -> 3 segs -
static constexpr int NCH1 = 13;

__global__ __launch_bounds__(128, 2)
void stage1_mma_kernel(const float* __restrict__ t1b, const float* __restrict__ i1b)
{
    extern __shared__ char smem_raw[];
    const uint32_t smem_u = smem_u32(smem_raw);
    const uint32_t base_u = (smem_u + 1023) & ~1023u;
    char* p = smem_raw + (base_u - smem_u);
    float* sb1 = (float*)(p + NSTAGE * TB_STAGE);

    const int tid  = threadIdx.x;
    const int lane = tid & 31;
    const int wid  = tid >> 5;
    const int wm   = wid & 1;
    const int wn   = wid >> 1;
    const int m0   = blockIdx.x * 128;
    const int n0   = blockIdx.y * 128;
    const int seg  = n0 >> 10;

    if (seg == 0)      sb1[tid] = t1b[n0 + tid];
    else if (seg == 1) sb1[tid] = i1b[n0 - 1024 + tid];
    else               sb1[tid] = 0.f;

    auto fillAB = [&](int stage, int k0) {
        const uint32_t sb = base_u + (uint32_t)stage * TB_STAGE;
        #pragma unroll
        for (int t = 0; t < 4; ++t) {
            int idx = tid + t * 128;
            int rl = idx >> 2;
            int cc = idx & 3;
            const __half* src = g_Xh + (size_t)(m0 + rl) * 416 + k0 + cc * 8;
            cp16(sb + TB_A + SWZ64((uint32_t)(rl * 64 + cc * 16)), src);
        }
        #pragma unroll
        for (int t = 0; t < 4; ++t) {
            int idx = tid + t * 128;
            int rl = idx >> 2;
            int cc = idx & 3;
            const __half* src = g_W1T + (size_t)(n0 + rl) * 416 + k0 + cc * 8;
            cp16(sb + TB_B + SWZ64((uint32_t)(rl * 64 + cc * 16)), src);
        }
    };

    uint32_t aoff[4], boff[4];
    #pragma unroll
    for (int mf = 0; mf < 4; ++mf)
        aoff[mf] = (uint32_t)((wm * 64 + mf * 16 + (lane & 15)) * 64 + (lane >> 4) * 16);
    #pragma unroll
    for (int nf2 = 0; nf2 < 4; ++nf2)
        boff[nf2] = (uint32_t)((wn * 64 + nf2 * 16 + (lane & 7) + ((lane & 16) ? 8 : 0)) * 64
                               + ((lane >> 3) & 1) * 16);

    float acc[4][8][4];
    #pragma unroll
    for (int mf = 0; mf < 4; ++mf)
        #pragma unroll
        for (int nf = 0; nf < 8; ++nf)
            #pragma unroll
            for (int q = 0; q < 4; ++q) acc[mf][nf][q] = 0.f;

    auto compute = [&](int stage) {
        const uint32_t sb = base_u + (uint32_t)stage * TB_STAGE;
        #pragma unroll
        for (int kf = 0; kf < 2; ++kf) {
            const uint32_t kadd = kf * 32;
            uint32_t ah[4][4], bf[8][2];
            #pragma unroll
            for (int mf = 0; mf < 4; ++mf) {
                uint32_t sw = SWZ64(aoff[mf] + kadd);
                ldsm4(ah[mf][0], ah[mf][1], ah[mf][2], ah[mf][3], sb + TB_A + sw);
            }
            #pragma unroll
            for (int nf2 = 0; nf2 < 4; ++nf2) {
                uint32_t sw = SWZ64(boff[nf2] + kadd);
                ldsm4(bf[nf2 * 2][0], bf[nf2 * 2][1],
                      bf[nf2 * 2 + 1][0], bf[nf2 * 2 + 1][1], sb + TB_B + sw);
            }
            #pragma unroll
            for (int mf = 0; mf < 4; ++mf)
                #pragma unroll
                for (int nf = 0; nf < 8; ++nf)
                    mma16816(acc[mf][nf], ah[mf], bf[nf]);
        }
    };

    fillAB(0, 0);  CP_COMMIT();
    fillAB(1, 32); CP_COMMIT();
    fillAB(2, 64); CP_COMMIT();

    #pragma unroll 1
    for (int c = 0; c < NCH1; ++c) {
        if (c + 3 < NCH1) {
            fillAB((c + 3) & 3, (c + 3) * 32); CP_COMMIT();
            CP_WAIT2();
        } else {
            CP_WAIT0();
        }
        __syncthreads();
        compute(c & 3);
        __syncthreads();
    }

    const int colBase = n0 & 1023;
    #pragma unroll
    for (int mf = 0; mf < 4; ++mf) {
        #pragma unroll
        for (int h = 0; h < 2; ++h) {
            const int m = m0 + wm * 64 + mf * 16 + (lane >> 2) + h * 8;
            #pragma unroll
            for (int nf = 0; nf < 8; ++nf) {
                const int nl = wn * 64 + nf * 8 + 2 * (lane & 3);
                float d0 = acc[mf][nf][h * 2 + 0] + sb1[nl];
                float d1 = acc[mf][nf][h * 2 + 1] + sb1[nl + 1];
                const size_t o = (size_t)m * 1024 + colBase + nl;
                if (seg == 0) {
                    d0 = fmaxf(d0, 0.f); d1 = fmaxf(d1, 0.f);
                    *(uint32_t*)&g_T1h[o] = packh2(__float2half_rn(d0), __float2half_rn(d1));
                } else if (seg == 1) {
                    *(uint32_t*)&g_A1h[o] = packh2(__float2half_rn(d0), __float2half_rn(d1));
                } else {
                    *(uint32_t*)&g_B1h[o] = packh2(__float2half_rn(d0), __float2half_rn(d1));
                }
            }
        }
    }
}

// --------------------------------------------- unified tensor stage (HMMA)
// 1-D grid, n-tile fastest. bx < 8192: interaction (A generated on the fly
// from L2-resident g_A1h/g_B1h); bx >= 8192: traj (A cp.async from g_T1h).
static constexpr int NCH = 32;   // 1024 / 32

__global__ __launch_bounds__(128, 2)
void tensor_stage_kernel(const float* __restrict__ t2b, const float* __restrict__ t3w,
                         const float* __restrict__ i2b, const float* __restrict__ i3w)
{
    extern __shared__ char smem_raw[];
    const uint32_t smem_u = smem_u32(smem_raw);
    const uint32_t base_u = (smem_u + 1023) & ~1023u;
    char* p = smem_raw + (base_u - smem_u);

    float* sb2 = (float*)(p + NSTAGE * TB_STAGE);
    float* sw3 = sb2 + 128;

    const int tid  = threadIdx.x;
    const int lane = tid & 31;
    const int wid  = tid >> 5;
    const int wm   = wid & 1;
    const int wn   = wid >> 1;

    const bool traj = (blockIdx.x >= 8192);
    const int idx   = traj ? (blockIdx.x - 8192) : blockIdx.x;
    const int m0    = (idx >> 3) * 128;
    const int n0    = (idx & 7) * 128;

    const __half* WT  = traj ? g_T2T : g_I2T;
    const float*  b2g = traj ? t2b : i2b;
    const float*  w3g = traj ? t3w : i3w;
    float* eout       = traj ? g_erow : g_eint;

    sb2[tid] = b2g[n0 + tid];
    sw3[tid] = w3g[n0 + tid];

    // interaction A-row decomposition: m = b*1024 + i*32 + j (b,i0 const/CTA)
    const int rowA_base = (m0 >> 10) * 32 + ((m0 >> 5) & 31);  // b*32 + i0
    const int rowB_base = (m0 >> 10) * 32;                      // b*32

    auto fillB = [&](int stage, int k0) {
        const uint32_t sb = base_u + (uint32_t)stage * TB_STAGE;
        #pragma unroll
        for (int t = 0; t < 4; ++t) {
            int idx2 = tid + t * 128;
            int rl = idx2 >> 2;
            int cc = idx2 & 3;
            const __half* src = WT + (size_t)(n0 + rl) * 1024 + k0 + cc * 8;
            cp16(sb + TB_B + SWZ64((uint32_t)(rl * 64 + cc * 16)), src);
        }
    };
    auto fillA_traj = [&](int stage, int k0) {
        const uint32_t sb = base_u + (uint32_t)stage * TB_STAGE;
        #pragma unroll
        for (int t = 0; t < 4; ++t) {
            int idx2 = tid + t * 128;
            int rl = idx2 >> 2;
            int cc = idx2 & 3;
            const __half* src = g_T1h + (size_t)(m0 + rl) * 1024 + k0 + cc * 8;
            cp16(sb + TB_A + SWZ64((uint32_t)(rl * 64 + cc * 16)), src);
        }
    };

    // interaction A prefetch/convert (registers hold next chunk's sources)
    uint4 va[4], vb[4];
    auto ldA_int = [&](int k0) {
        #pragma unroll
        for (int t = 0; t < 4; ++t) {
            int idx2 = tid + t * 128;
            int rl = idx2 >> 2;
            int cc = idx2 & 3;
            int ra = rowA_base + (rl >> 5);
            int rb = rowB_base + (rl & 31);
            va[t] = *(const uint4*)&g_A1h[(size_t)ra * 1024 + k0 + cc * 8];
            vb[t] = *(const uint4*)&g_B1h[(size_t)rb * 1024 + k0 + cc * 8];
        }
    };
    auto stA_int = [&](int stage) {
        #pragma unroll
        for (int t = 0; t < 4; ++t) {
            int idx2 = tid + t * 128;
            int rl = idx2 >> 2;
            int cc = idx2 & 3;
            uint4 o;
            o.x = haddrelu2(va[t].x, vb[t].x);
            o.y = haddrelu2(va[t].y, vb[t].y);
            o.z = haddrelu2(va[t].z, vb[t].z);
            o.w = haddrelu2(va[t].w, vb[t].w);
            *(uint4*)(p + (uint32_t)stage * TB_STAGE + TB_A
                      + SWZ64((uint32_t)(rl * 64 + cc * 16))) = o;
        }
    };

    uint32_t aoff[4], boff[4];
    #pragma unroll
    for (int mf = 0; mf < 4; ++mf)
        aoff[mf] = (uint32_t)((wm * 64 + mf * 16 + (lane & 15)) * 64 + (lane >> 4) * 16);
    #pragma unroll
    for (int nf2 = 0; nf2 < 4; ++nf2)
        boff[nf2] = (uint32_t)((wn * 64 + nf2 * 16 + (lane & 7) + ((lane & 16) ? 8 : 0)) * 64
                               + ((lane >> 3) & 1) * 16);

    float acc[4][8][4];
    #pragma unroll
    for (int mf = 0; mf < 4; ++mf)
        #pragma unroll
        for (int nf = 0; nf < 8; ++nf)
            #pragma unroll
            for (int q = 0; q < 4; ++q) acc[mf][nf][q] = 0.f;

    auto compute = [&](int stage) {
        const uint32_t sb = base_u + (uint32_t)stage * TB_STAGE;
        #pragma unroll
        for (int kf = 0; kf < 2; ++kf) {
            const uint32_t kadd = kf * 32;
            uint32_t ah[4][4], bf[8][2];
            #pragma unroll
            for (int mf = 0; mf < 4; ++mf) {
                uint32_t sw = SWZ64(aoff[mf] + kadd);
                ldsm4(ah[mf][0], ah[mf][1], ah[mf][2], ah[mf][3], sb + TB_A + sw);
            }
            #pragma unroll
            for (int nf2 = 0; nf2 < 4; ++nf2) {
                uint32_t sw = SWZ64(boff[nf2] + kadd);
                ldsm4(bf[nf2 * 2][0], bf[nf2 * 2][1],
                      bf[nf2 * 2 + 1][0], bf[nf2 * 2 + 1][1], sb + TB_B + sw);
            }
            #pragma unroll
            for (int mf = 0; mf < 4; ++mf)
                #pragma unroll
                for (int nf = 0; nf < 8; ++nf)
                    mma16816(acc[mf][nf], ah[mf], bf[nf]);
        }
    };

    // ---- prologue ----
    fillB(0, 0);  if (traj) fillA_traj(0, 0);  CP_COMMIT();
    fillB(1, 32); if (traj) fillA_traj(1, 32); CP_COMMIT();
    fillB(2, 64); if (traj) fillA_traj(2, 64); CP_COMMIT();
    if (!traj) { ldA_int(0); stA_int(0); }

    #pragma unroll 1
    for (int c = 0; c < NCH; ++c) {
        if (c + 3 < NCH) {
            fillB((c + 3) & 3, (c + 3) * 32);
            if (traj) fillA_traj((c + 3) & 3, (c + 3) * 32);
            CP_COMMIT();
        }
        if (!traj && c + 1 < NCH) ldA_int((c + 1) * 32);
        if (c + 3 < NCH) CP_WAIT2(); else CP_WAIT0();
        __syncthreads();
        compute(c & 3);
        if (!traj && c + 1 < NCH) stA_int((c + 1) & 3);
        __syncthreads();
    }

    // ---- epilogue: fused layer-3  e_m += sum_n w3[n]*relu(D+b2[n]) ----
    #pragma unroll
    for (int mf = 0; mf < 4; ++mf) {
        #pragma unroll
        for (int h = 0; h < 2; ++h) {
            float s = 0.f;
            #pragma unroll
            for (int nf = 0; nf < 8; ++nf) {
                int nl = wn * 64 + nf * 8 + 2 * (lane & 3);
                float d0 = acc[mf][nf][h * 2 + 0];
                float d1 = acc[mf][nf][h * 2 + 1];
                s += fmaxf(d0 + sb2[nl], 0.f) * sw3[nl]
                   + fmaxf(d1 + sb2[nl + 1], 0.f) * sw3[nl + 1];
            }
            s += __shfl_xor_sync(0xffffffffu, s, 1);
            s += __shfl_xor_sync(0xffffffffu, s, 2);
            if ((lane & 3) == 0) {
                int m = m0 + wm * 64 + mf * 16 + (lane >> 2) + h * 8;
                atomicAdd(&eout[m], s);
            }
        }
    }
}

// ------------------------------------------------------------------ finalize
__global__ void finalize_kernel(const float* __restrict__ edges,
                                const float* __restrict__ t3b,
                                const float* __restrict__ i3b,
                                float* __restrict__ out)
{
    const int b = blockIdx.x;
    const int tid = threadIdx.x;
    const float bias_i = i3b[0];

    float s = 0.f;
    #pragma unroll
    for (int it = 0; it < 4; ++it) {
        int idx = tid + it * 256;
        s += edges[b * 1024 + idx] * (g_eint[b * 1024 + idx] + bias_i);
    }
    if (tid < 32) s += g_erow[b * 32 + tid] + t3b[0];

    __shared__ float red[256];
    red[tid] = s;
    __syncthreads();
    for (int o = 128; o > 0; o >>= 1) {
        if (tid < o) red[tid] += red[tid + o];
        __syncthreads();
    }
    if (tid == 0) out[b] = red[0];
}

// ---------------------------------------------------------------------------
extern "C" void kernel_launch(void* const* d_in, const int* in_sizes, int n_in,
                              void* d_out, int out_size)
{
    const float* x   = (const float*)d_in[0];
    const float* edg = (const float*)d_in[1];
    const float* t1w = (const float*)d_in[2];
    const float* t1b = (const float*)d_in[3];
    const float* t2w = (const float*)d_in[4];
    const float* t2b = (const float*)d_in[5];
    const float* t3w = (const float*)d_in[6];
    const float* t3b = (const float*)d_in[7];
    const float* i1w = (const float*)d_in[8];
    const float* i1b = (const float*)d_in[9];
    const float* i2w = (const float*)d_in[10];
    const float* i2b = (const float*)d_in[11];
    const float* i3w = (const float*)d_in[12];
    const float* i3b = (const float*)d_in[13];
    float* out = (float*)d_out;

    cudaFuncSetAttribute(tensor_stage_kernel,
                         cudaFuncAttributeMaxDynamicSharedMemorySize, TS_SMEM);
    cudaFuncSetAttribute(stage1_mma_kernel,
                         cudaFuncAttributeMaxDynamicSharedMemorySize, TS_SMEM);

    init_kernel<<<512, 256>>>();

    dim3 gp(32, 32, 2);
    prep_transpose<<<gp, dim3(32, 32)>>>(t2w, i2w);

    convert_x_kernel<<<4096, 128>>>(x);
    convert_w1_kernel<<<dim3(96, 13), dim3(32, 32)>>>(t1w, i1w);

    stage1_mma_kernel<<<dim3(32, 24), 128, TS_SMEM>>>(t1b, i1b);

    tensor_stage_kernel<<<8448, 128, TS_SMEM>>>(t2b, t3w, i2b, i3w);

    finalize_kernel<<<128, 256>>>(edg, t3b, i3b, out);
}